// round 8
// baseline (speedup 1.0000x reference)
#include <cuda_runtime.h>
#include <cstdint>

#define S_LEN   2048
#define DMODEL  2048
#define NH      16
#define HDIM    128
#define KV_DM   512
#define NQT16   16
#define HEAVY   204
#define RECENT  204
#define SEL     (S_LEN - RECENT)    // 1844
#define MASKW   (S_LEN + 1)         // 2049

__device__ float g_hid[S_LEN * DMODEL];
__device__ float g_qwT[DMODEL * DMODEL];   // [n][k]
__device__ float g_kwT[KV_DM * DMODEL];
__device__ float g_vwT[KV_DM * DMODEL];
__device__ float g_owT[DMODEL * DMODEL];
__device__ float g_q[S_LEN * DMODEL];
__device__ float g_k[S_LEN * KV_DM];
__device__ float g_v[S_LEN * KV_DM];
__device__ float g_ctx[S_LEN * DMODEL];
__device__ float g_colpart[NH * NQT16 * S_LEN];
__device__ float g_lpart[NH * S_LEN * 16];
__device__ float g_E[(size_t)NH * S_LEN * S_LEN];   // exp'd scores (unnormalized)

// ---------------------------------------------------------------------------
__device__ __forceinline__ float tf32r(float x) {
    uint32_t u;
    asm("cvt.rna.tf32.f32 %0, %1;" : "=r"(u) : "f"(x));
    return __uint_as_float(u);
}
__device__ __forceinline__ float ex2f(float x) {
    float y;
    asm("ex2.approx.ftz.f32 %0, %1;" : "=f"(y) : "f"(x));
    return y;
}
__device__ __forceinline__ void mma_tf32(float* c, const uint32_t* a, const uint32_t* b) {
    asm volatile(
        "mma.sync.aligned.m16n8k8.row.col.f32.tf32.tf32.f32 "
        "{%0,%1,%2,%3}, {%4,%5,%6,%7}, {%8,%9}, {%0,%1,%2,%3};"
        : "+f"(c[0]), "+f"(c[1]), "+f"(c[2]), "+f"(c[3])
        : "r"(a[0]), "r"(a[1]), "r"(a[2]), "r"(a[3]), "r"(b[0]), "r"(b[1]));
}
__device__ __forceinline__ void ldsm4(uint32_t& r0, uint32_t& r1, uint32_t& r2, uint32_t& r3,
                                      uint32_t addr) {
    asm volatile("ldmatrix.sync.aligned.m8n8.x4.shared.b16 {%0,%1,%2,%3}, [%4];"
                 : "=r"(r0), "=r"(r1), "=r"(r2), "=r"(r3) : "r"(addr));
}
__device__ __forceinline__ void cpa16(uint32_t s, const float* g) {
    asm volatile("cp.async.cg.shared.global [%0], [%1], 16;" :: "r"(s), "l"(g));
}
__device__ __forceinline__ void cp_commit() { asm volatile("cp.async.commit_group;"); }
template<int N> __device__ __forceinline__ void cp_wait() {
    asm volatile("cp.async.wait_group %0;" :: "n"(N));
}
__device__ __forceinline__ unsigned encf(float x) {
    unsigned b = __float_as_uint(x);
    return (b & 0x80000000u) ? ~b : (b | 0x80000000u);
}

__global__ void zero_kernel(float* p, int n) {
    int i = blockIdx.x * 256 + threadIdx.x;
    if (i < n) p[i] = 0.0f;
}
__global__ void round4_kernel(float4* dst, const float4* src, int n4) {
    int i = blockIdx.x * 256 + threadIdx.x;
    if (i < n4) {
        float4 v = src[i];
        dst[i] = make_float4(tf32r(v.x), tf32r(v.y), tf32r(v.z), tf32r(v.w));
    }
}
// transpose + round: src [Kd][Nd] -> dst [Nd][Kd]
__global__ __launch_bounds__(256) void trr_kernel(float* dst, const float* src, int Kd, int Nd) {
    __shared__ float t[32][33];
    const int bx = blockIdx.x * 32;   // n
    const int by = blockIdx.y * 32;   // k
    const int tx = threadIdx.x, ty = threadIdx.y;
#pragma unroll
    for (int i = 0; i < 32; i += 8)
        t[ty + i][tx] = src[(size_t)(by + ty + i) * Nd + bx + tx];
    __syncthreads();
#pragma unroll
    for (int i = 0; i < 32; i += 8)
        dst[(size_t)(bx + ty + i) * Kd + by + tx] = tf32r(t[tx][ty + i]);
}

// ---------------------------------------------------------------------------
// BIG tf32 GEMM: 256x128 CTA tile, ldmatrix + 3-stage cp.async, 1 barrier/iter.
// A [M][2048], Bt [N][2048], tf32-rounded. 256 threads, warps 4m x 2n (64x64).
// Dynamic smem: As 3*256*20, Bs 3*128*20 floats (90 KB).
// ---------------------------------------------------------------------------
#define BIG_SMEM ((3 * 256 * 20 + 3 * 128 * 20) * 4)

template<bool ROUND, bool HASBIAS>
__global__ __launch_bounds__(256, 1) void gemm_big(
    const float* __restrict__ A, const float* __restrict__ Bt,
    const float* __restrict__ bias, float* __restrict__ C, int N)
{
    constexpr int KD = 2048, BK = 16, ASS = 20;
    constexpr int NIT = KD / BK;

    extern __shared__ float dyn[];
    float* AsF = dyn;
    float* BsF = dyn + 3 * 256 * ASS;

    const int tid = threadIdx.x;
    const int lane = tid & 31, w = tid >> 5;
    const int wm0 = (w & 3) * 64;
    const int wn0 = (w >> 2) * 64;
    const int bm = blockIdx.y * 256;
    const int bn = blockIdx.x * 128;

    const uint32_t sA = (uint32_t)__cvta_generic_to_shared(AsF);
    const uint32_t sB = (uint32_t)__cvta_generic_to_shared(BsF);

    const int g = lane >> 3, r = lane & 7;
    const int a_ro = (g & 1) * 8 + r, a_co = (g >> 1) * 4;
    const int b_ro = (g >> 1) * 8 + r, b_co = (g & 1) * 4;

    float acc[4][8][4];
#pragma unroll
    for (int mi = 0; mi < 4; mi++)
#pragma unroll
        for (int nj = 0; nj < 8; nj++)
#pragma unroll
            for (int c = 0; c < 4; c++) acc[mi][nj][c] = 0.0f;

    const int br = tid & 127;
    const int bc8 = (tid >> 7) * 8;

    auto issue = [&](int st, int k0) {
        const float* ga = &A[(size_t)(bm + tid) * KD + k0];
        uint32_t sa = sA + (uint32_t)((st * 256 + tid) * ASS) * 4u;
        cpa16(sa, ga); cpa16(sa + 16, ga + 4); cpa16(sa + 32, ga + 8); cpa16(sa + 48, ga + 12);
        const float* gb = &Bt[(size_t)(bn + br) * KD + k0 + bc8];
        uint32_t sb = sB + (uint32_t)((st * 128 + br) * ASS + bc8) * 4u;
        cpa16(sb, gb); cpa16(sb + 16, gb + 4);
    };

    issue(0, 0);       cp_commit();
    issue(1, BK);      cp_commit();

    int st = 0;
    for (int it = 0; it < NIT; it++) {
        if (it + 1 < NIT) cp_wait<1>(); else cp_wait<0>();
        __syncthreads();
        const uint32_t aB = sA + (uint32_t)(st * 256 * ASS) * 4u;
        const uint32_t bB = sB + (uint32_t)(st * 128 * ASS) * 4u;

#pragma unroll
        for (int ks = 0; ks < 2; ks++) {
            const int kk = ks * 8;
            uint32_t af[4][4], bf[8][2];
#pragma unroll
            for (int mi = 0; mi < 4; mi++) {
                uint32_t ad = aB + (uint32_t)(((wm0 + 16 * mi + a_ro) * ASS) + kk + a_co) * 4u;
                ldsm4(af[mi][0], af[mi][1], af[mi][2], af[mi][3], ad);
            }
#pragma unroll
            for (int p = 0; p < 4; p++) {
                uint32_t bd = bB + (uint32_t)(((wn0 + 16 * p + b_ro) * ASS) + kk + b_co) * 4u;
                ldsm4(bf[2 * p][0], bf[2 * p][1], bf[2 * p + 1][0], bf[2 * p + 1][1], bd);
            }
#pragma unroll
            for (int mi = 0; mi < 4; mi++)
#pragma unroll
                for (int nj = 0; nj < 8; nj++)
                    mma_tf32(acc[mi][nj], af[mi], bf[nj]);
        }

        if (it + 2 < NIT) {
            int wst = (st + 2) % 3;
            issue(wst, (it + 2) * BK);
            cp_commit();
        }
        st = (st + 1) % 3;
    }

#pragma unroll
    for (int mi = 0; mi < 4; mi++) {
#pragma unroll
        for (int nj = 0; nj < 8; nj++) {
            int row = bm + wm0 + 16 * mi + (lane >> 2);
            int col = bn + wn0 + 8 * nj + 2 * (lane & 3);
            float bx = 0.0f, by = 0.0f;
            if (HASBIAS) { bx = bias[col]; by = bias[col + 1]; }
            float v0x = acc[mi][nj][0] + bx, v0y = acc[mi][nj][1] + by;
            float v1x = acc[mi][nj][2] + bx, v1y = acc[mi][nj][3] + by;
            if (ROUND) {
                v0x = tf32r(v0x); v0y = tf32r(v0y);
                v1x = tf32r(v1x); v1y = tf32r(v1y);
            }
            *(float2*)&C[(size_t)row * N + col] = make_float2(v0x, v0y);
            *(float2*)&C[(size_t)(row + 8) * N + col] = make_float2(v1x, v1y);
        }
    }
}

// ---------------------------------------------------------------------------
// 128x128 tf32 GEMM (KV projections, z-fused). Same as R7.
// ---------------------------------------------------------------------------
template<bool ROUND, bool HASBIAS>
__global__ __launch_bounds__(256, 2) void gemm_lm(
    const float* __restrict__ A,
    const float* __restrict__ Bt0, const float* __restrict__ Bt1,
    const float* __restrict__ bias0, const float* __restrict__ bias1,
    float* __restrict__ C0, float* __restrict__ C1, int N)
{
    constexpr int KD = 2048, BK = 16, ASS = 20;
    constexpr int NIT = KD / BK;

    __shared__ float As[3][128 * ASS];
    __shared__ float Bs[3][128 * ASS];

    const int tid = threadIdx.x;
    const int lane = tid & 31, w = tid >> 5;
    const int wm0 = (w & 1) * 64;
    const int wn0 = (w >> 1) * 32;
    const int bm = blockIdx.y * 128;
    const int bn = blockIdx.x * 128;

    const float* Bt  = (blockIdx.z == 0) ? Bt0 : Bt1;
    const float* bia = (blockIdx.z == 0) ? bias0 : bias1;
    float* C         = (blockIdx.z == 0) ? C0 : C1;

    const int cr = tid & 127;
    const int cc8 = (tid >> 7) * 8;
    const uint32_t sA = (uint32_t)__cvta_generic_to_shared(&As[0][0]);
    const uint32_t sB = (uint32_t)__cvta_generic_to_shared(&Bs[0][0]);

    const int g = lane >> 3, r = lane & 7;
    const int a_ro = (g & 1) * 8 + r, a_co = (g >> 1) * 4;
    const int b_ro = (g >> 1) * 8 + r, b_co = (g & 1) * 4;

    float acc[4][4][4];
#pragma unroll
    for (int mi = 0; mi < 4; mi++)
#pragma unroll
        for (int nj = 0; nj < 4; nj++)
#pragma unroll
            for (int c = 0; c < 4; c++) acc[mi][nj][c] = 0.0f;

    auto issue = [&](int st, int k0) {
        const float* ga = &A[(size_t)(bm + cr) * KD + k0 + cc8];
        uint32_t sa = sA + (uint32_t)((st * 128 + cr) * ASS + cc8) * 4u;
        cpa16(sa, ga); cpa16(sa + 16, ga + 4);
        const float* gb = &Bt[(size_t)(bn + cr) * KD + k0 + cc8];
        uint32_t sb = sB + (uint32_t)((st * 128 + cr) * ASS + cc8) * 4u;
        cpa16(sb, gb); cpa16(sb + 16, gb + 4);
    };

    issue(0, 0);       cp_commit();
    issue(1, BK);      cp_commit();

    int st = 0;
    for (int it = 0; it < NIT; it++) {
        if (it + 1 < NIT) cp_wait<1>(); else cp_wait<0>();
        __syncthreads();
        const uint32_t aB = sA + (uint32_t)(st * 128 * ASS) * 4u;
        const uint32_t bB = sB + (uint32_t)(st * 128 * ASS) * 4u;

        uint32_t af[2][4][4], bf[2][4][2];
#pragma unroll
        for (int ks = 0; ks < 2; ks++) {
            const int kk = ks * 8;
#pragma unroll
            for (int mi = 0; mi < 4; mi++) {
                uint32_t ad = aB + (uint32_t)(((wm0 + 16 * mi + a_ro) * ASS) + kk + a_co) * 4u;
                ldsm4(af[ks][mi][0], af[ks][mi][1], af[ks][mi][2], af[ks][mi][3], ad);
            }
#pragma unroll
            for (int p = 0; p < 2; p++) {
                uint32_t bd = bB + (uint32_t)(((wn0 + 16 * p + b_ro) * ASS) + kk + b_co) * 4u;
                ldsm4(bf[ks][2 * p][0], bf[ks][2 * p][1], bf[ks][2 * p + 1][0], bf[ks][2 * p + 1][1], bd);
            }
        }
#pragma unroll
        for (int ks = 0; ks < 2; ks++)
#pragma unroll
            for (int mi = 0; mi < 4; mi++)
#pragma unroll
                for (int nj = 0; nj < 4; nj++)
                    mma_tf32(acc[mi][nj], af[ks][mi], bf[ks][nj]);

        if (it + 2 < NIT) {
            int wst = (st + 2) % 3;
            issue(wst, (it + 2) * BK);
            cp_commit();
        }
        st = (st + 1) % 3;
    }

#pragma unroll
    for (int mi = 0; mi < 4; mi++) {
#pragma unroll
        for (int nj = 0; nj < 4; nj++) {
            int row = bm + wm0 + 16 * mi + (lane >> 2);
            int col = bn + wn0 + 8 * nj + 2 * (lane & 3);
            float bx = 0.0f, by = 0.0f;
            if (HASBIAS) { bx = bia[col]; by = bia[col + 1]; }
            float v0x = acc[mi][nj][0] + bx, v0y = acc[mi][nj][1] + by;
            float v1x = acc[mi][nj][2] + bx, v1y = acc[mi][nj][3] + by;
            if (ROUND) {
                v0x = tf32r(v0x); v0y = tf32r(v0y);
                v1x = tf32r(v1x); v1y = tf32r(v1y);
            }
            *(float2*)&C[(size_t)row * N + col] = make_float2(v0x, v0y);
            *(float2*)&C[(size_t)(row + 8) * N + col] = make_float2(v1x, v1y);
        }
    }
}

// ---------------------------------------------------------------------------
// Scores kernel: E = 2^(QK^T * scale * log2e) causal-masked, + per-128-block
// row-sum partials. 3-stage pipeline (same as R7).
// ---------------------------------------------------------------------------
__global__ __launch_bounds__(256, 2) void scores_lm() {
    constexpr int ASS = 20, BK = 16;
    const int nb = blockIdx.x, mb = blockIdx.y, h = blockIdx.z;
    if (nb > mb) return;
    const int kvh = h >> 2;

    __shared__ float As[3][128 * ASS];
    __shared__ float Bs[3][128 * ASS];
    __shared__ float red[128 * 4];

    const int tid = threadIdx.x;
    const int lane = tid & 31, w = tid >> 5;
    const int wm0 = (w & 1) * 64;
    const int wn0 = (w >> 1) * 32;

    const int cr = tid & 127;
    const int cc8 = (tid >> 7) * 8;
    const uint32_t sA = (uint32_t)__cvta_generic_to_shared(&As[0][0]);
    const uint32_t sB = (uint32_t)__cvta_generic_to_shared(&Bs[0][0]);

    const int g = lane >> 3, r = lane & 7;
    const int a_ro = (g & 1) * 8 + r, a_co = (g >> 1) * 4;
    const int b_ro = (g >> 1) * 8 + r, b_co = (g & 1) * 4;

    const float* Qg = g_q + (size_t)(mb * 128) * DMODEL + h * HDIM;
    const float* Kg = g_k + (size_t)(nb * 128) * KV_DM + kvh * HDIM;

    float acc[4][4][4];
#pragma unroll
    for (int mi = 0; mi < 4; mi++)
#pragma unroll
        for (int nj = 0; nj < 4; nj++)
#pragma unroll
            for (int c = 0; c < 4; c++) acc[mi][nj][c] = 0.0f;

    auto issue = [&](int st, int k0) {
        const float* ga = &Qg[(size_t)cr * DMODEL + k0 + cc8];
        uint32_t sa = sA + (uint32_t)((st * 128 + cr) * ASS + cc8) * 4u;
        cpa16(sa, ga); cpa16(sa + 16, ga + 4);
        const float* gb = &Kg[(size_t)cr * KV_DM + k0 + cc8];
        uint32_t sb = sB + (uint32_t)((st * 128 + cr) * ASS + cc8) * 4u;
        cpa16(sb, gb); cpa16(sb + 16, gb + 4);
    };

    issue(0, 0);      cp_commit();
    issue(1, BK);     cp_commit();

    constexpr int NIT = HDIM / BK;
    int st = 0;
    for (int it = 0; it < NIT; it++) {
        if (it + 1 < NIT) cp_wait<1>(); else cp_wait<0>();
        __syncthreads();
        const uint32_t aB = sA + (uint32_t)(st * 128 * ASS) * 4u;
        const uint32_t bB = sB + (uint32_t)(st * 128 * ASS) * 4u;
        uint32_t af[2][4][4], bf[2][4][2];
#pragma unroll
        for (int ks = 0; ks < 2; ks++) {
            const int kk = ks * 8;
#pragma unroll
            for (int mi = 0; mi < 4; mi++) {
                uint32_t ad = aB + (uint32_t)(((wm0 + 16 * mi + a_ro) * ASS) + kk + a_co) * 4u;
                ldsm4(af[ks][mi][0], af[ks][mi][1], af[ks][mi][2], af[ks][mi][3], ad);
            }
#pragma unroll
            for (int p = 0; p < 2; p++) {
                uint32_t bd = bB + (uint32_t)(((wn0 + 16 * p + b_ro) * ASS) + kk + b_co) * 4u;
                ldsm4(bf[ks][2 * p][0], bf[ks][2 * p][1], bf[ks][2 * p + 1][0], bf[ks][2 * p + 1][1], bd);
            }
        }
#pragma unroll
        for (int ks = 0; ks < 2; ks++)
#pragma unroll
            for (int mi = 0; mi < 4; mi++)
#pragma unroll
                for (int nj = 0; nj < 4; nj++)
                    mma_tf32(acc[mi][nj], af[ks][mi], bf[ks][nj]);

        if (it + 2 < NIT) {
            int wst = (st + 2) % 3;
            issue(wst, (it + 2) * BK);
            cp_commit();
        }
        st = (st + 1) % 3;
    }

    const float SCL2 = 0.08838834764831845f * 1.4426950408889634f;
    float* Eh = g_E + (size_t)h * S_LEN * S_LEN;
    float rs[4][2];
#pragma unroll
    for (int mi = 0; mi < 4; mi++) { rs[mi][0] = 0.f; rs[mi][1] = 0.f; }

#pragma unroll
    for (int mi = 0; mi < 4; mi++) {
#pragma unroll
        for (int nj = 0; nj < 4; nj++) {
            int row = mb * 128 + wm0 + 16 * mi + (lane >> 2);
            int col = nb * 128 + wn0 + 8 * nj + 2 * (lane & 3);
            float e0 = (col     <= row)     ? ex2f(acc[mi][nj][0] * SCL2) : 0.f;
            float e1 = (col + 1 <= row)     ? ex2f(acc[mi][nj][1] * SCL2) : 0.f;
            float e2 = (col     <= row + 8) ? ex2f(acc[mi][nj][2] * SCL2) : 0.f;
            float e3 = (col + 1 <= row + 8) ? ex2f(acc[mi][nj][3] * SCL2) : 0.f;
            *(float2*)&Eh[(size_t)row * S_LEN + col] = make_float2(e0, e1);
            *(float2*)&Eh[(size_t)(row + 8) * S_LEN + col] = make_float2(e2, e3);
            rs[mi][0] += e0 + e1;
            rs[mi][1] += e2 + e3;
        }
    }
#pragma unroll
    for (int mi = 0; mi < 4; mi++)
#pragma unroll
        for (int hh = 0; hh < 2; hh++) {
            rs[mi][hh] += __shfl_xor_sync(0xFFFFFFFFu, rs[mi][hh], 1);
            rs[mi][hh] += __shfl_xor_sync(0xFFFFFFFFu, rs[mi][hh], 2);
        }
    if ((lane & 3) == 0) {
        int wg = w >> 1;
#pragma unroll
        for (int mi = 0; mi < 4; mi++) {
            red[(wm0 + 16 * mi + (lane >> 2)) * 4 + wg]     = rs[mi][0];
            red[(wm0 + 16 * mi + 8 + (lane >> 2)) * 4 + wg] = rs[mi][1];
        }
    }
    __syncthreads();
    if (tid < 128)
        g_lpart[((size_t)h * S_LEN + mb * 128 + tid) * 16 + nb] =
            red[tid * 4] + red[tid * 4 + 1] + red[tid * 4 + 2] + red[tid * 4 + 3];
}

// ---------------------------------------------------------------------------
// Attention over E: single pass. p = E * il -> smem, colsums + P@V.
// ---------------------------------------------------------------------------
#define SP_OFF   0
#define VS_OFF   8704
#define RED_OFF  17408
#define IL_OFF   17920
#define ATTN_SMEM ((17920 + 128) * 4)

__global__ __launch_bounds__(512, 1) void attn_pv() {
    extern __shared__ float smem[];
    float* sP  = smem + SP_OFF;     // [128][68]
    float* Vs  = smem + VS_OFF;     // [64][136]
    float* red = smem + RED_OFF;    // [512]
    float* il  = smem + IL_OFF;     // [128]

    const int qt = 15 - blockIdx.x;
    const int h  = blockIdx.y;
    const int kvh = h >> 2;
    const int qbase = qt * 128;
    const int tid = threadIdx.x;
    const int lane = tid & 31, w = tid >> 5;
    const int wm  = (w & 3) * 32;
    const int wn2 = (w >> 2) * 32;

    const int g = lane >> 3, r = lane & 7;
    const int a_ro = (g & 1) * 8 + r, a_co = (g >> 1) * 4;
    const uint32_t sPT = (uint32_t)__cvta_generic_to_shared(sP);

    const float* Eh = g_E + (size_t)h * S_LEN * S_LEN;

    if (tid < 128) {
        const float* lp = &g_lpart[((size_t)h * S_LEN + qbase + tid) * 16];
        float l = 0.0f;
        for (int nb = 0; nb <= qt; nb++) l += lp[nb];
        il[tid] = 1.0f / l;
    }
    __syncthreads();

    const int prow = tid >> 2;
    const int pcb = (tid & 3) * 16;
    const float myil = il[prow];

    float o[2][4][4];
#pragma unroll
    for (int mi = 0; mi < 2; mi++)
#pragma unroll
        for (int nj = 0; nj < 4; nj++)
#pragma unroll
            for (int c = 0; c < 4; c++) o[mi][nj][c] = 0.0f;

    const int nkt = 2 * qt + 2;
    for (int kt = 0; kt < nkt; kt++) {
        {
            const float* ep = &Eh[(size_t)(qbase + prow) * S_LEN + kt * 64 + pcb];
#pragma unroll
            for (int i = 0; i < 4; i++) {
                float4 v = *(const float4*)&ep[4 * i];
                v.x *= myil; v.y *= myil; v.z *= myil; v.w *= myil;
                *(float4*)&sP[prow * 68 + pcb + 4 * i] = v;
            }
            int vr = tid >> 3, vcb = (tid & 7) * 16;
            const float* vp = &g_v[(size_t)(kt * 64 + vr) * KV_DM + kvh * HDIM + vcb];
#pragma unroll
            for (int i = 0; i < 4; i++)
                *(float4*)&Vs[vr * 136 + vcb + 4 * i] = *(const float4*)&vp[4 * i];
        }
        __syncthreads();

        if (tid < 256) {
            int c = tid & 63, seg = tid >> 6;
            float cs = 0.0f;
#pragma unroll 8
            for (int q = 0; q < 32; q++) cs += sP[(seg * 32 + q) * 68 + c];
            red[c * 4 + seg] = cs;
        }

#pragma unroll
        for (int ks = 0; ks < 8; ks++) {
            const int kk = ks * 8;
            uint32_t af[2][4], bf[4][2];
#pragma unroll
            for (int mi = 0; mi < 2; mi++) {
                uint32_t ad = sPT + (uint32_t)(((wm + 16 * mi + a_ro) * 68) + kk + a_co) * 4u;
                ldsm4(af[mi][0], af[mi][1], af[mi][2], af[mi][3], ad);
            }
#pragma unroll
            for (int nj = 0; nj < 4; nj++) {
                int n0 = wn2 + 8 * nj + (lane >> 2);
                bf[nj][0] = __float_as_uint(Vs[(kk + (lane & 3)) * 136 + n0]);
                bf[nj][1] = __float_as_uint(Vs[(kk + 4 + (lane & 3)) * 136 + n0]);
            }
#pragma unroll
            for (int mi = 0; mi < 2; mi++)
#pragma unroll
                for (int nj = 0; nj < 4; nj++)
                    mma_tf32(o[mi][nj], af[mi], bf[nj]);
        }
        __syncthreads();
        if (tid < 64)
            g_colpart[((size_t)h * NQT16 + qt) * S_LEN + kt * 64 + tid] =
                red[tid * 4] + red[tid * 4 + 1] + red[tid * 4 + 2] + red[tid * 4 + 3];
    }

#pragma unroll
    for (int mi = 0; mi < 2; mi++)
#pragma unroll
        for (int nj = 0; nj < 4; nj++) {
            int row = qbase + wm + 16 * mi + (lane >> 2);
            int col = h * HDIM + wn2 + 8 * nj + 2 * (lane & 3);
            *(float2*)&g_ctx[(size_t)row * DMODEL + col] =
                make_float2(tf32r(o[mi][nj][0]), tf32r(o[mi][nj][1]));
            *(float2*)&g_ctx[(size_t)(row + 8) * DMODEL + col] =
                make_float2(tf32r(o[mi][nj][2]), tf32r(o[mi][nj][3]));
        }
}

// ---------------------------------------------------------------------------
// Heavy-hitter mask via bitonic sort (exact jax.lax.top_k tie semantics).
// ---------------------------------------------------------------------------
__global__ __launch_bounds__(1024) void topk_kernel(float* __restrict__ mask_out) {
    const int h = blockIdx.x;
    const int tid = threadIdx.x;
    __shared__ unsigned long long keys[2048];

    for (int i = tid; i < 2048; i += 1024) {
        unsigned ev = 0u;
        if (i < SEL) {
            float s = 0.0f;
#pragma unroll
            for (int qt = 0; qt < NQT16; qt++)
                s += g_colpart[((size_t)h * NQT16 + qt) * S_LEN + i];
            ev = encf(s);
        }
        keys[i] = ((unsigned long long)ev << 32) | (unsigned)(2047 - i);
    }
    float* mrow = mask_out + (size_t)h * MASKW;
    for (int i = tid; i < MASKW; i += 1024)
        mrow[i] = (i >= (MASKW - RECENT)) ? 1.0f : 0.0f;
    __syncthreads();

    for (int k = 2; k <= 2048; k <<= 1) {
        for (int j = k >> 1; j > 0; j >>= 1) {
            for (int idx = tid; idx < 2048; idx += 1024) {
                int ixj = idx ^ j;
                if (ixj > idx) {
                    unsigned long long a = keys[idx], b = keys[ixj];
                    bool up = (idx & k) == 0;
                    if (up ? (a > b) : (a < b)) { keys[idx] = b; keys[ixj] = a; }
                }
            }
            __syncthreads();
        }
    }
    for (int i = 2048 - HEAVY + tid; i < 2048; i += 1024) {
        int idx = 2047 - (int)(keys[i] & 0xFFFFFFFFu);
        mrow[idx] = 1.0f;
    }
}

// ---------------------------------------------------------------------------
extern "C" void kernel_launch(void* const* d_in, const int* in_sizes, int n_in,
                              void* d_out, int out_size) {
    (void)in_sizes; (void)n_in; (void)out_size;
    const float* hidden = (const float*)d_in[0];
    const float* q_w = (const float*)d_in[1];
    const float* q_b = (const float*)d_in[2];
    const float* k_w = (const float*)d_in[3];
    const float* k_b = (const float*)d_in[4];
    const float* v_w = (const float*)d_in[5];
    const float* v_b = (const float*)d_in[6];
    const float* o_w = (const float*)d_in[7];
    float* out = (float*)d_out;

    static bool init = false;
    static cudaStream_t sA, sB, sC;
    static cudaEvent_t evRoot, evHid, evKV, evZero, evAttn, evTrrO, evTrrQ, evDoneA, evDoneC;
    if (!init) {
        cudaFuncSetAttribute(attn_pv, cudaFuncAttributeMaxDynamicSharedMemorySize, ATTN_SMEM);
        cudaFuncSetAttribute(gemm_big<true, true>,
                             cudaFuncAttributeMaxDynamicSharedMemorySize, BIG_SMEM);
        cudaFuncSetAttribute(gemm_big<false, false>,
                             cudaFuncAttributeMaxDynamicSharedMemorySize, BIG_SMEM);
        cudaStreamCreateWithFlags(&sA, cudaStreamNonBlocking);
        cudaStreamCreateWithFlags(&sB, cudaStreamNonBlocking);
        cudaStreamCreateWithFlags(&sC, cudaStreamNonBlocking);
        cudaEventCreateWithFlags(&evRoot, cudaEventDisableTiming);
        cudaEventCreateWithFlags(&evHid,  cudaEventDisableTiming);
        cudaEventCreateWithFlags(&evKV,   cudaEventDisableTiming);
        cudaEventCreateWithFlags(&evZero, cudaEventDisableTiming);
        cudaEventCreateWithFlags(&evAttn, cudaEventDisableTiming);
        cudaEventCreateWithFlags(&evTrrO, cudaEventDisableTiming);
        cudaEventCreateWithFlags(&evTrrQ, cudaEventDisableTiming);
        cudaEventCreateWithFlags(&evDoneA, cudaEventDisableTiming);
        cudaEventCreateWithFlags(&evDoneC, cudaEventDisableTiming);
        init = true;
    }

    float *ghid, *gqwT, *gkwT, *gvwT, *gowT, *gq, *gk, *gv, *gctx, *gcp;
    cudaGetSymbolAddress((void**)&ghid, g_hid);
    cudaGetSymbolAddress((void**)&gqwT, g_qwT);
    cudaGetSymbolAddress((void**)&gkwT, g_kwT);
    cudaGetSymbolAddress((void**)&gvwT, g_vwT);
    cudaGetSymbolAddress((void**)&gowT, g_owT);
    cudaGetSymbolAddress((void**)&gq,   g_q);
    cudaGetSymbolAddress((void**)&gk,   g_k);
    cudaGetSymbolAddress((void**)&gv,   g_v);
    cudaGetSymbolAddress((void**)&gctx, g_ctx);
    cudaGetSymbolAddress((void**)&gcp,  g_colpart);

    // fork from the capture (legacy) stream
    cudaEventRecord(evRoot, 0);
    cudaStreamWaitEvent(sA, evRoot, 0);
    cudaStreamWaitEvent(sB, evRoot, 0);
    cudaStreamWaitEvent(sC, evRoot, 0);

    dim3 tb(32, 8);
    // sA: round_hid; sC: trr_q (concurrent)
    round4_kernel<<<(S_LEN * DMODEL / 4 + 255) / 256, 256, 0, sA>>>(
        (float4*)ghid, (const float4*)hidden, S_LEN * DMODEL / 4);
    cudaEventRecord(evHid, sA);
    trr_kernel<<<dim3(DMODEL / 32, DMODEL / 32), tb, 0, sC>>>(gqwT, q_w, DMODEL, DMODEL);
    cudaEventRecord(evTrrQ, sC);
    // sB: trr_k, trr_v
    trr_kernel<<<dim3(KV_DM / 32, DMODEL / 32), tb, 0, sB>>>(gkwT, k_w, DMODEL, KV_DM);
    trr_kernel<<<dim3(KV_DM / 32, DMODEL / 32), tb, 0, sB>>>(gvwT, v_w, DMODEL, KV_DM);
    // sC: trr_o, zero
    trr_kernel<<<dim3(DMODEL / 32, DMODEL / 32), tb, 0, sC>>>(gowT, o_w, DMODEL, DMODEL);
    cudaEventRecord(evTrrO, sC);

    // Q projection (256x128 tiles)
    cudaStreamWaitEvent(sA, evTrrQ, 0);
    gemm_big<true, true><<<dim3(DMODEL / 128, S_LEN / 256), 256, BIG_SMEM, sA>>>(
        ghid, gqwT, q_b, gq, DMODEL);

    // KV projections (128x128, z-fused), concurrent with Q
    cudaStreamWaitEvent(sB, evHid, 0);
    gemm_lm<true, true><<<dim3(KV_DM / 128, S_LEN / 128, 2), 256, 0, sB>>>(
        ghid, gkwT, gvwT, k_b, v_b, gk, gv, KV_DM);
    cudaEventRecord(evKV, sB);

    const int ncp = NH * NQT16 * S_LEN;
    zero_kernel<<<(ncp + 255) / 256, 256, 0, sC>>>(gcp, ncp);
    cudaEventRecord(evZero, sC);

    cudaStreamWaitEvent(sA, evKV, 0);
    scores_lm<<<dim3(16, 16, NH), 256, 0, sA>>>();

    cudaStreamWaitEvent(sA, evZero, 0);
    attn_pv<<<dim3(16, NH), 512, ATTN_SMEM, sA>>>();
    cudaEventRecord(evAttn, sA);

    // sC: topk (after attn), overlaps with gemmO on sA
    cudaStreamWaitEvent(sC, evAttn, 0);
    topk_kernel<<<NH, 1024, 0, sC>>>(out + (size_t)S_LEN * DMODEL);
    cudaEventRecord(evDoneC, sC);

    cudaStreamWaitEvent(sA, evTrrO, 0);
    gemm_big<false, false><<<dim3(DMODEL / 128, S_LEN / 256), 256, BIG_SMEM, sA>>>(
        gctx, gowT, nullptr, out, DMODEL);
    cudaEventRecord(evDoneA, sA);

    // join back to the capture stream
    cudaStreamWaitEvent(0, evDoneA, 0);
    cudaStreamWaitEvent(0, evDoneC, 0);
}

// round 9
// speedup vs baseline: 1.0275x; 1.0275x over previous
#include <cuda_runtime.h>
#include <cstdint>

#define S_LEN   2048
#define DMODEL  2048
#define NH      16
#define HDIM    128
#define KV_DM   512
#define NQT16   16
#define HEAVY   204
#define RECENT  204
#define SEL     (S_LEN - RECENT)    // 1844
#define MASKW   (S_LEN + 1)         // 2049

__device__ float g_hid[S_LEN * DMODEL];
__device__ float g_qwT[DMODEL * DMODEL];   // [n][k]
__device__ float g_kwT[KV_DM * DMODEL];
__device__ float g_vwT[KV_DM * DMODEL];
__device__ float g_owT[DMODEL * DMODEL];
__device__ float g_q[S_LEN * DMODEL];
__device__ float g_k[S_LEN * KV_DM];
__device__ float g_v[S_LEN * KV_DM];
__device__ float g_ctx[S_LEN * DMODEL];
__device__ float g_colpart[NH * NQT16 * S_LEN];
__device__ float g_lpart[NH * S_LEN * 16];
__device__ float g_E[(size_t)NH * S_LEN * S_LEN];   // exp'd scores (unnormalized)

// ---------------------------------------------------------------------------
__device__ __forceinline__ float tf32r(float x) {
    uint32_t u;
    asm("cvt.rna.tf32.f32 %0, %1;" : "=r"(u) : "f"(x));
    return __uint_as_float(u);
}
__device__ __forceinline__ float ex2f(float x) {
    float y;
    asm("ex2.approx.ftz.f32 %0, %1;" : "=f"(y) : "f"(x));
    return y;
}
__device__ __forceinline__ void mma_tf32(float* c, const uint32_t* a, const uint32_t* b) {
    asm volatile(
        "mma.sync.aligned.m16n8k8.row.col.f32.tf32.tf32.f32 "
        "{%0,%1,%2,%3}, {%4,%5,%6,%7}, {%8,%9}, {%0,%1,%2,%3};"
        : "+f"(c[0]), "+f"(c[1]), "+f"(c[2]), "+f"(c[3])
        : "r"(a[0]), "r"(a[1]), "r"(a[2]), "r"(a[3]), "r"(b[0]), "r"(b[1]));
}
__device__ __forceinline__ void ldsm4(uint32_t& r0, uint32_t& r1, uint32_t& r2, uint32_t& r3,
                                      uint32_t addr) {
    asm volatile("ldmatrix.sync.aligned.m8n8.x4.shared.b16 {%0,%1,%2,%3}, [%4];"
                 : "=r"(r0), "=r"(r1), "=r"(r2), "=r"(r3) : "r"(addr));
}
__device__ __forceinline__ void cpa16(uint32_t s, const float* g) {
    asm volatile("cp.async.cg.shared.global [%0], [%1], 16;" :: "r"(s), "l"(g));
}
__device__ __forceinline__ void cp_commit() { asm volatile("cp.async.commit_group;"); }
template<int N> __device__ __forceinline__ void cp_wait() {
    asm volatile("cp.async.wait_group %0;" :: "n"(N));
}
__device__ __forceinline__ unsigned encf(float x) {
    unsigned b = __float_as_uint(x);
    return (b & 0x80000000u) ? ~b : (b | 0x80000000u);
}

__global__ void zero_kernel(float* p, int n) {
    int i = blockIdx.x * 256 + threadIdx.x;
    if (i < n) p[i] = 0.0f;
}
__global__ void round4_kernel(float4* dst, const float4* src, int n4) {
    int i = blockIdx.x * 256 + threadIdx.x;
    if (i < n4) {
        float4 v = src[i];
        dst[i] = make_float4(tf32r(v.x), tf32r(v.y), tf32r(v.z), tf32r(v.w));
    }
}
// transpose + round: src [Kd][Nd] -> dst [Nd][Kd]
__global__ __launch_bounds__(256) void trr_kernel(float* dst, const float* src, int Kd, int Nd) {
    __shared__ float t[32][33];
    const int bx = blockIdx.x * 32;   // n
    const int by = blockIdx.y * 32;   // k
    const int tx = threadIdx.x, ty = threadIdx.y;
#pragma unroll
    for (int i = 0; i < 32; i += 8)
        t[ty + i][tx] = src[(size_t)(by + ty + i) * Nd + bx + tx];
    __syncthreads();
#pragma unroll
    for (int i = 0; i < 32; i += 8)
        dst[(size_t)(bx + ty + i) * Kd + by + tx] = tf32r(t[tx][ty + i]);
}

// ---------------------------------------------------------------------------
// 128x128 tf32 GEMM: ldmatrix + 3-stage cp.async, 1 barrier/iter, 2 CTAs/SM.
// A [M][2048], Bt [N][2048] (pre-transposed), tf32-rounded.
// blockIdx.z selects (Bt,bias,C).
// ---------------------------------------------------------------------------
template<bool ROUND, bool HASBIAS>
__global__ __launch_bounds__(256, 2) void gemm_lm(
    const float* __restrict__ A,
    const float* __restrict__ Bt0, const float* __restrict__ Bt1,
    const float* __restrict__ bias0, const float* __restrict__ bias1,
    float* __restrict__ C0, float* __restrict__ C1, int N)
{
    constexpr int KD = 2048, BK = 16, ASS = 20;
    constexpr int NIT = KD / BK;

    __shared__ float As[3][128 * ASS];
    __shared__ float Bs[3][128 * ASS];

    const int tid = threadIdx.x;
    const int lane = tid & 31, w = tid >> 5;
    const int wm0 = (w & 1) * 64;
    const int wn0 = (w >> 1) * 32;
    const int bm = blockIdx.y * 128;
    const int bn = blockIdx.x * 128;

    const float* Bt  = (blockIdx.z == 0) ? Bt0 : Bt1;
    const float* bia = (blockIdx.z == 0) ? bias0 : bias1;
    float* C         = (blockIdx.z == 0) ? C0 : C1;

    const int cr = tid & 127;
    const int cc8 = (tid >> 7) * 8;
    const uint32_t sA = (uint32_t)__cvta_generic_to_shared(&As[0][0]);
    const uint32_t sB = (uint32_t)__cvta_generic_to_shared(&Bs[0][0]);

    const int g = lane >> 3, r = lane & 7;
    const int a_ro = (g & 1) * 8 + r, a_co = (g >> 1) * 4;
    const int b_ro = (g >> 1) * 8 + r, b_co = (g & 1) * 4;

    float acc[4][4][4];
#pragma unroll
    for (int mi = 0; mi < 4; mi++)
#pragma unroll
        for (int nj = 0; nj < 4; nj++)
#pragma unroll
            for (int c = 0; c < 4; c++) acc[mi][nj][c] = 0.0f;

    auto issue = [&](int st, int k0) {
        const float* ga = &A[(size_t)(bm + cr) * KD + k0 + cc8];
        uint32_t sa = sA + (uint32_t)((st * 128 + cr) * ASS + cc8) * 4u;
        cpa16(sa, ga); cpa16(sa + 16, ga + 4);
        const float* gb = &Bt[(size_t)(bn + cr) * KD + k0 + cc8];
        uint32_t sb = sB + (uint32_t)((st * 128 + cr) * ASS + cc8) * 4u;
        cpa16(sb, gb); cpa16(sb + 16, gb + 4);
    };

    issue(0, 0);       cp_commit();
    issue(1, BK);      cp_commit();

    int st = 0;
    for (int it = 0; it < NIT; it++) {
        if (it + 1 < NIT) cp_wait<1>(); else cp_wait<0>();
        __syncthreads();
        const uint32_t aB = sA + (uint32_t)(st * 128 * ASS) * 4u;
        const uint32_t bB = sB + (uint32_t)(st * 128 * ASS) * 4u;

        uint32_t af[2][4][4], bf[2][4][2];
#pragma unroll
        for (int ks = 0; ks < 2; ks++) {
            const int kk = ks * 8;
#pragma unroll
            for (int mi = 0; mi < 4; mi++) {
                uint32_t ad = aB + (uint32_t)(((wm0 + 16 * mi + a_ro) * ASS) + kk + a_co) * 4u;
                ldsm4(af[ks][mi][0], af[ks][mi][1], af[ks][mi][2], af[ks][mi][3], ad);
            }
#pragma unroll
            for (int p = 0; p < 2; p++) {
                uint32_t bd = bB + (uint32_t)(((wn0 + 16 * p + b_ro) * ASS) + kk + b_co) * 4u;
                ldsm4(bf[ks][2 * p][0], bf[ks][2 * p][1], bf[ks][2 * p + 1][0], bf[ks][2 * p + 1][1], bd);
            }
        }
#pragma unroll
        for (int ks = 0; ks < 2; ks++)
#pragma unroll
            for (int mi = 0; mi < 4; mi++)
#pragma unroll
                for (int nj = 0; nj < 4; nj++)
                    mma_tf32(acc[mi][nj], af[ks][mi], bf[ks][nj]);

        if (it + 2 < NIT) {
            int wst = (st + 2) % 3;
            issue(wst, (it + 2) * BK);
            cp_commit();
        }
        st = (st + 1) % 3;
    }

#pragma unroll
    for (int mi = 0; mi < 4; mi++) {
#pragma unroll
        for (int nj = 0; nj < 4; nj++) {
            int row = bm + wm0 + 16 * mi + (lane >> 2);
            int col = bn + wn0 + 8 * nj + 2 * (lane & 3);
            float bx = 0.0f, by = 0.0f;
            if (HASBIAS) { bx = bia[col]; by = bia[col + 1]; }
            float v0x = acc[mi][nj][0] + bx, v0y = acc[mi][nj][1] + by;
            float v1x = acc[mi][nj][2] + bx, v1y = acc[mi][nj][3] + by;
            if (ROUND) {
                v0x = tf32r(v0x); v0y = tf32r(v0y);
                v1x = tf32r(v1x); v1y = tf32r(v1y);
            }
            *(float2*)&C[(size_t)row * N + col] = make_float2(v0x, v0y);
            *(float2*)&C[(size_t)(row + 8) * N + col] = make_float2(v1x, v1y);
        }
    }
}

// ---------------------------------------------------------------------------
// Scores kernel: E = 2^(QK^T * scale * log2e) causal-masked, + per-128-block
// row-sum partials. h = blockIdx.z + h0 (head-half pipelining).
// ---------------------------------------------------------------------------
__global__ __launch_bounds__(256, 2) void scores_lm(int h0) {
    constexpr int ASS = 20, BK = 16;
    const int nb = blockIdx.x, mb = blockIdx.y, h = blockIdx.z + h0;
    if (nb > mb) return;
    const int kvh = h >> 2;

    __shared__ float As[3][128 * ASS];
    __shared__ float Bs[3][128 * ASS];
    __shared__ float red[128 * 4];

    const int tid = threadIdx.x;
    const int lane = tid & 31, w = tid >> 5;
    const int wm0 = (w & 1) * 64;
    const int wn0 = (w >> 1) * 32;

    const int cr = tid & 127;
    const int cc8 = (tid >> 7) * 8;
    const uint32_t sA = (uint32_t)__cvta_generic_to_shared(&As[0][0]);
    const uint32_t sB = (uint32_t)__cvta_generic_to_shared(&Bs[0][0]);

    const int g = lane >> 3, r = lane & 7;
    const int a_ro = (g & 1) * 8 + r, a_co = (g >> 1) * 4;
    const int b_ro = (g >> 1) * 8 + r, b_co = (g & 1) * 4;

    const float* Qg = g_q + (size_t)(mb * 128) * DMODEL + h * HDIM;
    const float* Kg = g_k + (size_t)(nb * 128) * KV_DM + kvh * HDIM;

    float acc[4][4][4];
#pragma unroll
    for (int mi = 0; mi < 4; mi++)
#pragma unroll
        for (int nj = 0; nj < 4; nj++)
#pragma unroll
            for (int c = 0; c < 4; c++) acc[mi][nj][c] = 0.0f;

    auto issue = [&](int st, int k0) {
        const float* ga = &Qg[(size_t)cr * DMODEL + k0 + cc8];
        uint32_t sa = sA + (uint32_t)((st * 128 + cr) * ASS + cc8) * 4u;
        cpa16(sa, ga); cpa16(sa + 16, ga + 4);
        const float* gb = &Kg[(size_t)cr * KV_DM + k0 + cc8];
        uint32_t sb = sB + (uint32_t)((st * 128 + cr) * ASS + cc8) * 4u;
        cpa16(sb, gb); cpa16(sb + 16, gb + 4);
    };

    issue(0, 0);      cp_commit();
    issue(1, BK);     cp_commit();

    constexpr int NIT = HDIM / BK;
    int st = 0;
    for (int it = 0; it < NIT; it++) {
        if (it + 1 < NIT) cp_wait<1>(); else cp_wait<0>();
        __syncthreads();
        const uint32_t aB = sA + (uint32_t)(st * 128 * ASS) * 4u;
        const uint32_t bB = sB + (uint32_t)(st * 128 * ASS) * 4u;
        uint32_t af[2][4][4], bf[2][4][2];
#pragma unroll
        for (int ks = 0; ks < 2; ks++) {
            const int kk = ks * 8;
#pragma unroll
            for (int mi = 0; mi < 4; mi++) {
                uint32_t ad = aB + (uint32_t)(((wm0 + 16 * mi + a_ro) * ASS) + kk + a_co) * 4u;
                ldsm4(af[ks][mi][0], af[ks][mi][1], af[ks][mi][2], af[ks][mi][3], ad);
            }
#pragma unroll
            for (int p = 0; p < 2; p++) {
                uint32_t bd = bB + (uint32_t)(((wn0 + 16 * p + b_ro) * ASS) + kk + b_co) * 4u;
                ldsm4(bf[ks][2 * p][0], bf[ks][2 * p][1], bf[ks][2 * p + 1][0], bf[ks][2 * p + 1][1], bd);
            }
        }
#pragma unroll
        for (int ks = 0; ks < 2; ks++)
#pragma unroll
            for (int mi = 0; mi < 4; mi++)
#pragma unroll
                for (int nj = 0; nj < 4; nj++)
                    mma_tf32(acc[mi][nj], af[ks][mi], bf[ks][nj]);

        if (it + 2 < NIT) {
            int wst = (st + 2) % 3;
            issue(wst, (it + 2) * BK);
            cp_commit();
        }
        st = (st + 1) % 3;
    }

    const float SCL2 = 0.08838834764831845f * 1.4426950408889634f;
    float* Eh = g_E + (size_t)h * S_LEN * S_LEN;
    float rs[4][2];
#pragma unroll
    for (int mi = 0; mi < 4; mi++) { rs[mi][0] = 0.f; rs[mi][1] = 0.f; }

#pragma unroll
    for (int mi = 0; mi < 4; mi++) {
#pragma unroll
        for (int nj = 0; nj < 4; nj++) {
            int row = mb * 128 + wm0 + 16 * mi + (lane >> 2);
            int col = nb * 128 + wn0 + 8 * nj + 2 * (lane & 3);
            float e0 = (col     <= row)     ? ex2f(acc[mi][nj][0] * SCL2) : 0.f;
            float e1 = (col + 1 <= row)     ? ex2f(acc[mi][nj][1] * SCL2) : 0.f;
            float e2 = (col     <= row + 8) ? ex2f(acc[mi][nj][2] * SCL2) : 0.f;
            float e3 = (col + 1 <= row + 8) ? ex2f(acc[mi][nj][3] * SCL2) : 0.f;
            *(float2*)&Eh[(size_t)row * S_LEN + col] = make_float2(e0, e1);
            *(float2*)&Eh[(size_t)(row + 8) * S_LEN + col] = make_float2(e2, e3);
            rs[mi][0] += e0 + e1;
            rs[mi][1] += e2 + e3;
        }
    }
#pragma unroll
    for (int mi = 0; mi < 4; mi++)
#pragma unroll
        for (int hh = 0; hh < 2; hh++) {
            rs[mi][hh] += __shfl_xor_sync(0xFFFFFFFFu, rs[mi][hh], 1);
            rs[mi][hh] += __shfl_xor_sync(0xFFFFFFFFu, rs[mi][hh], 2);
        }
    if ((lane & 3) == 0) {
        int wg = w >> 1;
#pragma unroll
        for (int mi = 0; mi < 4; mi++) {
            red[(wm0 + 16 * mi + (lane >> 2)) * 4 + wg]     = rs[mi][0];
            red[(wm0 + 16 * mi + 8 + (lane >> 2)) * 4 + wg] = rs[mi][1];
        }
    }
    __syncthreads();
    if (tid < 128)
        g_lpart[((size_t)h * S_LEN + mb * 128 + tid) * 16 + nb] =
            red[tid * 4] + red[tid * 4 + 1] + red[tid * 4 + 2] + red[tid * 4 + 3];
}

// ---------------------------------------------------------------------------
// Attention over E: single pass. p = E * il -> smem, colsums + P@V.
// h = blockIdx.y + h0 (head-half pipelining).
// ---------------------------------------------------------------------------
#define SP_OFF   0
#define VS_OFF   8704
#define RED_OFF  17408
#define IL_OFF   17920
#define ATTN_SMEM ((17920 + 128) * 4)

__global__ __launch_bounds__(512, 1) void attn_pv(int h0) {
    extern __shared__ float smem[];
    float* sP  = smem + SP_OFF;     // [128][68]
    float* Vs  = smem + VS_OFF;     // [64][136]
    float* red = smem + RED_OFF;    // [512]
    float* il  = smem + IL_OFF;     // [128]

    const int qt = 15 - blockIdx.x;
    const int h  = blockIdx.y + h0;
    const int kvh = h >> 2;
    const int qbase = qt * 128;
    const int tid = threadIdx.x;
    const int lane = tid & 31, w = tid >> 5;
    const int wm  = (w & 3) * 32;
    const int wn2 = (w >> 2) * 32;

    const int g = lane >> 3, r = lane & 7;
    const int a_ro = (g & 1) * 8 + r, a_co = (g >> 1) * 4;
    const uint32_t sPT = (uint32_t)__cvta_generic_to_shared(sP);

    const float* Eh = g_E + (size_t)h * S_LEN * S_LEN;

    if (tid < 128) {
        const float* lp = &g_lpart[((size_t)h * S_LEN + qbase + tid) * 16];
        float l = 0.0f;
        for (int nb = 0; nb <= qt; nb++) l += lp[nb];
        il[tid] = 1.0f / l;
    }
    __syncthreads();

    const int prow = tid >> 2;
    const int pcb = (tid & 3) * 16;
    const float myil = il[prow];

    float o[2][4][4];
#pragma unroll
    for (int mi = 0; mi < 2; mi++)
#pragma unroll
        for (int nj = 0; nj < 4; nj++)
#pragma unroll
            for (int c = 0; c < 4; c++) o[mi][nj][c] = 0.0f;

    const int nkt = 2 * qt + 2;
    for (int kt = 0; kt < nkt; kt++) {
        {
            const float* ep = &Eh[(size_t)(qbase + prow) * S_LEN + kt * 64 + pcb];
#pragma unroll
            for (int i = 0; i < 4; i++) {
                float4 v = *(const float4*)&ep[4 * i];
                v.x *= myil; v.y *= myil; v.z *= myil; v.w *= myil;
                *(float4*)&sP[prow * 68 + pcb + 4 * i] = v;
            }
            int vr = tid >> 3, vcb = (tid & 7) * 16;
            const float* vp = &g_v[(size_t)(kt * 64 + vr) * KV_DM + kvh * HDIM + vcb];
#pragma unroll
            for (int i = 0; i < 4; i++)
                *(float4*)&Vs[vr * 136 + vcb + 4 * i] = *(const float4*)&vp[4 * i];
        }
        __syncthreads();

        if (tid < 256) {
            int c = tid & 63, seg = tid >> 6;
            float cs = 0.0f;
#pragma unroll 8
            for (int q = 0; q < 32; q++) cs += sP[(seg * 32 + q) * 68 + c];
            red[c * 4 + seg] = cs;
        }

#pragma unroll
        for (int ks = 0; ks < 8; ks++) {
            const int kk = ks * 8;
            uint32_t af[2][4], bf[4][2];
#pragma unroll
            for (int mi = 0; mi < 2; mi++) {
                uint32_t ad = sPT + (uint32_t)(((wm + 16 * mi + a_ro) * 68) + kk + a_co) * 4u;
                ldsm4(af[mi][0], af[mi][1], af[mi][2], af[mi][3], ad);
            }
#pragma unroll
            for (int nj = 0; nj < 4; nj++) {
                int n0 = wn2 + 8 * nj + (lane >> 2);
                bf[nj][0] = __float_as_uint(Vs[(kk + (lane & 3)) * 136 + n0]);
                bf[nj][1] = __float_as_uint(Vs[(kk + 4 + (lane & 3)) * 136 + n0]);
            }
#pragma unroll
            for (int mi = 0; mi < 2; mi++)
#pragma unroll
                for (int nj = 0; nj < 4; nj++)
                    mma_tf32(o[mi][nj], af[mi], bf[nj]);
        }
        __syncthreads();
        if (tid < 64)
            g_colpart[((size_t)h * NQT16 + qt) * S_LEN + kt * 64 + tid] =
                red[tid * 4] + red[tid * 4 + 1] + red[tid * 4 + 2] + red[tid * 4 + 3];
    }

#pragma unroll
    for (int mi = 0; mi < 2; mi++)
#pragma unroll
        for (int nj = 0; nj < 4; nj++) {
            int row = qbase + wm + 16 * mi + (lane >> 2);
            int col = h * HDIM + wn2 + 8 * nj + 2 * (lane & 3);
            *(float2*)&g_ctx[(size_t)row * DMODEL + col] =
                make_float2(tf32r(o[mi][nj][0]), tf32r(o[mi][nj][1]));
            *(float2*)&g_ctx[(size_t)(row + 8) * DMODEL + col] =
                make_float2(tf32r(o[mi][nj][2]), tf32r(o[mi][nj][3]));
        }
}

// ---------------------------------------------------------------------------
// Heavy-hitter mask via bitonic sort (exact jax.lax.top_k tie semantics).
// ---------------------------------------------------------------------------
__global__ __launch_bounds__(1024) void topk_kernel(float* __restrict__ mask_out) {
    const int h = blockIdx.x;
    const int tid = threadIdx.x;
    __shared__ unsigned long long keys[2048];

    for (int i = tid; i < 2048; i += 1024) {
        unsigned ev = 0u;
        if (i < SEL) {
            float s = 0.0f;
#pragma unroll
            for (int qt = 0; qt < NQT16; qt++)
                s += g_colpart[((size_t)h * NQT16 + qt) * S_LEN + i];
            ev = encf(s);
        }
        keys[i] = ((unsigned long long)ev << 32) | (unsigned)(2047 - i);
    }
    float* mrow = mask_out + (size_t)h * MASKW;
    for (int i = tid; i < MASKW; i += 1024)
        mrow[i] = (i >= (MASKW - RECENT)) ? 1.0f : 0.0f;
    __syncthreads();

    for (int k = 2; k <= 2048; k <<= 1) {
        for (int j = k >> 1; j > 0; j >>= 1) {
            for (int idx = tid; idx < 2048; idx += 1024) {
                int ixj = idx ^ j;
                if (ixj > idx) {
                    unsigned long long a = keys[idx], b = keys[ixj];
                    bool up = (idx & k) == 0;
                    if (up ? (a > b) : (a < b)) { keys[idx] = b; keys[ixj] = a; }
                }
            }
            __syncthreads();
        }
    }
    for (int i = 2048 - HEAVY + tid; i < 2048; i += 1024) {
        int idx = 2047 - (int)(keys[i] & 0xFFFFFFFFu);
        mrow[idx] = 1.0f;
    }
}

// ---------------------------------------------------------------------------
extern "C" void kernel_launch(void* const* d_in, const int* in_sizes, int n_in,
                              void* d_out, int out_size) {
    (void)in_sizes; (void)n_in; (void)out_size;
    const float* hidden = (const float*)d_in[0];
    const float* q_w = (const float*)d_in[1];
    const float* q_b = (const float*)d_in[2];
    const float* k_w = (const float*)d_in[3];
    const float* k_b = (const float*)d_in[4];
    const float* v_w = (const float*)d_in[5];
    const float* v_b = (const float*)d_in[6];
    const float* o_w = (const float*)d_in[7];
    float* out = (float*)d_out;

    static bool init = false;
    static cudaStream_t sA, sB, sC;
    static cudaEvent_t evRoot, evHid, evKV, evZero, evTrrO, evTrrQ,
                       evS1, evA0, evA1, evDoneA, evDoneC;
    if (!init) {
        cudaFuncSetAttribute(attn_pv, cudaFuncAttributeMaxDynamicSharedMemorySize, ATTN_SMEM);
        cudaStreamCreateWithFlags(&sA, cudaStreamNonBlocking);
        cudaStreamCreateWithFlags(&sB, cudaStreamNonBlocking);
        cudaStreamCreateWithFlags(&sC, cudaStreamNonBlocking);
        cudaEventCreateWithFlags(&evRoot, cudaEventDisableTiming);
        cudaEventCreateWithFlags(&evHid,  cudaEventDisableTiming);
        cudaEventCreateWithFlags(&evKV,   cudaEventDisableTiming);
        cudaEventCreateWithFlags(&evZero, cudaEventDisableTiming);
        cudaEventCreateWithFlags(&evTrrO, cudaEventDisableTiming);
        cudaEventCreateWithFlags(&evTrrQ, cudaEventDisableTiming);
        cudaEventCreateWithFlags(&evS1,   cudaEventDisableTiming);
        cudaEventCreateWithFlags(&evA0,   cudaEventDisableTiming);
        cudaEventCreateWithFlags(&evA1,   cudaEventDisableTiming);
        cudaEventCreateWithFlags(&evDoneA, cudaEventDisableTiming);
        cudaEventCreateWithFlags(&evDoneC, cudaEventDisableTiming);
        init = true;
    }

    float *ghid, *gqwT, *gkwT, *gvwT, *gowT, *gq, *gk, *gv, *gctx, *gcp;
    cudaGetSymbolAddress((void**)&ghid, g_hid);
    cudaGetSymbolAddress((void**)&gqwT, g_qwT);
    cudaGetSymbolAddress((void**)&gkwT, g_kwT);
    cudaGetSymbolAddress((void**)&gvwT, g_vwT);
    cudaGetSymbolAddress((void**)&gowT, g_owT);
    cudaGetSymbolAddress((void**)&gq,   g_q);
    cudaGetSymbolAddress((void**)&gk,   g_k);
    cudaGetSymbolAddress((void**)&gv,   g_v);
    cudaGetSymbolAddress((void**)&gctx, g_ctx);
    cudaGetSymbolAddress((void**)&gcp,  g_colpart);

    // fork from the capture (legacy) stream
    cudaEventRecord(evRoot, 0);
    cudaStreamWaitEvent(sA, evRoot, 0);
    cudaStreamWaitEvent(sB, evRoot, 0);
    cudaStreamWaitEvent(sC, evRoot, 0);

    dim3 tb(32, 8);
    // sA: round_hid; sC: trr_q (concurrent)
    round4_kernel<<<(S_LEN * DMODEL / 4 + 255) / 256, 256, 0, sA>>>(
        (float4*)ghid, (const float4*)hidden, S_LEN * DMODEL / 4);
    cudaEventRecord(evHid, sA);
    trr_kernel<<<dim3(DMODEL / 32, DMODEL / 32), tb, 0, sC>>>(gqwT, q_w, DMODEL, DMODEL);
    cudaEventRecord(evTrrQ, sC);
    // sB: trr_k, trr_v
    trr_kernel<<<dim3(KV_DM / 32, DMODEL / 32), tb, 0, sB>>>(gkwT, k_w, DMODEL, KV_DM);
    trr_kernel<<<dim3(KV_DM / 32, DMODEL / 32), tb, 0, sB>>>(gvwT, v_w, DMODEL, KV_DM);
    // sC: trr_o, zero
    trr_kernel<<<dim3(DMODEL / 32, DMODEL / 32), tb, 0, sC>>>(gowT, o_w, DMODEL, DMODEL);
    cudaEventRecord(evTrrO, sC);

    // Q projection (128x128, 2 CTAs/SM — proven config)
    cudaStreamWaitEvent(sA, evTrrQ, 0);
    gemm_lm<true, true><<<dim3(DMODEL / 128, S_LEN / 128, 1), 256, 0, sA>>>(
        ghid, gqwT, nullptr, q_b, nullptr, gq, nullptr, DMODEL);

    // KV projections (z-fused), concurrent with Q
    cudaStreamWaitEvent(sB, evHid, 0);
    gemm_lm<true, true><<<dim3(KV_DM / 128, S_LEN / 128, 2), 256, 0, sB>>>(
        ghid, gkwT, gvwT, k_b, v_b, gk, gv, KV_DM);
    cudaEventRecord(evKV, sB);

    const int ncp = NH * NQT16 * S_LEN;
    zero_kernel<<<(ncp + 255) / 256, 256, 0, sC>>>(gcp, ncp);
    cudaEventRecord(evZero, sC);

    // head-half pipelined scores/attn:
    //   sA: scores[0..7]  -> attn[0..7]
    //   sB: scores[8..15] -> attn[8..15]
    cudaStreamWaitEvent(sA, evKV, 0);
    scores_lm<<<dim3(16, 16, 8), 256, 0, sA>>>(0);
    scores_lm<<<dim3(16, 16, 8), 256, 0, sB>>>(8);
    cudaEventRecord(evS1, sB);

    cudaStreamWaitEvent(sA, evZero, 0);
    attn_pv<<<dim3(16, 8), 512, ATTN_SMEM, sA>>>(0);
    cudaEventRecord(evA0, sA);

    cudaStreamWaitEvent(sB, evZero, 0);
    attn_pv<<<dim3(16, 8), 512, ATTN_SMEM, sB>>>(8);
    cudaEventRecord(evA1, sB);

    // sC: topk (after both attn halves), overlaps with gemmO on sA
    cudaStreamWaitEvent(sC, evA0, 0);
    cudaStreamWaitEvent(sC, evA1, 0);
    topk_kernel<<<NH, 1024, 0, sC>>>(out + (size_t)S_LEN * DMODEL);
    cudaEventRecord(evDoneC, sC);

    // output projection (128x128, 2 CTAs/SM)
    cudaStreamWaitEvent(sA, evA1, 0);
    cudaStreamWaitEvent(sA, evTrrO, 0);
    gemm_lm<false, false><<<dim3(DMODEL / 128, S_LEN / 128, 1), 256, 0, sA>>>(
        gctx, gowT, nullptr, nullptr, nullptr, out, nullptr, DMODEL);
    cudaEventRecord(evDoneA, sA);

    // join back to the capture stream
    cudaStreamWaitEvent(0, evDoneA, 0);
    cudaStreamWaitEvent(0, evDoneC, 0);
}

// round 10
// speedup vs baseline: 1.5021x; 1.4619x over previous
#include <cuda_runtime.h>
#include <cuda_fp16.h>
#include <cstdint>

#define S_LEN   2048
#define DMODEL  2048
#define NH      16
#define HDIM    128
#define KV_DM   512
#define NQT16   16
#define HEAVY   204
#define RECENT  204
#define SEL     (S_LEN - RECENT)    // 1844
#define MASKW   (S_LEN + 1)         // 2049

__device__ __half g_hid[S_LEN * DMODEL];
__device__ __half g_qwT[DMODEL * DMODEL];   // [n][k]
__device__ __half g_kwT[KV_DM * DMODEL];
__device__ __half g_vwT[KV_DM * DMODEL];
__device__ __half g_owT[DMODEL * DMODEL];
__device__ __half g_q[S_LEN * DMODEL];
__device__ __half g_k[S_LEN * KV_DM];
__device__ float  g_v[S_LEN * KV_DM];       // V stays f32 (tf32 P@V path)
__device__ __half g_ctx[S_LEN * DMODEL];
__device__ float  g_colpart[NH * NQT16 * S_LEN];
__device__ float  g_lpart[NH * S_LEN * 16];
__device__ float  g_E[(size_t)NH * S_LEN * S_LEN];

// ---------------------------------------------------------------------------
__device__ __forceinline__ float tf32r(float x) {
    uint32_t u;
    asm("cvt.rna.tf32.f32 %0, %1;" : "=r"(u) : "f"(x));
    return __uint_as_float(u);
}
__device__ __forceinline__ float ex2f(float x) {
    float y;
    asm("ex2.approx.ftz.f32 %0, %1;" : "=f"(y) : "f"(x));
    return y;
}
__device__ __forceinline__ void mma_tf32(float* c, const uint32_t* a, const uint32_t* b) {
    asm volatile(
        "mma.sync.aligned.m16n8k8.row.col.f32.tf32.tf32.f32 "
        "{%0,%1,%2,%3}, {%4,%5,%6,%7}, {%8,%9}, {%0,%1,%2,%3};"
        : "+f"(c[0]), "+f"(c[1]), "+f"(c[2]), "+f"(c[3])
        : "r"(a[0]), "r"(a[1]), "r"(a[2]), "r"(a[3]), "r"(b[0]), "r"(b[1]));
}
__device__ __forceinline__ void mma_f16(float* c, const uint32_t* a, const uint32_t* b) {
    asm volatile(
        "mma.sync.aligned.m16n8k16.row.col.f32.f16.f16.f32 "
        "{%0,%1,%2,%3}, {%4,%5,%6,%7}, {%8,%9}, {%0,%1,%2,%3};"
        : "+f"(c[0]), "+f"(c[1]), "+f"(c[2]), "+f"(c[3])
        : "r"(a[0]), "r"(a[1]), "r"(a[2]), "r"(a[3]), "r"(b[0]), "r"(b[1]));
}
__device__ __forceinline__ void ldsm4(uint32_t& r0, uint32_t& r1, uint32_t& r2, uint32_t& r3,
                                      uint32_t addr) {
    asm volatile("ldmatrix.sync.aligned.m8n8.x4.shared.b16 {%0,%1,%2,%3}, [%4];"
                 : "=r"(r0), "=r"(r1), "=r"(r2), "=r"(r3) : "r"(addr));
}
__device__ __forceinline__ void cpa16(uint32_t s, const void* g) {
    asm volatile("cp.async.cg.shared.global [%0], [%1], 16;" :: "r"(s), "l"(g));
}
__device__ __forceinline__ void cp_commit() { asm volatile("cp.async.commit_group;"); }
template<int N> __device__ __forceinline__ void cp_wait() {
    asm volatile("cp.async.wait_group %0;" :: "n"(N));
}
__device__ __forceinline__ unsigned encf(float x) {
    unsigned b = __float_as_uint(x);
    return (b & 0x80000000u) ? ~b : (b | 0x80000000u);
}

__global__ void zero_kernel(float* p, int n) {
    int i = blockIdx.x * 256 + threadIdx.x;
    if (i < n) p[i] = 0.0f;
}
// f32 -> f16, 8 elems/thread
__global__ void f2h_kernel(__half* dst, const float* src, int n8) {
    int i = blockIdx.x * 256 + threadIdx.x;
    if (i < n8) {
        const float4 v0 = *(const float4*)&src[i * 8];
        const float4 v1 = *(const float4*)&src[i * 8 + 4];
        __half2 h[4];
        h[0] = __floats2half2_rn(v0.x, v0.y);
        h[1] = __floats2half2_rn(v0.z, v0.w);
        h[2] = __floats2half2_rn(v1.x, v1.y);
        h[3] = __floats2half2_rn(v1.z, v1.w);
        *(uint4*)&dst[i * 8] = *(uint4*)h;
    }
}
// transpose + f16: src [Kd][Nd] f32 -> dst [Nd][Kd] f16
__global__ __launch_bounds__(256) void trrh_kernel(__half* dst, const float* src, int Kd, int Nd) {
    __shared__ float t[32][33];
    const int bx = blockIdx.x * 32;   // n
    const int by = blockIdx.y * 32;   // k
    const int tx = threadIdx.x, ty = threadIdx.y;
#pragma unroll
    for (int i = 0; i < 32; i += 8)
        t[ty + i][tx] = src[(size_t)(by + ty + i) * Nd + bx + tx];
    __syncthreads();
#pragma unroll
    for (int i = 0; i < 32; i += 8)
        dst[(size_t)(bx + ty + i) * Kd + by + tx] = __float2half_rn(t[tx][ty + i]);
}

// ---------------------------------------------------------------------------
// fp16 GEMM: 128x128 tile, BK=32, ldmatrix b16 + 3-stage cp.async,
// 1 barrier/iter, 2 CTAs/SM. A [M][2048] f16, Bt [N][2048] f16.
// blockIdx.z selects (Bt,bias,C). OUT*_HALF: C dtype. ROUNDF: tf32-round f32 out.
// ---------------------------------------------------------------------------
#define GEMM_H_SMEM (2 * (3 * 128 * 40) * 2)

template<bool OUT0_HALF, bool OUT1_HALF, bool HASBIAS, bool ROUNDF>
__global__ __launch_bounds__(256, 2) void gemm_h(
    const __half* __restrict__ A,
    const __half* __restrict__ Bt0, const __half* __restrict__ Bt1,
    const float* __restrict__ bias0, const float* __restrict__ bias1,
    void* __restrict__ C0, void* __restrict__ C1, int N)
{
    constexpr int KD = 2048, BK = 32, ASS = 40;
    constexpr int NIT = KD / BK;

    extern __shared__ __half smem_h[];
    __half* AsH = smem_h;
    __half* BsH = smem_h + 3 * 128 * ASS;

    const int tid = threadIdx.x;
    const int lane = tid & 31, w = tid >> 5;
    const int wm0 = (w & 1) * 64;
    const int wn0 = (w >> 1) * 32;
    const int bm = blockIdx.y * 128;
    const int bn = blockIdx.x * 128;

    const __half* Bt = (blockIdx.z == 0) ? Bt0 : Bt1;
    const float* bia = (blockIdx.z == 0) ? bias0 : bias1;

    const int cr = tid & 127;
    const int co = (tid >> 7) * 16;     // half-offset 0 or 16
    const uint32_t sA = (uint32_t)__cvta_generic_to_shared(AsH);
    const uint32_t sB = (uint32_t)__cvta_generic_to_shared(BsH);

    // ldmatrix lane addressing (16-bit elements)
    const int a_row = lane & 15;
    const int a_k8  = (lane >> 4) * 8;
    const int b_row = (lane & 7) + ((lane >> 3) & 1) * 8;
    const int b_k8  = (lane >> 4) * 8;

    float acc[4][4][4];
#pragma unroll
    for (int mi = 0; mi < 4; mi++)
#pragma unroll
        for (int nj = 0; nj < 4; nj++)
#pragma unroll
            for (int c = 0; c < 4; c++) acc[mi][nj][c] = 0.0f;

    auto issue = [&](int st, int k0) {
        const __half* ga = &A[(size_t)(bm + cr) * KD + k0 + co];
        uint32_t sa = sA + (uint32_t)((st * 128 + cr) * ASS + co) * 2u;
        cpa16(sa, ga); cpa16(sa + 16, ga + 8);
        const __half* gb = &Bt[(size_t)(bn + cr) * KD + k0 + co];
        uint32_t sb = sB + (uint32_t)((st * 128 + cr) * ASS + co) * 2u;
        cpa16(sb, gb); cpa16(sb + 16, gb + 8);
    };

    issue(0, 0);       cp_commit();
    issue(1, BK);      cp_commit();

    int st = 0;
    for (int it = 0; it < NIT; it++) {
        if (it + 1 < NIT) cp_wait<1>(); else cp_wait<0>();
        __syncthreads();
        const uint32_t aB = sA + (uint32_t)(st * 128 * ASS) * 2u;
        const uint32_t bB = sB + (uint32_t)(st * 128 * ASS) * 2u;

#pragma unroll
        for (int ks = 0; ks < 2; ks++) {
            const int kk = ks * 16;
            uint32_t af[4][4], bf[4][2];
#pragma unroll
            for (int mi = 0; mi < 4; mi++) {
                uint32_t ad = aB + (uint32_t)(((wm0 + 16 * mi + a_row) * ASS) + kk + a_k8) * 2u;
                ldsm4(af[mi][0], af[mi][1], af[mi][2], af[mi][3], ad);
            }
#pragma unroll
            for (int p = 0; p < 2; p++) {
                uint32_t bd = bB + (uint32_t)(((wn0 + 16 * p + b_row) * ASS) + kk + b_k8) * 2u;
                uint32_t r0, r1, r2, r3;
                ldsm4(r0, r1, r2, r3, bd);
                bf[2 * p][0] = r0; bf[2 * p][1] = r2;
                bf[2 * p + 1][0] = r1; bf[2 * p + 1][1] = r3;
            }
#pragma unroll
            for (int mi = 0; mi < 4; mi++)
#pragma unroll
                for (int nj = 0; nj < 4; nj++)
                    mma_f16(acc[mi][nj], af[mi], bf[nj]);
        }

        if (it + 2 < NIT) {
            issue((st + 2) % 3, (it + 2) * BK);
            cp_commit();
        }
        st = (st + 1) % 3;
    }

    const bool outHalf = (blockIdx.z == 0) ? OUT0_HALF : OUT1_HALF;
    void* C = (blockIdx.z == 0) ? C0 : C1;
#pragma unroll
    for (int mi = 0; mi < 4; mi++) {
#pragma unroll
        for (int nj = 0; nj < 4; nj++) {
            int row = bm + wm0 + 16 * mi + (lane >> 2);
            int col = bn + wn0 + 8 * nj + 2 * (lane & 3);
            float bx = 0.0f, by = 0.0f;
            if (HASBIAS) { bx = bia[col]; by = bia[col + 1]; }
            float v0x = acc[mi][nj][0] + bx, v0y = acc[mi][nj][1] + by;
            float v1x = acc[mi][nj][2] + bx, v1y = acc[mi][nj][3] + by;
            if (outHalf) {
                __half* Ch = (__half*)C;
                *(__half2*)&Ch[(size_t)row * N + col] = __floats2half2_rn(v0x, v0y);
                *(__half2*)&Ch[(size_t)(row + 8) * N + col] = __floats2half2_rn(v1x, v1y);
            } else {
                float* Cf = (float*)C;
                if (ROUNDF) {
                    v0x = tf32r(v0x); v0y = tf32r(v0y);
                    v1x = tf32r(v1x); v1y = tf32r(v1y);
                }
                *(float2*)&Cf[(size_t)row * N + col] = make_float2(v0x, v0y);
                *(float2*)&Cf[(size_t)(row + 8) * N + col] = make_float2(v1x, v1y);
            }
        }
    }
}

// ---------------------------------------------------------------------------
// Scores (fp16): E = 2^(QK^T * scale * log2e) causal-masked + row-sum partials.
// Q [m][2048] f16, K [n][512] f16. BK=32, NIT=4.
// ---------------------------------------------------------------------------
#define SCORES_SMEM (2 * (3 * 128 * 40) * 2 + 128 * 4 * 4)

__global__ __launch_bounds__(256, 2) void scores_h() {
    constexpr int ASS = 40, BK = 32;
    const int nb = blockIdx.x, mb = blockIdx.y, h = blockIdx.z;
    if (nb > mb) return;
    const int kvh = h >> 2;

    extern __shared__ __half smem_h[];
    __half* AsH = smem_h;
    __half* BsH = smem_h + 3 * 128 * ASS;
    float* red = (float*)(smem_h + 2 * 3 * 128 * ASS);

    const int tid = threadIdx.x;
    const int lane = tid & 31, w = tid >> 5;
    const int wm0 = (w & 1) * 64;
    const int wn0 = (w >> 1) * 32;

    const int cr = tid & 127;
    const int co = (tid >> 7) * 16;
    const uint32_t sA = (uint32_t)__cvta_generic_to_shared(AsH);
    const uint32_t sB = (uint32_t)__cvta_generic_to_shared(BsH);

    const int a_row = lane & 15;
    const int a_k8  = (lane >> 4) * 8;
    const int b_row = (lane & 7) + ((lane >> 3) & 1) * 8;
    const int b_k8  = (lane >> 4) * 8;

    const __half* Qg = g_q + (size_t)(mb * 128) * DMODEL + h * HDIM;
    const __half* Kg = g_k + (size_t)(nb * 128) * KV_DM + kvh * HDIM;

    float acc[4][4][4];
#pragma unroll
    for (int mi = 0; mi < 4; mi++)
#pragma unroll
        for (int nj = 0; nj < 4; nj++)
#pragma unroll
            for (int c = 0; c < 4; c++) acc[mi][nj][c] = 0.0f;

    auto issue = [&](int st, int k0) {
        const __half* ga = &Qg[(size_t)cr * DMODEL + k0 + co];
        uint32_t sa = sA + (uint32_t)((st * 128 + cr) * ASS + co) * 2u;
        cpa16(sa, ga); cpa16(sa + 16, ga + 8);
        const __half* gb = &Kg[(size_t)cr * KV_DM + k0 + co];
        uint32_t sb = sB + (uint32_t)((st * 128 + cr) * ASS + co) * 2u;
        cpa16(sb, gb); cpa16(sb + 16, gb + 8);
    };

    issue(0, 0);      cp_commit();
    issue(1, BK);     cp_commit();

    constexpr int NIT = HDIM / BK;   // 4
    int st = 0;
    for (int it = 0; it < NIT; it++) {
        if (it + 1 < NIT) cp_wait<1>(); else cp_wait<0>();
        __syncthreads();
        const uint32_t aB = sA + (uint32_t)(st * 128 * ASS) * 2u;
        const uint32_t bB = sB + (uint32_t)(st * 128 * ASS) * 2u;
#pragma unroll
        for (int ks = 0; ks < 2; ks++) {
            const int kk = ks * 16;
            uint32_t af[4][4], bf[4][2];
#pragma unroll
            for (int mi = 0; mi < 4; mi++) {
                uint32_t ad = aB + (uint32_t)(((wm0 + 16 * mi + a_row) * ASS) + kk + a_k8) * 2u;
                ldsm4(af[mi][0], af[mi][1], af[mi][2], af[mi][3], ad);
            }
#pragma unroll
            for (int p = 0; p < 2; p++) {
                uint32_t bd = bB + (uint32_t)(((wn0 + 16 * p + b_row) * ASS) + kk + b_k8) * 2u;
                uint32_t r0, r1, r2, r3;
                ldsm4(r0, r1, r2, r3, bd);
                bf[2 * p][0] = r0; bf[2 * p][1] = r2;
                bf[2 * p + 1][0] = r1; bf[2 * p + 1][1] = r3;
            }
#pragma unroll
            for (int mi = 0; mi < 4; mi++)
#pragma unroll
                for (int nj = 0; nj < 4; nj++)
                    mma_f16(acc[mi][nj], af[mi], bf[nj]);
        }
        if (it + 2 < NIT) {
            issue((st + 2) % 3, (it + 2) * BK);
            cp_commit();
        }
        st = (st + 1) % 3;
    }

    const float SCL2 = 0.08838834764831845f * 1.4426950408889634f;
    float* Eh = g_E + (size_t)h * S_LEN * S_LEN;
    float rs[4][2];
#pragma unroll
    for (int mi = 0; mi < 4; mi++) { rs[mi][0] = 0.f; rs[mi][1] = 0.f; }

#pragma unroll
    for (int mi = 0; mi < 4; mi++) {
#pragma unroll
        for (int nj = 0; nj < 4; nj++) {
            int row = mb * 128 + wm0 + 16 * mi + (lane >> 2);
            int col = nb * 128 + wn0 + 8 * nj + 2 * (lane & 3);
            float e0 = (col     <= row)     ? ex2f(acc[mi][nj][0] * SCL2) : 0.f;
            float e1 = (col + 1 <= row)     ? ex2f(acc[mi][nj][1] * SCL2) : 0.f;
            float e2 = (col     <= row + 8) ? ex2f(acc[mi][nj][2] * SCL2) : 0.f;
            float e3 = (col + 1 <= row + 8) ? ex2f(acc[mi][nj][3] * SCL2) : 0.f;
            *(float2*)&Eh[(size_t)row * S_LEN + col] = make_float2(e0, e1);
            *(float2*)&Eh[(size_t)(row + 8) * S_LEN + col] = make_float2(e2, e3);
            rs[mi][0] += e0 + e1;
            rs[mi][1] += e2 + e3;
        }
    }
#pragma unroll
    for (int mi = 0; mi < 4; mi++)
#pragma unroll
        for (int hh = 0; hh < 2; hh++) {
            rs[mi][hh] += __shfl_xor_sync(0xFFFFFFFFu, rs[mi][hh], 1);
            rs[mi][hh] += __shfl_xor_sync(0xFFFFFFFFu, rs[mi][hh], 2);
        }
    if ((lane & 3) == 0) {
        int wg = w >> 1;
#pragma unroll
        for (int mi = 0; mi < 4; mi++) {
            red[(wm0 + 16 * mi + (lane >> 2)) * 4 + wg]     = rs[mi][0];
            red[(wm0 + 16 * mi + 8 + (lane >> 2)) * 4 + wg] = rs[mi][1];
        }
    }
    __syncthreads();
    if (tid < 128)
        g_lpart[((size_t)h * S_LEN + mb * 128 + tid) * 16 + nb] =
            red[tid * 4] + red[tid * 4 + 1] + red[tid * 4 + 2] + red[tid * 4 + 3];
}

// ---------------------------------------------------------------------------
// Attention over E: single pass, tf32 P@V (unchanged math); ctx written as f16.
// ---------------------------------------------------------------------------
#define SP_OFF   0
#define VS_OFF   8704
#define RED_OFF  17408
#define IL_OFF   17920
#define ATTN_SMEM ((17920 + 128) * 4)

__global__ __launch_bounds__(512, 1) void attn_pv() {
    extern __shared__ float smem[];
    float* sP  = smem + SP_OFF;     // [128][68]
    float* Vs  = smem + VS_OFF;     // [64][136]
    float* red = smem + RED_OFF;    // [512]
    float* il  = smem + IL_OFF;     // [128]

    const int qt = 15 - blockIdx.x;
    const int h  = blockIdx.y;
    const int kvh = h >> 2;
    const int qbase = qt * 128;
    const int tid = threadIdx.x;
    const int lane = tid & 31, w = tid >> 5;
    const int wm  = (w & 3) * 32;
    const int wn2 = (w >> 2) * 32;

    const int g = lane >> 3, r = lane & 7;
    const int a_ro = (g & 1) * 8 + r, a_co = (g >> 1) * 4;
    const uint32_t sPT = (uint32_t)__cvta_generic_to_shared(sP);

    const float* Eh = g_E + (size_t)h * S_LEN * S_LEN;

    if (tid < 128) {
        const float* lp = &g_lpart[((size_t)h * S_LEN + qbase + tid) * 16];
        float l = 0.0f;
        for (int nb = 0; nb <= qt; nb++) l += lp[nb];
        il[tid] = 1.0f / l;
    }
    __syncthreads();

    const int prow = tid >> 2;
    const int pcb = (tid & 3) * 16;
    const float myil = il[prow];

    float o[2][4][4];
#pragma unroll
    for (int mi = 0; mi < 2; mi++)
#pragma unroll
        for (int nj = 0; nj < 4; nj++)
#pragma unroll
            for (int c = 0; c < 4; c++) o[mi][nj][c] = 0.0f;

    const int nkt = 2 * qt + 2;
    for (int kt = 0; kt < nkt; kt++) {
        {
            const float* ep = &Eh[(size_t)(qbase + prow) * S_LEN + kt * 64 + pcb];
#pragma unroll
            for (int i = 0; i < 4; i++) {
                float4 v = *(const float4*)&ep[4 * i];
                v.x *= myil; v.y *= myil; v.z *= myil; v.w *= myil;
                *(float4*)&sP[prow * 68 + pcb + 4 * i] = v;
            }
            int vr = tid >> 3, vcb = (tid & 7) * 16;
            const float* vp = &g_v[(size_t)(kt * 64 + vr) * KV_DM + kvh * HDIM + vcb];
#pragma unroll
            for (int i = 0; i < 4; i++)
                *(float4*)&Vs[vr * 136 + vcb + 4 * i] = *(const float4*)&vp[4 * i];
        }
        __syncthreads();

        if (tid < 256) {
            int c = tid & 63, seg = tid >> 6;
            float cs = 0.0f;
#pragma unroll 8
            for (int q = 0; q < 32; q++) cs += sP[(seg * 32 + q) * 68 + c];
            red[c * 4 + seg] = cs;
        }

#pragma unroll
        for (int ks = 0; ks < 8; ks++) {
            const int kk = ks * 8;
            uint32_t af[2][4], bf[4][2];
#pragma unroll
            for (int mi = 0; mi < 2; mi++) {
                uint32_t ad = sPT + (uint32_t)(((wm + 16 * mi + a_ro) * 68) + kk + a_co) * 4u;
                ldsm4(af[mi][0], af[mi][1], af[mi][2], af[mi][3], ad);
            }
#pragma unroll
            for (int nj = 0; nj < 4; nj++) {
                int n0 = wn2 + 8 * nj + (lane >> 2);
                bf[nj][0] = __float_as_uint(Vs[(kk + (lane & 3)) * 136 + n0]);
                bf[nj][1] = __float_as_uint(Vs[(kk + 4 + (lane & 3)) * 136 + n0]);
            }
#pragma unroll
            for (int mi = 0; mi < 2; mi++)
#pragma unroll
                for (int nj = 0; nj < 4; nj++)
                    mma_tf32(o[mi][nj], af[mi], bf[nj]);
        }
        __syncthreads();
        if (tid < 64)
            g_colpart[((size_t)h * NQT16 + qt) * S_LEN + kt * 64 + tid] =
                red[tid * 4] + red[tid * 4 + 1] + red[tid * 4 + 2] + red[tid * 4 + 3];
    }

#pragma unroll
    for (int mi = 0; mi < 2; mi++)
#pragma unroll
        for (int nj = 0; nj < 4; nj++) {
            int row = qbase + wm + 16 * mi + (lane >> 2);
            int col = h * HDIM + wn2 + 8 * nj + 2 * (lane & 3);
            *(__half2*)&g_ctx[(size_t)row * DMODEL + col] =
                __floats2half2_rn(o[mi][nj][0], o[mi][nj][1]);
            *(__half2*)&g_ctx[(size_t)(row + 8) * DMODEL + col] =
                __floats2half2_rn(o[mi][nj][2], o[mi][nj][3]);
        }
}

// ---------------------------------------------------------------------------
// Heavy-hitter mask via bitonic sort (exact jax.lax.top_k tie semantics).
// ---------------------------------------------------------------------------
__global__ __launch_bounds__(1024) void topk_kernel(float* __restrict__ mask_out) {
    const int h = blockIdx.x;
    const int tid = threadIdx.x;
    __shared__ unsigned long long keys[2048];

    for (int i = tid; i < 2048; i += 1024) {
        unsigned ev = 0u;
        if (i < SEL) {
            float s = 0.0f;
#pragma unroll
            for (int qt = 0; qt < NQT16; qt++)
                s += g_colpart[((size_t)h * NQT16 + qt) * S_LEN + i];
            ev = encf(s);
        }
        keys[i] = ((unsigned long long)ev << 32) | (unsigned)(2047 - i);
    }
    float* mrow = mask_out + (size_t)h * MASKW;
    for (int i = tid; i < MASKW; i += 1024)
        mrow[i] = (i >= (MASKW - RECENT)) ? 1.0f : 0.0f;
    __syncthreads();

    for (int k = 2; k <= 2048; k <<= 1) {
        for (int j = k >> 1; j > 0; j >>= 1) {
            for (int idx = tid; idx < 2048; idx += 1024) {
                int ixj = idx ^ j;
                if (ixj > idx) {
                    unsigned long long a = keys[idx], b = keys[ixj];
                    bool up = (idx & k) == 0;
                    if (up ? (a > b) : (a < b)) { keys[idx] = b; keys[ixj] = a; }
                }
            }
            __syncthreads();
        }
    }
    for (int i = 2048 - HEAVY + tid; i < 2048; i += 1024) {
        int idx = 2047 - (int)(keys[i] & 0xFFFFFFFFu);
        mrow[idx] = 1.0f;
    }
}

// ---------------------------------------------------------------------------
extern "C" void kernel_launch(void* const* d_in, const int* in_sizes, int n_in,
                              void* d_out, int out_size) {
    (void)in_sizes; (void)n_in; (void)out_size;
    const float* hidden = (const float*)d_in[0];
    const float* q_w = (const float*)d_in[1];
    const float* q_b = (const float*)d_in[2];
    const float* k_w = (const float*)d_in[3];
    const float* k_b = (const float*)d_in[4];
    const float* v_w = (const float*)d_in[5];
    const float* v_b = (const float*)d_in[6];
    const float* o_w = (const float*)d_in[7];
    float* out = (float*)d_out;

    static bool init = false;
    static cudaStream_t sA, sB, sC;
    static cudaEvent_t evRoot, evHid, evKV, evZero, evAttn, evTrrO, evTrrQ, evDoneA, evDoneC;
    if (!init) {
        cudaFuncSetAttribute(attn_pv, cudaFuncAttributeMaxDynamicSharedMemorySize, ATTN_SMEM);
        cudaFuncSetAttribute(gemm_h<true, false, true, true>,
                             cudaFuncAttributeMaxDynamicSharedMemorySize, GEMM_H_SMEM);
        cudaFuncSetAttribute(gemm_h<false, false, false, false>,
                             cudaFuncAttributeMaxDynamicSharedMemorySize, GEMM_H_SMEM);
        cudaFuncSetAttribute(scores_h,
                             cudaFuncAttributeMaxDynamicSharedMemorySize, SCORES_SMEM);
        cudaStreamCreateWithFlags(&sA, cudaStreamNonBlocking);
        cudaStreamCreateWithFlags(&sB, cudaStreamNonBlocking);
        cudaStreamCreateWithFlags(&sC, cudaStreamNonBlocking);
        cudaEventCreateWithFlags(&evRoot, cudaEventDisableTiming);
        cudaEventCreateWithFlags(&evHid,  cudaEventDisableTiming);
        cudaEventCreateWithFlags(&evKV,   cudaEventDisableTiming);
        cudaEventCreateWithFlags(&evZero, cudaEventDisableTiming);
        cudaEventCreateWithFlags(&evAttn, cudaEventDisableTiming);
        cudaEventCreateWithFlags(&evTrrO, cudaEventDisableTiming);
        cudaEventCreateWithFlags(&evTrrQ, cudaEventDisableTiming);
        cudaEventCreateWithFlags(&evDoneA, cudaEventDisableTiming);
        cudaEventCreateWithFlags(&evDoneC, cudaEventDisableTiming);
        init = true;
    }

    __half *ghid, *gqwT, *gkwT, *gvwT, *gowT, *gq, *gk, *gctx;
    float *gv, *gcp;
    cudaGetSymbolAddress((void**)&ghid, g_hid);
    cudaGetSymbolAddress((void**)&gqwT, g_qwT);
    cudaGetSymbolAddress((void**)&gkwT, g_kwT);
    cudaGetSymbolAddress((void**)&gvwT, g_vwT);
    cudaGetSymbolAddress((void**)&gowT, g_owT);
    cudaGetSymbolAddress((void**)&gq,   g_q);
    cudaGetSymbolAddress((void**)&gk,   g_k);
    cudaGetSymbolAddress((void**)&gv,   g_v);
    cudaGetSymbolAddress((void**)&gctx, g_ctx);
    cudaGetSymbolAddress((void**)&gcp,  g_colpart);

    // fork from the capture (legacy) stream
    cudaEventRecord(evRoot, 0);
    cudaStreamWaitEvent(sA, evRoot, 0);
    cudaStreamWaitEvent(sB, evRoot, 0);
    cudaStreamWaitEvent(sC, evRoot, 0);

    dim3 tb(32, 8);
    // sA: hid f16; sC: trr_q (concurrent)
    f2h_kernel<<<(S_LEN * DMODEL / 8 + 255) / 256, 256, 0, sA>>>(
        ghid, hidden, S_LEN * DMODEL / 8);
    cudaEventRecord(evHid, sA);
    trrh_kernel<<<dim3(DMODEL / 32, DMODEL / 32), tb, 0, sC>>>(gqwT, q_w, DMODEL, DMODEL);
    cudaEventRecord(evTrrQ, sC);
    // sB: trr_k, trr_v
    trrh_kernel<<<dim3(KV_DM / 32, DMODEL / 32), tb, 0, sB>>>(gkwT, k_w, DMODEL, KV_DM);
    trrh_kernel<<<dim3(KV_DM / 32, DMODEL / 32), tb, 0, sB>>>(gvwT, v_w, DMODEL, KV_DM);
    // sC: trr_o, zero
    trrh_kernel<<<dim3(DMODEL / 32, DMODEL / 32), tb, 0, sC>>>(gowT, o_w, DMODEL, DMODEL);
    cudaEventRecord(evTrrO, sC);

    // Q projection (fp16, out half)
    cudaStreamWaitEvent(sA, evTrrQ, 0);
    gemm_h<true, false, true, true><<<dim3(DMODEL / 128, S_LEN / 128, 1), 256, GEMM_H_SMEM, sA>>>(
        ghid, gqwT, nullptr, q_b, nullptr, gq, nullptr, DMODEL);

    // KV projections (z-fused: K half, V float+tf32r), concurrent with Q
    cudaStreamWaitEvent(sB, evHid, 0);
    gemm_h<true, false, true, true><<<dim3(KV_DM / 128, S_LEN / 128, 2), 256, GEMM_H_SMEM, sB>>>(
        ghid, gkwT, gvwT, k_b, v_b, gk, gv, KV_DM);
    cudaEventRecord(evKV, sB);

    const int ncp = NH * NQT16 * S_LEN;
    zero_kernel<<<(ncp + 255) / 256, 256, 0, sC>>>(gcp, ncp);
    cudaEventRecord(evZero, sC);

    cudaStreamWaitEvent(sA, evKV, 0);
    scores_h<<<dim3(16, 16, NH), 256, SCORES_SMEM, sA>>>();

    cudaStreamWaitEvent(sA, evZero, 0);
    attn_pv<<<dim3(16, NH), 512, ATTN_SMEM, sA>>>();
    cudaEventRecord(evAttn, sA);

    // sC: topk (after attn), overlaps with gemmO on sA
    cudaStreamWaitEvent(sC, evAttn, 0);
    topk_kernel<<<NH, 1024, 0, sC>>>(out + (size_t)S_LEN * DMODEL);
    cudaEventRecord(evDoneC, sC);

    // output projection (fp16 in, f32 out, no bias)
    cudaStreamWaitEvent(sA, evTrrO, 0);
    gemm_h<false, false, false, false><<<dim3(DMODEL / 128, S_LEN / 128, 1), 256, GEMM_H_SMEM, sA>>>(
        gctx, gowT, nullptr, nullptr, nullptr, out, nullptr, DMODEL);
    cudaEventRecord(evDoneA, sA);

    // join back to the capture stream
    cudaStreamWaitEvent(0, evDoneA, 0);
    cudaStreamWaitEvent(0, evDoneC, 0);
}

// round 11
// speedup vs baseline: 1.7339x; 1.1543x over previous
#include <cuda_runtime.h>
#include <cuda_fp16.h>
#include <cstdint>

#define S_LEN   2048
#define DMODEL  2048
#define NH      16
#define HDIM    128
#define KV_DM   512
#define NQT16   16
#define HEAVY   204
#define RECENT  204
#define SEL     (S_LEN - RECENT)    // 1844
#define MASKW   (S_LEN + 1)         // 2049

__device__ __half g_hid[S_LEN * DMODEL];
__device__ __half g_qwT[DMODEL * DMODEL];   // [n][k]
__device__ __half g_kwT[KV_DM * DMODEL];
__device__ __half g_vwT[KV_DM * DMODEL];
__device__ __half g_owT[DMODEL * DMODEL];
__device__ __half g_q[S_LEN * DMODEL];
__device__ __half g_k[S_LEN * KV_DM];
__device__ __half g_v[S_LEN * KV_DM];       // V now fp16 (fp16 P@V path)
__device__ __half g_ctx[S_LEN * DMODEL];
__device__ float  g_colpart[NH * NQT16 * S_LEN];
__device__ float  g_lpart[NH * S_LEN * 16];
__device__ float  g_E[(size_t)NH * S_LEN * S_LEN];

// ---------------------------------------------------------------------------
__device__ __forceinline__ float tf32r(float x) {
    uint32_t u;
    asm("cvt.rna.tf32.f32 %0, %1;" : "=r"(u) : "f"(x));
    return __uint_as_float(u);
}
__device__ __forceinline__ float ex2f(float x) {
    float y;
    asm("ex2.approx.ftz.f32 %0, %1;" : "=f"(y) : "f"(x));
    return y;
}
__device__ __forceinline__ void mma_f16(float* c, const uint32_t* a, const uint32_t* b) {
    asm volatile(
        "mma.sync.aligned.m16n8k16.row.col.f32.f16.f16.f32 "
        "{%0,%1,%2,%3}, {%4,%5,%6,%7}, {%8,%9}, {%0,%1,%2,%3};"
        : "+f"(c[0]), "+f"(c[1]), "+f"(c[2]), "+f"(c[3])
        : "r"(a[0]), "r"(a[1]), "r"(a[2]), "r"(a[3]), "r"(b[0]), "r"(b[1]));
}
__device__ __forceinline__ void ldsm4(uint32_t& r0, uint32_t& r1, uint32_t& r2, uint32_t& r3,
                                      uint32_t addr) {
    asm volatile("ldmatrix.sync.aligned.m8n8.x4.shared.b16 {%0,%1,%2,%3}, [%4];"
                 : "=r"(r0), "=r"(r1), "=r"(r2), "=r"(r3) : "r"(addr));
}
__device__ __forceinline__ void ldsm4t(uint32_t& r0, uint32_t& r1, uint32_t& r2, uint32_t& r3,
                                       uint32_t addr) {
    asm volatile("ldmatrix.sync.aligned.m8n8.x4.trans.shared.b16 {%0,%1,%2,%3}, [%4];"
                 : "=r"(r0), "=r"(r1), "=r"(r2), "=r"(r3) : "r"(addr));
}
__device__ __forceinline__ void cpa16(uint32_t s, const void* g) {
    asm volatile("cp.async.cg.shared.global [%0], [%1], 16;" :: "r"(s), "l"(g));
}
__device__ __forceinline__ void cp_commit() { asm volatile("cp.async.commit_group;"); }
template<int N> __device__ __forceinline__ void cp_wait() {
    asm volatile("cp.async.wait_group %0;" :: "n"(N));
}
__device__ __forceinline__ unsigned encf(float x) {
    unsigned b = __float_as_uint(x);
    return (b & 0x80000000u) ? ~b : (b | 0x80000000u);
}

__global__ void zero_kernel(float* p, int n) {
    int i = blockIdx.x * 256 + threadIdx.x;
    if (i < n) p[i] = 0.0f;
}
// f32 -> f16, 8 elems/thread
__global__ void f2h_kernel(__half* dst, const float* src, int n8) {
    int i = blockIdx.x * 256 + threadIdx.x;
    if (i < n8) {
        const float4 v0 = *(const float4*)&src[i * 8];
        const float4 v1 = *(const float4*)&src[i * 8 + 4];
        __half2 h[4];
        h[0] = __floats2half2_rn(v0.x, v0.y);
        h[1] = __floats2half2_rn(v0.z, v0.w);
        h[2] = __floats2half2_rn(v1.x, v1.y);
        h[3] = __floats2half2_rn(v1.z, v1.w);
        *(uint4*)&dst[i * 8] = *(uint4*)h;
    }
}
// transpose + f16: src [Kd][Nd] f32 -> dst [Nd][Kd] f16
__global__ __launch_bounds__(256) void trrh_kernel(__half* dst, const float* src, int Kd, int Nd) {
    __shared__ float t[32][33];
    const int bx = blockIdx.x * 32;   // n
    const int by = blockIdx.y * 32;   // k
    const int tx = threadIdx.x, ty = threadIdx.y;
#pragma unroll
    for (int i = 0; i < 32; i += 8)
        t[ty + i][tx] = src[(size_t)(by + ty + i) * Nd + bx + tx];
    __syncthreads();
#pragma unroll
    for (int i = 0; i < 32; i += 8)
        dst[(size_t)(bx + ty + i) * Kd + by + tx] = __float2half_rn(t[tx][ty + i]);
}

// ---------------------------------------------------------------------------
// fp16 GEMM: 128x128 tile, BK=32, ldmatrix b16 + 3-stage cp.async,
// 1 barrier/iter, 2 CTAs/SM. A [M][2048] f16, Bt [N][2048] f16.
// blockIdx.z selects (Bt,bias,C). OUT*_HALF: C dtype.
// ---------------------------------------------------------------------------
#define GEMM_H_SMEM (2 * (3 * 128 * 40) * 2)

template<bool OUT0_HALF, bool OUT1_HALF, bool HASBIAS>
__global__ __launch_bounds__(256, 2) void gemm_h(
    const __half* __restrict__ A,
    const __half* __restrict__ Bt0, const __half* __restrict__ Bt1,
    const float* __restrict__ bias0, const float* __restrict__ bias1,
    void* __restrict__ C0, void* __restrict__ C1, int N)
{
    constexpr int KD = 2048, BK = 32, ASS = 40;
    constexpr int NIT = KD / BK;

    extern __shared__ __half smem_h[];
    __half* AsH = smem_h;
    __half* BsH = smem_h + 3 * 128 * ASS;

    const int tid = threadIdx.x;
    const int lane = tid & 31, w = tid >> 5;
    const int wm0 = (w & 1) * 64;
    const int wn0 = (w >> 1) * 32;
    const int bm = blockIdx.y * 128;
    const int bn = blockIdx.x * 128;

    const __half* Bt = (blockIdx.z == 0) ? Bt0 : Bt1;
    const float* bia = (blockIdx.z == 0) ? bias0 : bias1;

    const int cr = tid & 127;
    const int co = (tid >> 7) * 16;     // half-offset 0 or 16
    const uint32_t sA = (uint32_t)__cvta_generic_to_shared(AsH);
    const uint32_t sB = (uint32_t)__cvta_generic_to_shared(BsH);

    const int a_row = lane & 15;
    const int a_k8  = (lane >> 4) * 8;
    const int b_row = (lane & 7) + ((lane >> 3) & 1) * 8;
    const int b_k8  = (lane >> 4) * 8;

    float acc[4][4][4];
#pragma unroll
    for (int mi = 0; mi < 4; mi++)
#pragma unroll
        for (int nj = 0; nj < 4; nj++)
#pragma unroll
            for (int c = 0; c < 4; c++) acc[mi][nj][c] = 0.0f;

    auto issue = [&](int st, int k0) {
        const __half* ga = &A[(size_t)(bm + cr) * KD + k0 + co];
        uint32_t sa = sA + (uint32_t)((st * 128 + cr) * ASS + co) * 2u;
        cpa16(sa, ga); cpa16(sa + 16, ga + 8);
        const __half* gb = &Bt[(size_t)(bn + cr) * KD + k0 + co];
        uint32_t sb = sB + (uint32_t)((st * 128 + cr) * ASS + co) * 2u;
        cpa16(sb, gb); cpa16(sb + 16, gb + 8);
    };

    issue(0, 0);       cp_commit();
    issue(1, BK);      cp_commit();

    int st = 0;
    for (int it = 0; it < NIT; it++) {
        if (it + 1 < NIT) cp_wait<1>(); else cp_wait<0>();
        __syncthreads();
        const uint32_t aB = sA + (uint32_t)(st * 128 * ASS) * 2u;
        const uint32_t bB = sB + (uint32_t)(st * 128 * ASS) * 2u;

#pragma unroll
        for (int ks = 0; ks < 2; ks++) {
            const int kk = ks * 16;
            uint32_t af[4][4], bf[4][2];
#pragma unroll
            for (int mi = 0; mi < 4; mi++) {
                uint32_t ad = aB + (uint32_t)(((wm0 + 16 * mi + a_row) * ASS) + kk + a_k8) * 2u;
                ldsm4(af[mi][0], af[mi][1], af[mi][2], af[mi][3], ad);
            }
#pragma unroll
            for (int p = 0; p < 2; p++) {
                uint32_t bd = bB + (uint32_t)(((wn0 + 16 * p + b_row) * ASS) + kk + b_k8) * 2u;
                uint32_t r0, r1, r2, r3;
                ldsm4(r0, r1, r2, r3, bd);
                bf[2 * p][0] = r0; bf[2 * p][1] = r2;
                bf[2 * p + 1][0] = r1; bf[2 * p + 1][1] = r3;
            }
#pragma unroll
            for (int mi = 0; mi < 4; mi++)
#pragma unroll
                for (int nj = 0; nj < 4; nj++)
                    mma_f16(acc[mi][nj], af[mi], bf[nj]);
        }

        if (it + 2 < NIT) {
            issue((st + 2) % 3, (it + 2) * BK);
            cp_commit();
        }
        st = (st + 1) % 3;
    }

    const bool outHalf = (blockIdx.z == 0) ? OUT0_HALF : OUT1_HALF;
    void* C = (blockIdx.z == 0) ? C0 : C1;
#pragma unroll
    for (int mi = 0; mi < 4; mi++) {
#pragma unroll
        for (int nj = 0; nj < 4; nj++) {
            int row = bm + wm0 + 16 * mi + (lane >> 2);
            int col = bn + wn0 + 8 * nj + 2 * (lane & 3);
            float bx = 0.0f, by = 0.0f;
            if (HASBIAS) { bx = bia[col]; by = bia[col + 1]; }
            float v0x = acc[mi][nj][0] + bx, v0y = acc[mi][nj][1] + by;
            float v1x = acc[mi][nj][2] + bx, v1y = acc[mi][nj][3] + by;
            if (outHalf) {
                __half* Ch = (__half*)C;
                *(__half2*)&Ch[(size_t)row * N + col] = __floats2half2_rn(v0x, v0y);
                *(__half2*)&Ch[(size_t)(row + 8) * N + col] = __floats2half2_rn(v1x, v1y);
            } else {
                float* Cf = (float*)C;
                *(float2*)&Cf[(size_t)row * N + col] = make_float2(v0x, v0y);
                *(float2*)&Cf[(size_t)(row + 8) * N + col] = make_float2(v1x, v1y);
            }
        }
    }
}

// ---------------------------------------------------------------------------
// Scores (fp16): E = 2^(QK^T * scale * log2e) causal-masked + row-sum partials.
// ---------------------------------------------------------------------------
#define SCORES_SMEM (2 * (3 * 128 * 40) * 2 + 128 * 4 * 4)

__global__ __launch_bounds__(256, 2) void scores_h() {
    constexpr int ASS = 40, BK = 32;
    const int nb = blockIdx.x, mb = blockIdx.y, h = blockIdx.z;
    if (nb > mb) return;
    const int kvh = h >> 2;

    extern __shared__ __half smem_h[];
    __half* AsH = smem_h;
    __half* BsH = smem_h + 3 * 128 * ASS;
    float* red = (float*)(smem_h + 2 * 3 * 128 * ASS);

    const int tid = threadIdx.x;
    const int lane = tid & 31, w = tid >> 5;
    const int wm0 = (w & 1) * 64;
    const int wn0 = (w >> 1) * 32;

    const int cr = tid & 127;
    const int co = (tid >> 7) * 16;
    const uint32_t sA = (uint32_t)__cvta_generic_to_shared(AsH);
    const uint32_t sB = (uint32_t)__cvta_generic_to_shared(BsH);

    const int a_row = lane & 15;
    const int a_k8  = (lane >> 4) * 8;
    const int b_row = (lane & 7) + ((lane >> 3) & 1) * 8;
    const int b_k8  = (lane >> 4) * 8;

    const __half* Qg = g_q + (size_t)(mb * 128) * DMODEL + h * HDIM;
    const __half* Kg = g_k + (size_t)(nb * 128) * KV_DM + kvh * HDIM;

    float acc[4][4][4];
#pragma unroll
    for (int mi = 0; mi < 4; mi++)
#pragma unroll
        for (int nj = 0; nj < 4; nj++)
#pragma unroll
            for (int c = 0; c < 4; c++) acc[mi][nj][c] = 0.0f;

    auto issue = [&](int st, int k0) {
        const __half* ga = &Qg[(size_t)cr * DMODEL + k0 + co];
        uint32_t sa = sA + (uint32_t)((st * 128 + cr) * ASS + co) * 2u;
        cpa16(sa, ga); cpa16(sa + 16, ga + 8);
        const __half* gb = &Kg[(size_t)cr * KV_DM + k0 + co];
        uint32_t sb = sB + (uint32_t)((st * 128 + cr) * ASS + co) * 2u;
        cpa16(sb, gb); cpa16(sb + 16, gb + 8);
    };

    issue(0, 0);      cp_commit();
    issue(1, BK);     cp_commit();

    constexpr int NIT = HDIM / BK;   // 4
    int st = 0;
    for (int it = 0; it < NIT; it++) {
        if (it + 1 < NIT) cp_wait<1>(); else cp_wait<0>();
        __syncthreads();
        const uint32_t aB = sA + (uint32_t)(st * 128 * ASS) * 2u;
        const uint32_t bB = sB + (uint32_t)(st * 128 * ASS) * 2u;
#pragma unroll
        for (int ks = 0; ks < 2; ks++) {
            const int kk = ks * 16;
            uint32_t af[4][4], bf[4][2];
#pragma unroll
            for (int mi = 0; mi < 4; mi++) {
                uint32_t ad = aB + (uint32_t)(((wm0 + 16 * mi + a_row) * ASS) + kk + a_k8) * 2u;
                ldsm4(af[mi][0], af[mi][1], af[mi][2], af[mi][3], ad);
            }
#pragma unroll
            for (int p = 0; p < 2; p++) {
                uint32_t bd = bB + (uint32_t)(((wn0 + 16 * p + b_row) * ASS) + kk + b_k8) * 2u;
                uint32_t r0, r1, r2, r3;
                ldsm4(r0, r1, r2, r3, bd);
                bf[2 * p][0] = r0; bf[2 * p][1] = r2;
                bf[2 * p + 1][0] = r1; bf[2 * p + 1][1] = r3;
            }
#pragma unroll
            for (int mi = 0; mi < 4; mi++)
#pragma unroll
                for (int nj = 0; nj < 4; nj++)
                    mma_f16(acc[mi][nj], af[mi], bf[nj]);
        }
        if (it + 2 < NIT) {
            issue((st + 2) % 3, (it + 2) * BK);
            cp_commit();
        }
        st = (st + 1) % 3;
    }

    const float SCL2 = 0.08838834764831845f * 1.4426950408889634f;
    float* Eh = g_E + (size_t)h * S_LEN * S_LEN;
    float rs[4][2];
#pragma unroll
    for (int mi = 0; mi < 4; mi++) { rs[mi][0] = 0.f; rs[mi][1] = 0.f; }

#pragma unroll
    for (int mi = 0; mi < 4; mi++) {
#pragma unroll
        for (int nj = 0; nj < 4; nj++) {
            int row = mb * 128 + wm0 + 16 * mi + (lane >> 2);
            int col = nb * 128 + wn0 + 8 * nj + 2 * (lane & 3);
            float e0 = (col     <= row)     ? ex2f(acc[mi][nj][0] * SCL2) : 0.f;
            float e1 = (col + 1 <= row)     ? ex2f(acc[mi][nj][1] * SCL2) : 0.f;
            float e2 = (col     <= row + 8) ? ex2f(acc[mi][nj][2] * SCL2) : 0.f;
            float e3 = (col + 1 <= row + 8) ? ex2f(acc[mi][nj][3] * SCL2) : 0.f;
            *(float2*)&Eh[(size_t)row * S_LEN + col] = make_float2(e0, e1);
            *(float2*)&Eh[(size_t)(row + 8) * S_LEN + col] = make_float2(e2, e3);
            rs[mi][0] += e0 + e1;
            rs[mi][1] += e2 + e3;
        }
    }
#pragma unroll
    for (int mi = 0; mi < 4; mi++)
#pragma unroll
        for (int hh = 0; hh < 2; hh++) {
            rs[mi][hh] += __shfl_xor_sync(0xFFFFFFFFu, rs[mi][hh], 1);
            rs[mi][hh] += __shfl_xor_sync(0xFFFFFFFFu, rs[mi][hh], 2);
        }
    if ((lane & 3) == 0) {
        int wg = w >> 1;
#pragma unroll
        for (int mi = 0; mi < 4; mi++) {
            red[(wm0 + 16 * mi + (lane >> 2)) * 4 + wg]     = rs[mi][0];
            red[(wm0 + 16 * mi + 8 + (lane >> 2)) * 4 + wg] = rs[mi][1];
        }
    }
    __syncthreads();
    if (tid < 128)
        g_lpart[((size_t)h * S_LEN + mb * 128 + tid) * 16 + nb] =
            red[tid * 4] + red[tid * 4 + 1] + red[tid * 4 + 2] + red[tid * 4 + 3];
}

// ---------------------------------------------------------------------------
// Attention over E: p = E*il -> smem f16, colsums + fp16 P@V (ldmatrix.trans V).
// smem: sP half[128][72], Vs half[64][136], red f32[512], il f32[128] = 38400 B.
// ---------------------------------------------------------------------------
#define SPS 72
#define VSS 136
#define ATTN_SMEM (128 * SPS * 2 + 64 * VSS * 2 + 512 * 4 + 128 * 4)

__global__ __launch_bounds__(512, 1) void attn_pv() {
    extern __shared__ __half smh[];
    __half* sP = smh;                          // [128][72]
    __half* Vs = smh + 128 * SPS;              // [64][136]
    float* red = (float*)(smh + 128 * SPS + 64 * VSS);   // [512]
    float* il  = red + 512;                    // [128]

    const int qt = 15 - blockIdx.x;
    const int h  = blockIdx.y;
    const int kvh = h >> 2;
    const int qbase = qt * 128;
    const int tid = threadIdx.x;
    const int lane = tid & 31, w = tid >> 5;
    const int wm  = (w & 3) * 32;
    const int wn2 = (w >> 2) * 32;

    const int a_row = lane & 15;
    const int a_k8  = (lane >> 4) * 8;
    const uint32_t sPT = (uint32_t)__cvta_generic_to_shared(sP);
    const uint32_t sVT = (uint32_t)__cvta_generic_to_shared(Vs);

    const float* Eh = g_E + (size_t)h * S_LEN * S_LEN;

    if (tid < 128) {
        const float* lp = &g_lpart[((size_t)h * S_LEN + qbase + tid) * 16];
        float l = 0.0f;
        for (int nb = 0; nb <= qt; nb++) l += lp[nb];
        il[tid] = 1.0f / l;
    }
    __syncthreads();

    const int prow = tid >> 2;
    const int pcb = (tid & 3) * 16;
    const float myil = il[prow];

    float o[2][4][4];
#pragma unroll
    for (int mi = 0; mi < 2; mi++)
#pragma unroll
        for (int nj = 0; nj < 4; nj++)
#pragma unroll
            for (int c = 0; c < 4; c++) o[mi][nj][c] = 0.0f;

    const int nkt = 2 * qt + 2;
    for (int kt = 0; kt < nkt; kt++) {
        {
            // P tile: E * il -> f16
            const float* ep = &Eh[(size_t)(qbase + prow) * S_LEN + kt * 64 + pcb];
            __half2 hbuf[8];
#pragma unroll
            for (int i = 0; i < 4; i++) {
                float4 v = *(const float4*)&ep[4 * i];
                hbuf[2 * i]     = __floats2half2_rn(v.x * myil, v.y * myil);
                hbuf[2 * i + 1] = __floats2half2_rn(v.z * myil, v.w * myil);
            }
            *(uint4*)&sP[prow * SPS + pcb]     = ((uint4*)hbuf)[0];
            *(uint4*)&sP[prow * SPS + pcb + 8] = ((uint4*)hbuf)[1];

            // V tile: f16 [k][n]
            int vr = tid >> 3, vcb = (tid & 7) * 16;
            const __half* vp = &g_v[(size_t)(kt * 64 + vr) * KV_DM + kvh * HDIM + vcb];
            *(uint4*)&Vs[vr * VSS + vcb]     = *(const uint4*)vp;
            *(uint4*)&Vs[vr * VSS + vcb + 8] = *(const uint4*)(vp + 8);
        }
        __syncthreads();

        // deterministic column sums (from rounded halves; fixed 4-way split)
        if (tid < 256) {
            int c = tid & 63, seg = tid >> 6;
            float cs = 0.0f;
#pragma unroll 8
            for (int q = 0; q < 32; q++) cs += __half2float(sP[(seg * 32 + q) * SPS + c]);
            red[c * 4 + seg] = cs;
        }

        // P@V fp16: 4 k-steps of 16
#pragma unroll
        for (int ks = 0; ks < 4; ks++) {
            const int kk = ks * 16;
            uint32_t af[2][4], bf[4][2];
#pragma unroll
            for (int mi = 0; mi < 2; mi++) {
                uint32_t ad = sPT + (uint32_t)(((wm + 16 * mi + a_row) * SPS) + kk + a_k8) * 2u;
                ldsm4(af[mi][0], af[mi][1], af[mi][2], af[mi][3], ad);
            }
#pragma unroll
            for (int p = 0; p < 2; p++) {
                uint32_t bd = sVT + (uint32_t)(((kk + (lane & 15)) * VSS) + wn2 + p * 16 + (lane >> 4) * 8) * 2u;
                uint32_t r0, r1, r2, r3;
                ldsm4t(r0, r1, r2, r3, bd);
                bf[2 * p][0] = r0; bf[2 * p][1] = r1;
                bf[2 * p + 1][0] = r2; bf[2 * p + 1][1] = r3;
            }
#pragma unroll
            for (int mi = 0; mi < 2; mi++)
#pragma unroll
                for (int nj = 0; nj < 4; nj++)
                    mma_f16(o[mi][nj], af[mi], bf[nj]);
        }
        __syncthreads();
        if (tid < 64)
            g_colpart[((size_t)h * NQT16 + qt) * S_LEN + kt * 64 + tid] =
                red[tid * 4] + red[tid * 4 + 1] + red[tid * 4 + 2] + red[tid * 4 + 3];
    }

#pragma unroll
    for (int mi = 0; mi < 2; mi++)
#pragma unroll
        for (int nj = 0; nj < 4; nj++) {
            int row = qbase + wm + 16 * mi + (lane >> 2);
            int col = h * HDIM + wn2 + 8 * nj + 2 * (lane & 3);
            *(__half2*)&g_ctx[(size_t)row * DMODEL + col] =
                __floats2half2_rn(o[mi][nj][0], o[mi][nj][1]);
            *(__half2*)&g_ctx[(size_t)(row + 8) * DMODEL + col] =
                __floats2half2_rn(o[mi][nj][2], o[mi][nj][3]);
        }
}

// ---------------------------------------------------------------------------
// Heavy-hitter mask via bitonic sort (exact jax.lax.top_k tie semantics).
// ---------------------------------------------------------------------------
__global__ __launch_bounds__(1024) void topk_kernel(float* __restrict__ mask_out) {
    const int h = blockIdx.x;
    const int tid = threadIdx.x;
    __shared__ unsigned long long keys[2048];

    for (int i = tid; i < 2048; i += 1024) {
        unsigned ev = 0u;
        if (i < SEL) {
            float s = 0.0f;
#pragma unroll
            for (int qt = 0; qt < NQT16; qt++)
                s += g_colpart[((size_t)h * NQT16 + qt) * S_LEN + i];
            ev = encf(s);
        }
        keys[i] = ((unsigned long long)ev << 32) | (unsigned)(2047 - i);
    }
    float* mrow = mask_out + (size_t)h * MASKW;
    for (int i = tid; i < MASKW; i += 1024)
        mrow[i] = (i >= (MASKW - RECENT)) ? 1.0f : 0.0f;
    __syncthreads();

    for (int k = 2; k <= 2048; k <<= 1) {
        for (int j = k >> 1; j > 0; j >>= 1) {
            for (int idx = tid; idx < 2048; idx += 1024) {
                int ixj = idx ^ j;
                if (ixj > idx) {
                    unsigned long long a = keys[idx], b = keys[ixj];
                    bool up = (idx & k) == 0;
                    if (up ? (a > b) : (a < b)) { keys[idx] = b; keys[ixj] = a; }
                }
            }
            __syncthreads();
        }
    }
    for (int i = 2048 - HEAVY + tid; i < 2048; i += 1024) {
        int idx = 2047 - (int)(keys[i] & 0xFFFFFFFFu);
        mrow[idx] = 1.0f;
    }
}

// ---------------------------------------------------------------------------
extern "C" void kernel_launch(void* const* d_in, const int* in_sizes, int n_in,
                              void* d_out, int out_size) {
    (void)in_sizes; (void)n_in; (void)out_size;
    const float* hidden = (const float*)d_in[0];
    const float* q_w = (const float*)d_in[1];
    const float* q_b = (const float*)d_in[2];
    const float* k_w = (const float*)d_in[3];
    const float* k_b = (const float*)d_in[4];
    const float* v_w = (const float*)d_in[5];
    const float* v_b = (const float*)d_in[6];
    const float* o_w = (const float*)d_in[7];
    float* out = (float*)d_out;

    static bool init = false;
    static cudaStream_t sA, sB, sC;
    static cudaEvent_t evRoot, evHid, evKV, evZero, evAttn, evTrrO, evTrrQ, evDoneA, evDoneC;
    if (!init) {
        cudaFuncSetAttribute(attn_pv, cudaFuncAttributeMaxDynamicSharedMemorySize, ATTN_SMEM);
        cudaFuncSetAttribute(gemm_h<true, false, true>,
                             cudaFuncAttributeMaxDynamicSharedMemorySize, GEMM_H_SMEM);
        cudaFuncSetAttribute(gemm_h<true, true, true>,
                             cudaFuncAttributeMaxDynamicSharedMemorySize, GEMM_H_SMEM);
        cudaFuncSetAttribute(gemm_h<false, false, false>,
                             cudaFuncAttributeMaxDynamicSharedMemorySize, GEMM_H_SMEM);
        cudaFuncSetAttribute(scores_h,
                             cudaFuncAttributeMaxDynamicSharedMemorySize, SCORES_SMEM);
        cudaStreamCreateWithFlags(&sA, cudaStreamNonBlocking);
        cudaStreamCreateWithFlags(&sB, cudaStreamNonBlocking);
        cudaStreamCreateWithFlags(&sC, cudaStreamNonBlocking);
        cudaEventCreateWithFlags(&evRoot, cudaEventDisableTiming);
        cudaEventCreateWithFlags(&evHid,  cudaEventDisableTiming);
        cudaEventCreateWithFlags(&evKV,   cudaEventDisableTiming);
        cudaEventCreateWithFlags(&evZero, cudaEventDisableTiming);
        cudaEventCreateWithFlags(&evAttn, cudaEventDisableTiming);
        cudaEventCreateWithFlags(&evTrrO, cudaEventDisableTiming);
        cudaEventCreateWithFlags(&evTrrQ, cudaEventDisableTiming);
        cudaEventCreateWithFlags(&evDoneA, cudaEventDisableTiming);
        cudaEventCreateWithFlags(&evDoneC, cudaEventDisableTiming);
        init = true;
    }

    __half *ghid, *gqwT, *gkwT, *gvwT, *gowT, *gq, *gk, *gv, *gctx;
    float *gcp;
    cudaGetSymbolAddress((void**)&ghid, g_hid);
    cudaGetSymbolAddress((void**)&gqwT, g_qwT);
    cudaGetSymbolAddress((void**)&gkwT, g_kwT);
    cudaGetSymbolAddress((void**)&gvwT, g_vwT);
    cudaGetSymbolAddress((void**)&gowT, g_owT);
    cudaGetSymbolAddress((void**)&gq,   g_q);
    cudaGetSymbolAddress((void**)&gk,   g_k);
    cudaGetSymbolAddress((void**)&gv,   g_v);
    cudaGetSymbolAddress((void**)&gctx, g_ctx);
    cudaGetSymbolAddress((void**)&gcp,  g_colpart);

    // fork from the capture (legacy) stream
    cudaEventRecord(evRoot, 0);
    cudaStreamWaitEvent(sA, evRoot, 0);
    cudaStreamWaitEvent(sB, evRoot, 0);
    cudaStreamWaitEvent(sC, evRoot, 0);

    dim3 tb(32, 8);
    // sA: hid f16; sC: trr_q (concurrent)
    f2h_kernel<<<(S_LEN * DMODEL / 8 + 255) / 256, 256, 0, sA>>>(
        ghid, hidden, S_LEN * DMODEL / 8);
    cudaEventRecord(evHid, sA);
    trrh_kernel<<<dim3(DMODEL / 32, DMODEL / 32), tb, 0, sC>>>(gqwT, q_w, DMODEL, DMODEL);
    cudaEventRecord(evTrrQ, sC);
    // sB: trr_k, trr_v
    trrh_kernel<<<dim3(KV_DM / 32, DMODEL / 32), tb, 0, sB>>>(gkwT, k_w, DMODEL, KV_DM);
    trrh_kernel<<<dim3(KV_DM / 32, DMODEL / 32), tb, 0, sB>>>(gvwT, v_w, DMODEL, KV_DM);
    // sC: trr_o, zero
    trrh_kernel<<<dim3(DMODEL / 32, DMODEL / 32), tb, 0, sC>>>(gowT, o_w, DMODEL, DMODEL);
    cudaEventRecord(evTrrO, sC);

    // Q projection (fp16, out half)
    cudaStreamWaitEvent(sA, evTrrQ, 0);
    gemm_h<true, false, true><<<dim3(DMODEL / 128, S_LEN / 128, 1), 256, GEMM_H_SMEM, sA>>>(
        ghid, gqwT, nullptr, q_b, nullptr, gq, nullptr, DMODEL);

    // KV projections (z-fused: K half, V half), concurrent with Q
    cudaStreamWaitEvent(sB, evHid, 0);
    gemm_h<true, true, true><<<dim3(KV_DM / 128, S_LEN / 128, 2), 256, GEMM_H_SMEM, sB>>>(
        ghid, gkwT, gvwT, k_b, v_b, gk, gv, KV_DM);
    cudaEventRecord(evKV, sB);

    const int ncp = NH * NQT16 * S_LEN;
    zero_kernel<<<(ncp + 255) / 256, 256, 0, sC>>>(gcp, ncp);
    cudaEventRecord(evZero, sC);

    cudaStreamWaitEvent(sA, evKV, 0);
    scores_h<<<dim3(16, 16, NH), 256, SCORES_SMEM, sA>>>();

    cudaStreamWaitEvent(sA, evZero, 0);
    attn_pv<<<dim3(16, NH), 512, ATTN_SMEM, sA>>>();
    cudaEventRecord(evAttn, sA);

    // sC: topk (after attn), overlaps with gemmO on sA
    cudaStreamWaitEvent(sC, evAttn, 0);
    topk_kernel<<<NH, 1024, 0, sC>>>(out + (size_t)S_LEN * DMODEL);
    cudaEventRecord(evDoneC, sC);

    // output projection (fp16 in, f32 out, no bias)
    cudaStreamWaitEvent(sA, evTrrO, 0);
    gemm_h<false, false, false><<<dim3(DMODEL / 128, S_LEN / 128, 1), 256, GEMM_H_SMEM, sA>>>(
        gctx, gowT, nullptr, nullptr, nullptr, out, nullptr, DMODEL);
    cudaEventRecord(evDoneA, sA);

    // join back to the capture stream
    cudaStreamWaitEvent(0, evDoneA, 0);
    cudaStreamWaitEvent(0, evDoneC, 0);
}

// round 12
// speedup vs baseline: 1.8359x; 1.0589x over previous
#include <cuda_runtime.h>
#include <cuda_fp16.h>
#include <cstdint>

#define S_LEN   2048
#define DMODEL  2048
#define NH      16
#define HDIM    128
#define KV_DM   512
#define NQT16   16
#define HEAVY   204
#define RECENT  204
#define SEL     (S_LEN - RECENT)    // 1844
#define MASKW   (S_LEN + 1)         // 2049

__device__ __half g_hid[S_LEN * DMODEL];
__device__ __half g_qwT[DMODEL * DMODEL];   // [n][k]
__device__ __half g_kwT[KV_DM * DMODEL];
__device__ __half g_vwT[KV_DM * DMODEL];
__device__ __half g_owT[DMODEL * DMODEL];
__device__ __half g_q[S_LEN * DMODEL];
__device__ __half g_k[S_LEN * KV_DM];
__device__ __half g_v[S_LEN * KV_DM];
__device__ __half g_ctx[S_LEN * DMODEL];
__device__ float  g_colpart[NH * NQT16 * S_LEN];
__device__ float  g_lpart[NH * S_LEN * 16];
__device__ __half g_E[(size_t)NH * S_LEN * S_LEN];   // exp'd scores, fp16 (128 MB)

// ---------------------------------------------------------------------------
__device__ __forceinline__ float ex2f(float x) {
    float y;
    asm("ex2.approx.ftz.f32 %0, %1;" : "=f"(y) : "f"(x));
    return y;
}
__device__ __forceinline__ void mma_f16(float* c, const uint32_t* a, const uint32_t* b) {
    asm volatile(
        "mma.sync.aligned.m16n8k16.row.col.f32.f16.f16.f32 "
        "{%0,%1,%2,%3}, {%4,%5,%6,%7}, {%8,%9}, {%0,%1,%2,%3};"
        : "+f"(c[0]), "+f"(c[1]), "+f"(c[2]), "+f"(c[3])
        : "r"(a[0]), "r"(a[1]), "r"(a[2]), "r"(a[3]), "r"(b[0]), "r"(b[1]));
}
__device__ __forceinline__ void ldsm4(uint32_t& r0, uint32_t& r1, uint32_t& r2, uint32_t& r3,
                                      uint32_t addr) {
    asm volatile("ldmatrix.sync.aligned.m8n8.x4.shared.b16 {%0,%1,%2,%3}, [%4];"
                 : "=r"(r0), "=r"(r1), "=r"(r2), "=r"(r3) : "r"(addr));
}
__device__ __forceinline__ void ldsm4t(uint32_t& r0, uint32_t& r1, uint32_t& r2, uint32_t& r3,
                                       uint32_t addr) {
    asm volatile("ldmatrix.sync.aligned.m8n8.x4.trans.shared.b16 {%0,%1,%2,%3}, [%4];"
                 : "=r"(r0), "=r"(r1), "=r"(r2), "=r"(r3) : "r"(addr));
}
__device__ __forceinline__ void cpa16(uint32_t s, const void* g) {
    asm volatile("cp.async.cg.shared.global [%0], [%1], 16;" :: "r"(s), "l"(g));
}
__device__ __forceinline__ void cp_commit() { asm volatile("cp.async.commit_group;"); }
template<int N> __device__ __forceinline__ void cp_wait() {
    asm volatile("cp.async.wait_group %0;" :: "n"(N));
}
__device__ __forceinline__ unsigned encf(float x) {
    unsigned b = __float_as_uint(x);
    return (b & 0x80000000u) ? ~b : (b | 0x80000000u);
}

__global__ void zero_kernel(float* p, int n) {
    int i = blockIdx.x * 256 + threadIdx.x;
    if (i < n) p[i] = 0.0f;
}
// f32 -> f16, 8 elems/thread
__global__ void f2h_kernel(__half* dst, const float* src, int n8) {
    int i = blockIdx.x * 256 + threadIdx.x;
    if (i < n8) {
        const float4 v0 = *(const float4*)&src[i * 8];
        const float4 v1 = *(const float4*)&src[i * 8 + 4];
        __half2 h[4];
        h[0] = __floats2half2_rn(v0.x, v0.y);
        h[1] = __floats2half2_rn(v0.z, v0.w);
        h[2] = __floats2half2_rn(v1.x, v1.y);
        h[3] = __floats2half2_rn(v1.z, v1.w);
        *(uint4*)&dst[i * 8] = *(uint4*)h;
    }
}
// transpose + f16: src [Kd][Nd] f32 -> dst [Nd][Kd] f16
__global__ __launch_bounds__(256) void trrh_kernel(__half* dst, const float* src, int Kd, int Nd) {
    __shared__ float t[32][33];
    const int bx = blockIdx.x * 32;   // n
    const int by = blockIdx.y * 32;   // k
    const int tx = threadIdx.x, ty = threadIdx.y;
#pragma unroll
    for (int i = 0; i < 32; i += 8)
        t[ty + i][tx] = src[(size_t)(by + ty + i) * Nd + bx + tx];
    __syncthreads();
#pragma unroll
    for (int i = 0; i < 32; i += 8)
        dst[(size_t)(bx + ty + i) * Kd + by + tx] = __float2half_rn(t[tx][ty + i]);
}

// ---------------------------------------------------------------------------
// fp16 GEMM: 128x128 tile, BK=32, ldmatrix b16 + 3-stage cp.async,
// 1 barrier/iter, 2 CTAs/SM. A [M][2048] f16, Bt [N][2048] f16.
// ---------------------------------------------------------------------------
#define GEMM_H_SMEM (2 * (3 * 128 * 40) * 2)

template<bool OUT0_HALF, bool OUT1_HALF, bool HASBIAS>
__global__ __launch_bounds__(256, 2) void gemm_h(
    const __half* __restrict__ A,
    const __half* __restrict__ Bt0, const __half* __restrict__ Bt1,
    const float* __restrict__ bias0, const float* __restrict__ bias1,
    void* __restrict__ C0, void* __restrict__ C1, int N)
{
    constexpr int KD = 2048, BK = 32, ASS = 40;
    constexpr int NIT = KD / BK;

    extern __shared__ __half smem_h[];
    __half* AsH = smem_h;
    __half* BsH = smem_h + 3 * 128 * ASS;

    const int tid = threadIdx.x;
    const int lane = tid & 31, w = tid >> 5;
    const int wm0 = (w & 1) * 64;
    const int wn0 = (w >> 1) * 32;
    const int bm = blockIdx.y * 128;
    const int bn = blockIdx.x * 128;

    const __half* Bt = (blockIdx.z == 0) ? Bt0 : Bt1;
    const float* bia = (blockIdx.z == 0) ? bias0 : bias1;

    const int cr = tid & 127;
    const int co = (tid >> 7) * 16;
    const uint32_t sA = (uint32_t)__cvta_generic_to_shared(AsH);
    const uint32_t sB = (uint32_t)__cvta_generic_to_shared(BsH);

    const int a_row = lane & 15;
    const int a_k8  = (lane >> 4) * 8;
    const int b_row = (lane & 7) + ((lane >> 3) & 1) * 8;
    const int b_k8  = (lane >> 4) * 8;

    float acc[4][4][4];
#pragma unroll
    for (int mi = 0; mi < 4; mi++)
#pragma unroll
        for (int nj = 0; nj < 4; nj++)
#pragma unroll
            for (int c = 0; c < 4; c++) acc[mi][nj][c] = 0.0f;

    auto issue = [&](int st, int k0) {
        const __half* ga = &A[(size_t)(bm + cr) * KD + k0 + co];
        uint32_t sa = sA + (uint32_t)((st * 128 + cr) * ASS + co) * 2u;
        cpa16(sa, ga); cpa16(sa + 16, ga + 8);
        const __half* gb = &Bt[(size_t)(bn + cr) * KD + k0 + co];
        uint32_t sb = sB + (uint32_t)((st * 128 + cr) * ASS + co) * 2u;
        cpa16(sb, gb); cpa16(sb + 16, gb + 8);
    };

    issue(0, 0);       cp_commit();
    issue(1, BK);      cp_commit();

    int st = 0;
    for (int it = 0; it < NIT; it++) {
        if (it + 1 < NIT) cp_wait<1>(); else cp_wait<0>();
        __syncthreads();
        const uint32_t aB = sA + (uint32_t)(st * 128 * ASS) * 2u;
        const uint32_t bB = sB + (uint32_t)(st * 128 * ASS) * 2u;

#pragma unroll
        for (int ks = 0; ks < 2; ks++) {
            const int kk = ks * 16;
            uint32_t af[4][4], bf[4][2];
#pragma unroll
            for (int mi = 0; mi < 4; mi++) {
                uint32_t ad = aB + (uint32_t)(((wm0 + 16 * mi + a_row) * ASS) + kk + a_k8) * 2u;
                ldsm4(af[mi][0], af[mi][1], af[mi][2], af[mi][3], ad);
            }
#pragma unroll
            for (int p = 0; p < 2; p++) {
                uint32_t bd = bB + (uint32_t)(((wn0 + 16 * p + b_row) * ASS) + kk + b_k8) * 2u;
                uint32_t r0, r1, r2, r3;
                ldsm4(r0, r1, r2, r3, bd);
                bf[2 * p][0] = r0; bf[2 * p][1] = r2;
                bf[2 * p + 1][0] = r1; bf[2 * p + 1][1] = r3;
            }
#pragma unroll
            for (int mi = 0; mi < 4; mi++)
#pragma unroll
                for (int nj = 0; nj < 4; nj++)
                    mma_f16(acc[mi][nj], af[mi], bf[nj]);
        }

        if (it + 2 < NIT) {
            issue((st + 2) % 3, (it + 2) * BK);
            cp_commit();
        }
        st = (st + 1) % 3;
    }

    const bool outHalf = (blockIdx.z == 0) ? OUT0_HALF : OUT1_HALF;
    void* C = (blockIdx.z == 0) ? C0 : C1;
#pragma unroll
    for (int mi = 0; mi < 4; mi++) {
#pragma unroll
        for (int nj = 0; nj < 4; nj++) {
            int row = bm + wm0 + 16 * mi + (lane >> 2);
            int col = bn + wn0 + 8 * nj + 2 * (lane & 3);
            float bx = 0.0f, by = 0.0f;
            if (HASBIAS) { bx = bia[col]; by = bia[col + 1]; }
            float v0x = acc[mi][nj][0] + bx, v0y = acc[mi][nj][1] + by;
            float v1x = acc[mi][nj][2] + bx, v1y = acc[mi][nj][3] + by;
            if (outHalf) {
                __half* Ch = (__half*)C;
                *(__half2*)&Ch[(size_t)row * N + col] = __floats2half2_rn(v0x, v0y);
                *(__half2*)&Ch[(size_t)(row + 8) * N + col] = __floats2half2_rn(v1x, v1y);
            } else {
                float* Cf = (float*)C;
                *(float2*)&Cf[(size_t)row * N + col] = make_float2(v0x, v0y);
                *(float2*)&Cf[(size_t)(row + 8) * N + col] = make_float2(v1x, v1y);
            }
        }
    }
}

// ---------------------------------------------------------------------------
// Scores (fp16): E = 2^(QK^T * scale * log2e) causal-masked, stored fp16;
// row-sum partials accumulated from the ROUNDED values (l consistent with E).
// ---------------------------------------------------------------------------
#define SCORES_SMEM (2 * (3 * 128 * 40) * 2 + 128 * 4 * 4)

__global__ __launch_bounds__(256, 2) void scores_h() {
    constexpr int ASS = 40, BK = 32;
    const int nb = blockIdx.x, mb = blockIdx.y, h = blockIdx.z;
    if (nb > mb) return;
    const int kvh = h >> 2;

    extern __shared__ __half smem_h[];
    __half* AsH = smem_h;
    __half* BsH = smem_h + 3 * 128 * ASS;
    float* red = (float*)(smem_h + 2 * 3 * 128 * ASS);

    const int tid = threadIdx.x;
    const int lane = tid & 31, w = tid >> 5;
    const int wm0 = (w & 1) * 64;
    const int wn0 = (w >> 1) * 32;

    const int cr = tid & 127;
    const int co = (tid >> 7) * 16;
    const uint32_t sA = (uint32_t)__cvta_generic_to_shared(AsH);
    const uint32_t sB = (uint32_t)__cvta_generic_to_shared(BsH);

    const int a_row = lane & 15;
    const int a_k8  = (lane >> 4) * 8;
    const int b_row = (lane & 7) + ((lane >> 3) & 1) * 8;
    const int b_k8  = (lane >> 4) * 8;

    const __half* Qg = g_q + (size_t)(mb * 128) * DMODEL + h * HDIM;
    const __half* Kg = g_k + (size_t)(nb * 128) * KV_DM + kvh * HDIM;

    float acc[4][4][4];
#pragma unroll
    for (int mi = 0; mi < 4; mi++)
#pragma unroll
        for (int nj = 0; nj < 4; nj++)
#pragma unroll
            for (int c = 0; c < 4; c++) acc[mi][nj][c] = 0.0f;

    auto issue = [&](int st, int k0) {
        const __half* ga = &Qg[(size_t)cr * DMODEL + k0 + co];
        uint32_t sa = sA + (uint32_t)((st * 128 + cr) * ASS + co) * 2u;
        cpa16(sa, ga); cpa16(sa + 16, ga + 8);
        const __half* gb = &Kg[(size_t)cr * KV_DM + k0 + co];
        uint32_t sb = sB + (uint32_t)((st * 128 + cr) * ASS + co) * 2u;
        cpa16(sb, gb); cpa16(sb + 16, gb + 8);
    };

    issue(0, 0);      cp_commit();
    issue(1, BK);     cp_commit();

    constexpr int NIT = HDIM / BK;   // 4
    int st = 0;
    for (int it = 0; it < NIT; it++) {
        if (it + 1 < NIT) cp_wait<1>(); else cp_wait<0>();
        __syncthreads();
        const uint32_t aB = sA + (uint32_t)(st * 128 * ASS) * 2u;
        const uint32_t bB = sB + (uint32_t)(st * 128 * ASS) * 2u;
#pragma unroll
        for (int ks = 0; ks < 2; ks++) {
            const int kk = ks * 16;
            uint32_t af[4][4], bf[4][2];
#pragma unroll
            for (int mi = 0; mi < 4; mi++) {
                uint32_t ad = aB + (uint32_t)(((wm0 + 16 * mi + a_row) * ASS) + kk + a_k8) * 2u;
                ldsm4(af[mi][0], af[mi][1], af[mi][2], af[mi][3], ad);
            }
#pragma unroll
            for (int p = 0; p < 2; p++) {
                uint32_t bd = bB + (uint32_t)(((wn0 + 16 * p + b_row) * ASS) + kk + b_k8) * 2u;
                uint32_t r0, r1, r2, r3;
                ldsm4(r0, r1, r2, r3, bd);
                bf[2 * p][0] = r0; bf[2 * p][1] = r2;
                bf[2 * p + 1][0] = r1; bf[2 * p + 1][1] = r3;
            }
#pragma unroll
            for (int mi = 0; mi < 4; mi++)
#pragma unroll
                for (int nj = 0; nj < 4; nj++)
                    mma_f16(acc[mi][nj], af[mi], bf[nj]);
        }
        if (it + 2 < NIT) {
            issue((st + 2) % 3, (it + 2) * BK);
            cp_commit();
        }
        st = (st + 1) % 3;
    }

    const float SCL2 = 0.08838834764831845f * 1.4426950408889634f;
    __half* Eh = g_E + (size_t)h * S_LEN * S_LEN;
    float rs[4][2];
#pragma unroll
    for (int mi = 0; mi < 4; mi++) { rs[mi][0] = 0.f; rs[mi][1] = 0.f; }

#pragma unroll
    for (int mi = 0; mi < 4; mi++) {
#pragma unroll
        for (int nj = 0; nj < 4; nj++) {
            int row = mb * 128 + wm0 + 16 * mi + (lane >> 2);
            int col = nb * 128 + wn0 + 8 * nj + 2 * (lane & 3);
            float e0 = (col     <= row)     ? ex2f(acc[mi][nj][0] * SCL2) : 0.f;
            float e1 = (col + 1 <= row)     ? ex2f(acc[mi][nj][1] * SCL2) : 0.f;
            float e2 = (col     <= row + 8) ? ex2f(acc[mi][nj][2] * SCL2) : 0.f;
            float e3 = (col + 1 <= row + 8) ? ex2f(acc[mi][nj][3] * SCL2) : 0.f;
            __half2 h01 = __floats2half2_rn(e0, e1);
            __half2 h23 = __floats2half2_rn(e2, e3);
            *(__half2*)&Eh[(size_t)row * S_LEN + col] = h01;
            *(__half2*)&Eh[(size_t)(row + 8) * S_LEN + col] = h23;
            // accumulate l from the rounded values (consistent with attn reads)
            float2 f01 = __half22float2(h01);
            float2 f23 = __half22float2(h23);
            rs[mi][0] += f01.x + f01.y;
            rs[mi][1] += f23.x + f23.y;
        }
    }
#pragma unroll
    for (int mi = 0; mi < 4; mi++)
#pragma unroll
        for (int hh = 0; hh < 2; hh++) {
            rs[mi][hh] += __shfl_xor_sync(0xFFFFFFFFu, rs[mi][hh], 1);
            rs[mi][hh] += __shfl_xor_sync(0xFFFFFFFFu, rs[mi][hh], 2);
        }
    if ((lane & 3) == 0) {
        int wg = w >> 1;
#pragma unroll
        for (int mi = 0; mi < 4; mi++) {
            red[(wm0 + 16 * mi + (lane >> 2)) * 4 + wg]     = rs[mi][0];
            red[(wm0 + 16 * mi + 8 + (lane >> 2)) * 4 + wg] = rs[mi][1];
        }
    }
    __syncthreads();
    if (tid < 128)
        g_lpart[((size_t)h * S_LEN + mb * 128 + tid) * 16 + nb] =
            red[tid * 4] + red[tid * 4 + 1] + red[tid * 4 + 2] + red[tid * 4 + 3];
}

// ---------------------------------------------------------------------------
// Attention over E (fp16): p = E*il -> smem f16, colsums + fp16 P@V.
// ---------------------------------------------------------------------------
#define SPS 72
#define VSS 136
#define ATTN_SMEM (128 * SPS * 2 + 64 * VSS * 2 + 512 * 4 + 128 * 4)

__global__ __launch_bounds__(512, 1) void attn_pv() {
    extern __shared__ __half smh[];
    __half* sP = smh;                          // [128][72]
    __half* Vs = smh + 128 * SPS;              // [64][136]
    float* red = (float*)(smh + 128 * SPS + 64 * VSS);   // [512]
    float* il  = red + 512;                    // [128]

    const int qt = 15 - blockIdx.x;
    const int h  = blockIdx.y;
    const int kvh = h >> 2;
    const int qbase = qt * 128;
    const int tid = threadIdx.x;
    const int lane = tid & 31, w = tid >> 5;
    const int wm  = (w & 3) * 32;
    const int wn2 = (w >> 2) * 32;

    const int a_row = lane & 15;
    const int a_k8  = (lane >> 4) * 8;
    const uint32_t sPT = (uint32_t)__cvta_generic_to_shared(sP);
    const uint32_t sVT = (uint32_t)__cvta_generic_to_shared(Vs);

    const __half* Eh = g_E + (size_t)h * S_LEN * S_LEN;

    if (tid < 128) {
        const float* lp = &g_lpart[((size_t)h * S_LEN + qbase + tid) * 16];
        float l = 0.0f;
        for (int nb = 0; nb <= qt; nb++) l += lp[nb];
        il[tid] = 1.0f / l;
    }
    __syncthreads();

    const int prow = tid >> 2;
    const int pcb = (tid & 3) * 16;
    const float myil = il[prow];

    float o[2][4][4];
#pragma unroll
    for (int mi = 0; mi < 2; mi++)
#pragma unroll
        for (int nj = 0; nj < 4; nj++)
#pragma unroll
            for (int c = 0; c < 4; c++) o[mi][nj][c] = 0.0f;

    const int nkt = 2 * qt + 2;
    for (int kt = 0; kt < nkt; kt++) {
        {
            // P tile: E(h16) -> f32 * il -> f16
            const __half* ep = &Eh[(size_t)(qbase + prow) * S_LEN + kt * 64 + pcb];
            uint4 u0 = *(const uint4*)ep;        // 8 halves
            uint4 u1 = *(const uint4*)(ep + 8);  // 8 halves
            const __half2* e01 = (const __half2*)&u0;
            const __half2* e23 = (const __half2*)&u1;
            __half2 hbuf[8];
#pragma unroll
            for (int i = 0; i < 4; i++) {
                float2 f = __half22float2(e01[i]);
                hbuf[i] = __floats2half2_rn(f.x * myil, f.y * myil);
            }
#pragma unroll
            for (int i = 0; i < 4; i++) {
                float2 f = __half22float2(e23[i]);
                hbuf[4 + i] = __floats2half2_rn(f.x * myil, f.y * myil);
            }
            *(uint4*)&sP[prow * SPS + pcb]     = ((uint4*)hbuf)[0];
            *(uint4*)&sP[prow * SPS + pcb + 8] = ((uint4*)hbuf)[1];

            // V tile: f16 [k][n]
            int vr = tid >> 3, vcb = (tid & 7) * 16;
            const __half* vp = &g_v[(size_t)(kt * 64 + vr) * KV_DM + kvh * HDIM + vcb];
            *(uint4*)&Vs[vr * VSS + vcb]     = *(const uint4*)vp;
            *(uint4*)&Vs[vr * VSS + vcb + 8] = *(const uint4*)(vp + 8);
        }
        __syncthreads();

        // deterministic column sums (fixed 4-way split)
        if (tid < 256) {
            int c = tid & 63, seg = tid >> 6;
            float cs = 0.0f;
#pragma unroll 8
            for (int q = 0; q < 32; q++) cs += __half2float(sP[(seg * 32 + q) * SPS + c]);
            red[c * 4 + seg] = cs;
        }

        // P@V fp16: 4 k-steps of 16
#pragma unroll
        for (int ks = 0; ks < 4; ks++) {
            const int kk = ks * 16;
            uint32_t af[2][4], bf[4][2];
#pragma unroll
            for (int mi = 0; mi < 2; mi++) {
                uint32_t ad = sPT + (uint32_t)(((wm + 16 * mi + a_row) * SPS) + kk + a_k8) * 2u;
                ldsm4(af[mi][0], af[mi][1], af[mi][2], af[mi][3], ad);
            }
#pragma unroll
            for (int p = 0; p < 2; p++) {
                uint32_t bd = sVT + (uint32_t)(((kk + (lane & 15)) * VSS) + wn2 + p * 16 + (lane >> 4) * 8) * 2u;
                uint32_t r0, r1, r2, r3;
                ldsm4t(r0, r1, r2, r3, bd);
                bf[2 * p][0] = r0; bf[2 * p][1] = r1;
                bf[2 * p + 1][0] = r2; bf[2 * p + 1][1] = r3;
            }
#pragma unroll
            for (int mi = 0; mi < 2; mi++)
#pragma unroll
                for (int nj = 0; nj < 4; nj++)
                    mma_f16(o[mi][nj], af[mi], bf[nj]);
        }
        __syncthreads();
        if (tid < 64)
            g_colpart[((size_t)h * NQT16 + qt) * S_LEN + kt * 64 + tid] =
                red[tid * 4] + red[tid * 4 + 1] + red[tid * 4 + 2] + red[tid * 4 + 3];
    }

#pragma unroll
    for (int mi = 0; mi < 2; mi++)
#pragma unroll
        for (int nj = 0; nj < 4; nj++) {
            int row = qbase + wm + 16 * mi + (lane >> 2);
            int col = h * HDIM + wn2 + 8 * nj + 2 * (lane & 3);
            *(__half2*)&g_ctx[(size_t)row * DMODEL + col] =
                __floats2half2_rn(o[mi][nj][0], o[mi][nj][1]);
            *(__half2*)&g_ctx[(size_t)(row + 8) * DMODEL + col] =
                __floats2half2_rn(o[mi][nj][2], o[mi][nj][3]);
        }
}

// ---------------------------------------------------------------------------
// Heavy-hitter mask via bitonic sort (exact jax.lax.top_k tie semantics).
// ---------------------------------------------------------------------------
__global__ __launch_bounds__(1024) void topk_kernel(float* __restrict__ mask_out) {
    const int h = blockIdx.x;
    const int tid = threadIdx.x;
    __shared__ unsigned long long keys[2048];

    for (int i = tid; i < 2048; i += 1024) {
        unsigned ev = 0u;
        if (i < SEL) {
            float s = 0.0f;
#pragma unroll
            for (int qt = 0; qt < NQT16; qt++)
                s += g_colpart[((size_t)h * NQT16 + qt) * S_LEN + i];
            ev = encf(s);
        }
        keys[i] = ((unsigned long long)ev << 32) | (unsigned)(2047 - i);
    }
    float* mrow = mask_out + (size_t)h * MASKW;
    for (int i = tid; i < MASKW; i += 1024)
        mrow[i] = (i >= (MASKW - RECENT)) ? 1.0f : 0.0f;
    __syncthreads();

    for (int k = 2; k <= 2048; k <<= 1) {
        for (int j = k >> 1; j > 0; j >>= 1) {
            for (int idx = tid; idx < 2048; idx += 1024) {
                int ixj = idx ^ j;
                if (ixj > idx) {
                    unsigned long long a = keys[idx], b = keys[ixj];
                    bool up = (idx & k) == 0;
                    if (up ? (a > b) : (a < b)) { keys[idx] = b; keys[ixj] = a; }
                }
            }
            __syncthreads();
        }
    }
    for (int i = 2048 - HEAVY + tid; i < 2048; i += 1024) {
        int idx = 2047 - (int)(keys[i] & 0xFFFFFFFFu);
        mrow[idx] = 1.0f;
    }
}

// ---------------------------------------------------------------------------
extern "C" void kernel_launch(void* const* d_in, const int* in_sizes, int n_in,
                              void* d_out, int out_size) {
    (void)in_sizes; (void)n_in; (void)out_size;
    const float* hidden = (const float*)d_in[0];
    const float* q_w = (const float*)d_in[1];
    const float* q_b = (const float*)d_in[2];
    const float* k_w = (const float*)d_in[3];
    const float* k_b = (const float*)d_in[4];
    const float* v_w = (const float*)d_in[5];
    const float* v_b = (const float*)d_in[6];
    const float* o_w = (const float*)d_in[7];
    float* out = (float*)d_out;

    static bool init = false;
    static cudaStream_t sA, sB, sC;
    static cudaEvent_t evRoot, evHid, evKV, evZero, evAttn, evTrrO, evTrrQ, evDoneA, evDoneC;
    if (!init) {
        cudaFuncSetAttribute(attn_pv, cudaFuncAttributeMaxDynamicSharedMemorySize, ATTN_SMEM);
        cudaFuncSetAttribute(gemm_h<true, false, true>,
                             cudaFuncAttributeMaxDynamicSharedMemorySize, GEMM_H_SMEM);
        cudaFuncSetAttribute(gemm_h<true, true, true>,
                             cudaFuncAttributeMaxDynamicSharedMemorySize, GEMM_H_SMEM);
        cudaFuncSetAttribute(gemm_h<false, false, false>,
                             cudaFuncAttributeMaxDynamicSharedMemorySize, GEMM_H_SMEM);
        cudaFuncSetAttribute(scores_h,
                             cudaFuncAttributeMaxDynamicSharedMemorySize, SCORES_SMEM);
        cudaStreamCreateWithFlags(&sA, cudaStreamNonBlocking);
        cudaStreamCreateWithFlags(&sB, cudaStreamNonBlocking);
        cudaStreamCreateWithFlags(&sC, cudaStreamNonBlocking);
        cudaEventCreateWithFlags(&evRoot, cudaEventDisableTiming);
        cudaEventCreateWithFlags(&evHid,  cudaEventDisableTiming);
        cudaEventCreateWithFlags(&evKV,   cudaEventDisableTiming);
        cudaEventCreateWithFlags(&evZero, cudaEventDisableTiming);
        cudaEventCreateWithFlags(&evAttn, cudaEventDisableTiming);
        cudaEventCreateWithFlags(&evTrrO, cudaEventDisableTiming);
        cudaEventCreateWithFlags(&evTrrQ, cudaEventDisableTiming);
        cudaEventCreateWithFlags(&evDoneA, cudaEventDisableTiming);
        cudaEventCreateWithFlags(&evDoneC, cudaEventDisableTiming);
        init = true;
    }

    __half *ghid, *gqwT, *gkwT, *gvwT, *gowT, *gq, *gk, *gv, *gctx;
    float *gcp;
    cudaGetSymbolAddress((void**)&ghid, g_hid);
    cudaGetSymbolAddress((void**)&gqwT, g_qwT);
    cudaGetSymbolAddress((void**)&gkwT, g_kwT);
    cudaGetSymbolAddress((void**)&gvwT, g_vwT);
    cudaGetSymbolAddress((void**)&gowT, g_owT);
    cudaGetSymbolAddress((void**)&gq,   g_q);
    cudaGetSymbolAddress((void**)&gk,   g_k);
    cudaGetSymbolAddress((void**)&gv,   g_v);
    cudaGetSymbolAddress((void**)&gctx, g_ctx);
    cudaGetSymbolAddress((void**)&gcp,  g_colpart);

    // fork from the capture (legacy) stream
    cudaEventRecord(evRoot, 0);
    cudaStreamWaitEvent(sA, evRoot, 0);
    cudaStreamWaitEvent(sB, evRoot, 0);
    cudaStreamWaitEvent(sC, evRoot, 0);

    dim3 tb(32, 8);
    // sA: hid f16; sC: trr_q (concurrent)
    f2h_kernel<<<(S_LEN * DMODEL / 8 + 255) / 256, 256, 0, sA>>>(
        ghid, hidden, S_LEN * DMODEL / 8);
    cudaEventRecord(evHid, sA);
    trrh_kernel<<<dim3(DMODEL / 32, DMODEL / 32), tb, 0, sC>>>(gqwT, q_w, DMODEL, DMODEL);
    cudaEventRecord(evTrrQ, sC);
    // sB: trr_k, trr_v
    trrh_kernel<<<dim3(KV_DM / 32, DMODEL / 32), tb, 0, sB>>>(gkwT, k_w, DMODEL, KV_DM);
    trrh_kernel<<<dim3(KV_DM / 32, DMODEL / 32), tb, 0, sB>>>(gvwT, v_w, DMODEL, KV_DM);
    // sC: trr_o, zero
    trrh_kernel<<<dim3(DMODEL / 32, DMODEL / 32), tb, 0, sC>>>(gowT, o_w, DMODEL, DMODEL);
    cudaEventRecord(evTrrO, sC);

    // Q projection (fp16, out half)
    cudaStreamWaitEvent(sA, evTrrQ, 0);
    gemm_h<true, false, true><<<dim3(DMODEL / 128, S_LEN / 128, 1), 256, GEMM_H_SMEM, sA>>>(
        ghid, gqwT, nullptr, q_b, nullptr, gq, nullptr, DMODEL);

    // KV projections (z-fused: K half, V half), concurrent with Q
    cudaStreamWaitEvent(sB, evHid, 0);
    gemm_h<true, true, true><<<dim3(KV_DM / 128, S_LEN / 128, 2), 256, GEMM_H_SMEM, sB>>>(
        ghid, gkwT, gvwT, k_b, v_b, gk, gv, KV_DM);
    cudaEventRecord(evKV, sB);

    const int ncp = NH * NQT16 * S_LEN;
    zero_kernel<<<(ncp + 255) / 256, 256, 0, sC>>>(gcp, ncp);
    cudaEventRecord(evZero, sC);

    cudaStreamWaitEvent(sA, evKV, 0);
    scores_h<<<dim3(16, 16, NH), 256, SCORES_SMEM, sA>>>();

    cudaStreamWaitEvent(sA, evZero, 0);
    attn_pv<<<dim3(16, NH), 512, ATTN_SMEM, sA>>>();
    cudaEventRecord(evAttn, sA);

    // sC: topk (after attn), overlaps with gemmO on sA
    cudaStreamWaitEvent(sC, evAttn, 0);
    topk_kernel<<<NH, 1024, 0, sC>>>(out + (size_t)S_LEN * DMODEL);
    cudaEventRecord(evDoneC, sC);

    // output projection (fp16 in, f32 out, no bias)
    cudaStreamWaitEvent(sA, evTrrO, 0);
    gemm_h<false, false, false><<<dim3(DMODEL / 128, S_LEN / 128, 1), 256, GEMM_H_SMEM, sA>>>(
        gctx, gowT, nullptr, nullptr, nullptr, out, nullptr, DMODEL);
    cudaEventRecord(evDoneA, sA);

    // join back to the capture stream
    cudaStreamWaitEvent(0, evDoneA, 0);
    cudaStreamWaitEvent(0, evDoneC, 0);
}

// round 13
// speedup vs baseline: 1.8697x; 1.0184x over previous
#include <cuda_runtime.h>
#include <cuda_fp16.h>
#include <cstdint>

#define S_LEN   2048
#define DMODEL  2048
#define NH      16
#define HDIM    128
#define KV_DM   512
#define NQT16   16
#define HEAVY   204
#define RECENT  204
#define SEL     (S_LEN - RECENT)    // 1844
#define MASKW   (S_LEN + 1)         // 2049

__device__ __half g_hid[S_LEN * DMODEL];
__device__ __half g_qwT[DMODEL * DMODEL];   // [n][k]
__device__ __half g_kwT[KV_DM * DMODEL];
__device__ __half g_vwT[KV_DM * DMODEL];
__device__ __half g_owT[DMODEL * DMODEL];
__device__ __half g_q[S_LEN * DMODEL];
__device__ __half g_k[S_LEN * KV_DM];
__device__ __half g_v[S_LEN * KV_DM];
__device__ __half g_ctx[S_LEN * DMODEL];
__device__ float  g_colpart[NH * NQT16 * S_LEN];
__device__ float  g_lpart[NH * S_LEN * 16];
__device__ __half g_E[(size_t)NH * S_LEN * S_LEN];   // exp'd scores, fp16

// ---------------------------------------------------------------------------
__device__ __forceinline__ float ex2f(float x) {
    float y;
    asm("ex2.approx.ftz.f32 %0, %1;" : "=f"(y) : "f"(x));
    return y;
}
__device__ __forceinline__ void mma_f16(float* c, const uint32_t* a, const uint32_t* b) {
    asm volatile(
        "mma.sync.aligned.m16n8k16.row.col.f32.f16.f16.f32 "
        "{%0,%1,%2,%3}, {%4,%5,%6,%7}, {%8,%9}, {%0,%1,%2,%3};"
        : "+f"(c[0]), "+f"(c[1]), "+f"(c[2]), "+f"(c[3])
        : "r"(a[0]), "r"(a[1]), "r"(a[2]), "r"(a[3]), "r"(b[0]), "r"(b[1]));
}
__device__ __forceinline__ void ldsm4(uint32_t& r0, uint32_t& r1, uint32_t& r2, uint32_t& r3,
                                      uint32_t addr) {
    asm volatile("ldmatrix.sync.aligned.m8n8.x4.shared.b16 {%0,%1,%2,%3}, [%4];"
                 : "=r"(r0), "=r"(r1), "=r"(r2), "=r"(r3) : "r"(addr));
}
__device__ __forceinline__ void ldsm4t(uint32_t& r0, uint32_t& r1, uint32_t& r2, uint32_t& r3,
                                       uint32_t addr) {
    asm volatile("ldmatrix.sync.aligned.m8n8.x4.trans.shared.b16 {%0,%1,%2,%3}, [%4];"
                 : "=r"(r0), "=r"(r1), "=r"(r2), "=r"(r3) : "r"(addr));
}
__device__ __forceinline__ void cpa16(uint32_t s, const void* g) {
    asm volatile("cp.async.cg.shared.global [%0], [%1], 16;" :: "r"(s), "l"(g));
}
__device__ __forceinline__ void cp_commit() { asm volatile("cp.async.commit_group;"); }
template<int N> __device__ __forceinline__ void cp_wait() {
    asm volatile("cp.async.wait_group %0;" :: "n"(N));
}
__device__ __forceinline__ unsigned encf(float x) {
    unsigned b = __float_as_uint(x);
    return (b & 0x80000000u) ? ~b : (b | 0x80000000u);
}

__global__ void zero_kernel(float* p, int n) {
    int i = blockIdx.x * 256 + threadIdx.x;
    if (i < n) p[i] = 0.0f;
}
__global__ void f2h_kernel(__half* dst, const float* src, int n8) {
    int i = blockIdx.x * 256 + threadIdx.x;
    if (i < n8) {
        const float4 v0 = *(const float4*)&src[i * 8];
        const float4 v1 = *(const float4*)&src[i * 8 + 4];
        __half2 h[4];
        h[0] = __floats2half2_rn(v0.x, v0.y);
        h[1] = __floats2half2_rn(v0.z, v0.w);
        h[2] = __floats2half2_rn(v1.x, v1.y);
        h[3] = __floats2half2_rn(v1.z, v1.w);
        *(uint4*)&dst[i * 8] = *(uint4*)h;
    }
}
__global__ __launch_bounds__(256) void trrh_kernel(__half* dst, const float* src, int Kd, int Nd) {
    __shared__ float t[32][33];
    const int bx = blockIdx.x * 32;
    const int by = blockIdx.y * 32;
    const int tx = threadIdx.x, ty = threadIdx.y;
#pragma unroll
    for (int i = 0; i < 32; i += 8)
        t[ty + i][tx] = src[(size_t)(by + ty + i) * Nd + bx + tx];
    __syncthreads();
#pragma unroll
    for (int i = 0; i < 32; i += 8)
        dst[(size_t)(bx + ty + i) * Kd + by + tx] = __float2half_rn(t[tx][ty + i]);
}

// ---------------------------------------------------------------------------
// fp16 GEMM: 128x128 tile, BK=32, ldmatrix b16 + 3-stage cp.async,
// 1 barrier/iter, 2 CTAs/SM.
// ---------------------------------------------------------------------------
#define GEMM_H_SMEM (2 * (3 * 128 * 40) * 2)

template<bool OUT0_HALF, bool OUT1_HALF, bool HASBIAS>
__global__ __launch_bounds__(256, 2) void gemm_h(
    const __half* __restrict__ A,
    const __half* __restrict__ Bt0, const __half* __restrict__ Bt1,
    const float* __restrict__ bias0, const float* __restrict__ bias1,
    void* __restrict__ C0, void* __restrict__ C1, int N)
{
    constexpr int KD = 2048, BK = 32, ASS = 40;
    constexpr int NIT = KD / BK;

    extern __shared__ __half smem_h[];
    __half* AsH = smem_h;
    __half* BsH = smem_h + 3 * 128 * ASS;

    const int tid = threadIdx.x;
    const int lane = tid & 31, w = tid >> 5;
    const int wm0 = (w & 1) * 64;
    const int wn0 = (w >> 1) * 32;
    const int bm = blockIdx.y * 128;
    const int bn = blockIdx.x * 128;

    const __half* Bt = (blockIdx.z == 0) ? Bt0 : Bt1;
    const float* bia = (blockIdx.z == 0) ? bias0 : bias1;

    const int cr = tid & 127;
    const int co = (tid >> 7) * 16;
    const uint32_t sA = (uint32_t)__cvta_generic_to_shared(AsH);
    const uint32_t sB = (uint32_t)__cvta_generic_to_shared(BsH);

    const int a_row = lane & 15;
    const int a_k8  = (lane >> 4) * 8;
    const int b_row = (lane & 7) + ((lane >> 3) & 1) * 8;
    const int b_k8  = (lane >> 4) * 8;

    float acc[4][4][4];
#pragma unroll
    for (int mi = 0; mi < 4; mi++)
#pragma unroll
        for (int nj = 0; nj < 4; nj++)
#pragma unroll
            for (int c = 0; c < 4; c++) acc[mi][nj][c] = 0.0f;

    auto issue = [&](int st, int k0) {
        const __half* ga = &A[(size_t)(bm + cr) * KD + k0 + co];
        uint32_t sa = sA + (uint32_t)((st * 128 + cr) * ASS + co) * 2u;
        cpa16(sa, ga); cpa16(sa + 16, ga + 8);
        const __half* gb = &Bt[(size_t)(bn + cr) * KD + k0 + co];
        uint32_t sb = sB + (uint32_t)((st * 128 + cr) * ASS + co) * 2u;
        cpa16(sb, gb); cpa16(sb + 16, gb + 8);
    };

    issue(0, 0);       cp_commit();
    issue(1, BK);      cp_commit();

    int st = 0;
    for (int it = 0; it < NIT; it++) {
        if (it + 1 < NIT) cp_wait<1>(); else cp_wait<0>();
        __syncthreads();
        const uint32_t aB = sA + (uint32_t)(st * 128 * ASS) * 2u;
        const uint32_t bB = sB + (uint32_t)(st * 128 * ASS) * 2u;

#pragma unroll
        for (int ks = 0; ks < 2; ks++) {
            const int kk = ks * 16;
            uint32_t af[4][4], bf[4][2];
#pragma unroll
            for (int mi = 0; mi < 4; mi++) {
                uint32_t ad = aB + (uint32_t)(((wm0 + 16 * mi + a_row) * ASS) + kk + a_k8) * 2u;
                ldsm4(af[mi][0], af[mi][1], af[mi][2], af[mi][3], ad);
            }
#pragma unroll
            for (int p = 0; p < 2; p++) {
                uint32_t bd = bB + (uint32_t)(((wn0 + 16 * p + b_row) * ASS) + kk + b_k8) * 2u;
                uint32_t r0, r1, r2, r3;
                ldsm4(r0, r1, r2, r3, bd);
                bf[2 * p][0] = r0; bf[2 * p][1] = r2;
                bf[2 * p + 1][0] = r1; bf[2 * p + 1][1] = r3;
            }
#pragma unroll
            for (int mi = 0; mi < 4; mi++)
#pragma unroll
                for (int nj = 0; nj < 4; nj++)
                    mma_f16(acc[mi][nj], af[mi], bf[nj]);
        }

        if (it + 2 < NIT) {
            issue((st + 2) % 3, (it + 2) * BK);
            cp_commit();
        }
        st = (st + 1) % 3;
    }

    const bool outHalf = (blockIdx.z == 0) ? OUT0_HALF : OUT1_HALF;
    void* C = (blockIdx.z == 0) ? C0 : C1;
#pragma unroll
    for (int mi = 0; mi < 4; mi++) {
#pragma unroll
        for (int nj = 0; nj < 4; nj++) {
            int row = bm + wm0 + 16 * mi + (lane >> 2);
            int col = bn + wn0 + 8 * nj + 2 * (lane & 3);
            float bx = 0.0f, by = 0.0f;
            if (HASBIAS) { bx = bia[col]; by = bia[col + 1]; }
            float v0x = acc[mi][nj][0] + bx, v0y = acc[mi][nj][1] + by;
            float v1x = acc[mi][nj][2] + bx, v1y = acc[mi][nj][3] + by;
            if (outHalf) {
                __half* Ch = (__half*)C;
                *(__half2*)&Ch[(size_t)row * N + col] = __floats2half2_rn(v0x, v0y);
                *(__half2*)&Ch[(size_t)(row + 8) * N + col] = __floats2half2_rn(v1x, v1y);
            } else {
                float* Cf = (float*)C;
                *(float2*)&Cf[(size_t)row * N + col] = make_float2(v0x, v0y);
                *(float2*)&Cf[(size_t)(row + 8) * N + col] = make_float2(v1x, v1y);
            }
        }
    }
}

// ---------------------------------------------------------------------------
// Scores (fp16): E = 2^(QK^T * scale * log2e) causal-masked, stored fp16;
// l-partials accumulated from ROUNDED values.
// ---------------------------------------------------------------------------
#define SCORES_SMEM (2 * (3 * 128 * 40) * 2 + 128 * 4 * 4)

__global__ __launch_bounds__(256, 2) void scores_h() {
    constexpr int ASS = 40, BK = 32;
    const int nb = blockIdx.x, mb = blockIdx.y, h = blockIdx.z;
    if (nb > mb) return;
    const int kvh = h >> 2;

    extern __shared__ __half smem_h[];
    __half* AsH = smem_h;
    __half* BsH = smem_h + 3 * 128 * ASS;
    float* red = (float*)(smem_h + 2 * 3 * 128 * ASS);

    const int tid = threadIdx.x;
    const int lane = tid & 31, w = tid >> 5;
    const int wm0 = (w & 1) * 64;
    const int wn0 = (w >> 1) * 32;

    const int cr = tid & 127;
    const int co = (tid >> 7) * 16;
    const uint32_t sA = (uint32_t)__cvta_generic_to_shared(AsH);
    const uint32_t sB = (uint32_t)__cvta_generic_to_shared(BsH);

    const int a_row = lane & 15;
    const int a_k8  = (lane >> 4) * 8;
    const int b_row = (lane & 7) + ((lane >> 3) & 1) * 8;
    const int b_k8  = (lane >> 4) * 8;

    const __half* Qg = g_q + (size_t)(mb * 128) * DMODEL + h * HDIM;
    const __half* Kg = g_k + (size_t)(nb * 128) * KV_DM + kvh * HDIM;

    float acc[4][4][4];
#pragma unroll
    for (int mi = 0; mi < 4; mi++)
#pragma unroll
        for (int nj = 0; nj < 4; nj++)
#pragma unroll
            for (int c = 0; c < 4; c++) acc[mi][nj][c] = 0.0f;

    auto issue = [&](int st, int k0) {
        const __half* ga = &Qg[(size_t)cr * DMODEL + k0 + co];
        uint32_t sa = sA + (uint32_t)((st * 128 + cr) * ASS + co) * 2u;
        cpa16(sa, ga); cpa16(sa + 16, ga + 8);
        const __half* gb = &Kg[(size_t)cr * KV_DM + k0 + co];
        uint32_t sb = sB + (uint32_t)((st * 128 + cr) * ASS + co) * 2u;
        cpa16(sb, gb); cpa16(sb + 16, gb + 8);
    };

    issue(0, 0);      cp_commit();
    issue(1, BK);     cp_commit();

    constexpr int NIT = HDIM / BK;   // 4
    int st = 0;
    for (int it = 0; it < NIT; it++) {
        if (it + 1 < NIT) cp_wait<1>(); else cp_wait<0>();
        __syncthreads();
        const uint32_t aB = sA + (uint32_t)(st * 128 * ASS) * 2u;
        const uint32_t bB = sB + (uint32_t)(st * 128 * ASS) * 2u;
#pragma unroll
        for (int ks = 0; ks < 2; ks++) {
            const int kk = ks * 16;
            uint32_t af[4][4], bf[4][2];
#pragma unroll
            for (int mi = 0; mi < 4; mi++) {
                uint32_t ad = aB + (uint32_t)(((wm0 + 16 * mi + a_row) * ASS) + kk + a_k8) * 2u;
                ldsm4(af[mi][0], af[mi][1], af[mi][2], af[mi][3], ad);
            }
#pragma unroll
            for (int p = 0; p < 2; p++) {
                uint32_t bd = bB + (uint32_t)(((wn0 + 16 * p + b_row) * ASS) + kk + b_k8) * 2u;
                uint32_t r0, r1, r2, r3;
                ldsm4(r0, r1, r2, r3, bd);
                bf[2 * p][0] = r0; bf[2 * p][1] = r2;
                bf[2 * p + 1][0] = r1; bf[2 * p + 1][1] = r3;
            }
#pragma unroll
            for (int mi = 0; mi < 4; mi++)
#pragma unroll
                for (int nj = 0; nj < 4; nj++)
                    mma_f16(acc[mi][nj], af[mi], bf[nj]);
        }
        if (it + 2 < NIT) {
            issue((st + 2) % 3, (it + 2) * BK);
            cp_commit();
        }
        st = (st + 1) % 3;
    }

    const float SCL2 = 0.08838834764831845f * 1.4426950408889634f;
    __half* Eh = g_E + (size_t)h * S_LEN * S_LEN;
    float rs[4][2];
#pragma unroll
    for (int mi = 0; mi < 4; mi++) { rs[mi][0] = 0.f; rs[mi][1] = 0.f; }

#pragma unroll
    for (int mi = 0; mi < 4; mi++) {
#pragma unroll
        for (int nj = 0; nj < 4; nj++) {
            int row = mb * 128 + wm0 + 16 * mi + (lane >> 2);
            int col = nb * 128 + wn0 + 8 * nj + 2 * (lane & 3);
            float e0 = (col     <= row)     ? ex2f(acc[mi][nj][0] * SCL2) : 0.f;
            float e1 = (col + 1 <= row)     ? ex2f(acc[mi][nj][1] * SCL2) : 0.f;
            float e2 = (col     <= row + 8) ? ex2f(acc[mi][nj][2] * SCL2) : 0.f;
            float e3 = (col + 1 <= row + 8) ? ex2f(acc[mi][nj][3] * SCL2) : 0.f;
            __half2 h01 = __floats2half2_rn(e0, e1);
            __half2 h23 = __floats2half2_rn(e2, e3);
            *(__half2*)&Eh[(size_t)row * S_LEN + col] = h01;
            *(__half2*)&Eh[(size_t)(row + 8) * S_LEN + col] = h23;
            float2 f01 = __half22float2(h01);
            float2 f23 = __half22float2(h23);
            rs[mi][0] += f01.x + f01.y;
            rs[mi][1] += f23.x + f23.y;
        }
    }
#pragma unroll
    for (int mi = 0; mi < 4; mi++)
#pragma unroll
        for (int hh = 0; hh < 2; hh++) {
            rs[mi][hh] += __shfl_xor_sync(0xFFFFFFFFu, rs[mi][hh], 1);
            rs[mi][hh] += __shfl_xor_sync(0xFFFFFFFFu, rs[mi][hh], 2);
        }
    if ((lane & 3) == 0) {
        int wg = w >> 1;
#pragma unroll
        for (int mi = 0; mi < 4; mi++) {
            red[(wm0 + 16 * mi + (lane >> 2)) * 4 + wg]     = rs[mi][0];
            red[(wm0 + 16 * mi + 8 + (lane >> 2)) * 4 + wg] = rs[mi][1];
        }
    }
    __syncthreads();
    if (tid < 128)
        g_lpart[((size_t)h * S_LEN + mb * 128 + tid) * 16 + nb] =
            red[tid * 4] + red[tid * 4 + 1] + red[tid * 4 + 2] + red[tid * 4 + 3];
}

// ---------------------------------------------------------------------------
// Attention over E (fp16): 3-stage cp.async pipelined E/V tiles, fragment
// scaling by 1/l in registers, 1 barrier/iter, deferred colsum writes.
// smem: Es[3][128*72]h, Vs[3][64*136]h, red f32[2][256], il f32[128].
// ---------------------------------------------------------------------------
#define ESS 72
#define VSS 136
#define ATTN_SMEM (3 * 128 * ESS * 2 + 3 * 64 * VSS * 2 + 2 * 256 * 4 + 128 * 4)

__global__ __launch_bounds__(512, 1) void attn_pv() {
    extern __shared__ __half smh[];
    __half* Es = smh;                               // [3][128][72]
    __half* Vs = smh + 3 * 128 * ESS;               // [3][64][136]
    float* red = (float*)(smh + 3 * 128 * ESS + 3 * 64 * VSS);  // [2][256]
    float* il  = red + 2 * 256;                     // [128]

    const int qt = 15 - blockIdx.x;
    const int h  = blockIdx.y;
    const int kvh = h >> 2;
    const int qbase = qt * 128;
    const int tid = threadIdx.x;
    const int lane = tid & 31, w = tid >> 5;
    const int wm  = (w & 3) * 32;
    const int wn2 = (w >> 2) * 32;

    const int a_row = lane & 15;
    const int a_k8  = (lane >> 4) * 8;
    const uint32_t sET = (uint32_t)__cvta_generic_to_shared(Es);
    const uint32_t sVT = (uint32_t)__cvta_generic_to_shared(Vs);

    const __half* Eg = g_E + (size_t)h * S_LEN * S_LEN;
    const int nkt = 2 * qt + 2;

    const int prow = tid >> 2, pcb = (tid & 3) * 16;
    const int vr = tid >> 3, vcb = (tid & 7) * 16;

    auto issue = [&](int st, int kt) {
        const __half* ep = &Eg[(size_t)(qbase + prow) * S_LEN + kt * 64 + pcb];
        uint32_t se = sET + (uint32_t)((st * 128 + prow) * ESS + pcb) * 2u;
        cpa16(se, ep); cpa16(se + 16, ep + 8);
        const __half* vp = &g_v[(size_t)(kt * 64 + vr) * KV_DM + kvh * HDIM + vcb];
        uint32_t sv = sVT + (uint32_t)((st * 64 + vr) * VSS + vcb) * 2u;
        cpa16(sv, vp); cpa16(sv + 16, vp + 8);
    };

    issue(0, 0);  cp_commit();
    issue(1, 1);  cp_commit();   // nkt >= 2 always

    if (tid < 128) {
        const float* lp = &g_lpart[((size_t)h * S_LEN + qbase + tid) * 16];
        float l = 0.0f;
        for (int nb = 0; nb <= qt; nb++) l += lp[nb];
        il[tid] = 1.0f / l;
    }
    __syncthreads();

    // per-warp row scales (fragment rows: g = wm+16*mi+(lane>>2), g+8)
    float il0[2], il1[2];
#pragma unroll
    for (int mi = 0; mi < 2; mi++) {
        il0[mi] = il[wm + 16 * mi + (lane >> 2)];
        il1[mi] = il[wm + 16 * mi + 8 + (lane >> 2)];
    }

    float o[2][4][4];
#pragma unroll
    for (int mi = 0; mi < 2; mi++)
#pragma unroll
        for (int nj = 0; nj < 4; nj++)
#pragma unroll
            for (int c = 0; c < 4; c++) o[mi][nj][c] = 0.0f;

    float* cpart = &g_colpart[((size_t)h * NQT16 + qt) * S_LEN];

    int st = 0;
    for (int kt = 0; kt < nkt; kt++) {
        if (kt + 1 < nkt) cp_wait<1>(); else cp_wait<0>();
        __syncthreads();

        // deferred colpart write for tile kt-1 (red writes ordered by the sync)
        if (kt > 0 && tid < 64) {
            const float* rp = &red[((kt - 1) & 1) * 256 + tid * 4];
            cpart[(kt - 1) * 64 + tid] = rp[0] + rp[1] + rp[2] + rp[3];
        }

        if (kt + 2 < nkt) {
            issue((st + 2) % 3, kt + 2);
            cp_commit();
        }

        // colsum partials: f32 E * il, 4 segments of 32 rows
        if (tid < 256) {
            int c = tid & 63, seg = tid >> 6;
            const __half* eb = &Es[(st * 128 + seg * 32) * ESS + c];
            float cs = 0.0f;
#pragma unroll 8
            for (int q = 0; q < 32; q++)
                cs += __half2float(eb[q * ESS]) * il[seg * 32 + q];
            red[(kt & 1) * 256 + c * 4 + seg] = cs;
        }

        // P@V: ldmatrix raw E, scale fragments by il in f32, fp16 mma
        const uint32_t eB = sET + (uint32_t)(st * 128 * ESS) * 2u;
        const uint32_t vB = sVT + (uint32_t)(st * 64 * VSS) * 2u;
#pragma unroll
        for (int ks = 0; ks < 4; ks++) {
            const int kk = ks * 16;
            uint32_t af[2][4], bf[4][2];
#pragma unroll
            for (int mi = 0; mi < 2; mi++) {
                uint32_t ad = eB + (uint32_t)(((wm + 16 * mi + a_row) * ESS) + kk + a_k8) * 2u;
                ldsm4(af[mi][0], af[mi][1], af[mi][2], af[mi][3], ad);
#pragma unroll
                for (int r = 0; r < 4; r++) {
                    float s = (r & 1) ? il1[mi] : il0[mi];
                    __half2 hv = *(__half2*)&af[mi][r];
                    float2 f = __half22float2(hv);
                    __half2 ho = __floats2half2_rn(f.x * s, f.y * s);
                    af[mi][r] = *(uint32_t*)&ho;
                }
            }
#pragma unroll
            for (int p = 0; p < 2; p++) {
                uint32_t bd = vB + (uint32_t)(((kk + (lane & 15)) * VSS) + wn2 + p * 16 + (lane >> 4) * 8) * 2u;
                uint32_t r0, r1, r2, r3;
                ldsm4t(r0, r1, r2, r3, bd);
                bf[2 * p][0] = r0; bf[2 * p][1] = r1;
                bf[2 * p + 1][0] = r2; bf[2 * p + 1][1] = r3;
            }
#pragma unroll
            for (int mi = 0; mi < 2; mi++)
#pragma unroll
                for (int nj = 0; nj < 4; nj++)
                    mma_f16(o[mi][nj], af[mi], bf[nj]);
        }
        st = (st + 1) % 3;
    }

    __syncthreads();
    if (tid < 64) {
        const float* rp = &red[((nkt - 1) & 1) * 256 + tid * 4];
        cpart[(nkt - 1) * 64 + tid] = rp[0] + rp[1] + rp[2] + rp[3];
    }

#pragma unroll
    for (int mi = 0; mi < 2; mi++)
#pragma unroll
        for (int nj = 0; nj < 4; nj++) {
            int row = qbase + wm + 16 * mi + (lane >> 2);
            int col = h * HDIM + wn2 + 8 * nj + 2 * (lane & 3);
            *(__half2*)&g_ctx[(size_t)row * DMODEL + col] =
                __floats2half2_rn(o[mi][nj][0], o[mi][nj][1]);
            *(__half2*)&g_ctx[(size_t)(row + 8) * DMODEL + col] =
                __floats2half2_rn(o[mi][nj][2], o[mi][nj][3]);
        }
}

// ---------------------------------------------------------------------------
// Heavy-hitter mask via bitonic sort (exact jax.lax.top_k tie semantics).
// ---------------------------------------------------------------------------
__global__ __launch_bounds__(1024) void topk_kernel(float* __restrict__ mask_out) {
    const int h = blockIdx.x;
    const int tid = threadIdx.x;
    __shared__ unsigned long long keys[2048];

    for (int i = tid; i < 2048; i += 1024) {
        unsigned ev = 0u;
        if (i < SEL) {
            float s = 0.0f;
#pragma unroll
            for (int qt = 0; qt < NQT16; qt++)
                s += g_colpart[((size_t)h * NQT16 + qt) * S_LEN + i];
            ev = encf(s);
        }
        keys[i] = ((unsigned long long)ev << 32) | (unsigned)(2047 - i);
    }
    float* mrow = mask_out + (size_t)h * MASKW;
    for (int i = tid; i < MASKW; i += 1024)
        mrow[i] = (i >= (MASKW - RECENT)) ? 1.0f : 0.0f;
    __syncthreads();

    for (int k = 2; k <= 2048; k <<= 1) {
        for (int j = k >> 1; j > 0; j >>= 1) {
            for (int idx = tid; idx < 2048; idx += 1024) {
                int ixj = idx ^ j;
                if (ixj > idx) {
                    unsigned long long a = keys[idx], b = keys[ixj];
                    bool up = (idx & k) == 0;
                    if (up ? (a > b) : (a < b)) { keys[idx] = b; keys[ixj] = a; }
                }
            }
            __syncthreads();
        }
    }
    for (int i = 2048 - HEAVY + tid; i < 2048; i += 1024) {
        int idx = 2047 - (int)(keys[i] & 0xFFFFFFFFu);
        mrow[idx] = 1.0f;
    }
}

// ---------------------------------------------------------------------------
extern "C" void kernel_launch(void* const* d_in, const int* in_sizes, int n_in,
                              void* d_out, int out_size) {
    (void)in_sizes; (void)n_in; (void)out_size;
    const float* hidden = (const float*)d_in[0];
    const float* q_w = (const float*)d_in[1];
    const float* q_b = (const float*)d_in[2];
    const float* k_w = (const float*)d_in[3];
    const float* k_b = (const float*)d_in[4];
    const float* v_w = (const float*)d_in[5];
    const float* v_b = (const float*)d_in[6];
    const float* o_w = (const float*)d_in[7];
    float* out = (float*)d_out;

    static bool init = false;
    static cudaStream_t sA, sB, sC;
    static cudaEvent_t evRoot, evHid, evKV, evZero, evAttn, evTrrO, evTrrQ, evDoneA, evDoneC;
    if (!init) {
        cudaFuncSetAttribute(attn_pv, cudaFuncAttributeMaxDynamicSharedMemorySize, ATTN_SMEM);
        cudaFuncSetAttribute(gemm_h<true, false, true>,
                             cudaFuncAttributeMaxDynamicSharedMemorySize, GEMM_H_SMEM);
        cudaFuncSetAttribute(gemm_h<true, true, true>,
                             cudaFuncAttributeMaxDynamicSharedMemorySize, GEMM_H_SMEM);
        cudaFuncSetAttribute(gemm_h<false, false, false>,
                             cudaFuncAttributeMaxDynamicSharedMemorySize, GEMM_H_SMEM);
        cudaFuncSetAttribute(scores_h,
                             cudaFuncAttributeMaxDynamicSharedMemorySize, SCORES_SMEM);
        cudaStreamCreateWithFlags(&sA, cudaStreamNonBlocking);
        cudaStreamCreateWithFlags(&sB, cudaStreamNonBlocking);
        cudaStreamCreateWithFlags(&sC, cudaStreamNonBlocking);
        cudaEventCreateWithFlags(&evRoot, cudaEventDisableTiming);
        cudaEventCreateWithFlags(&evHid,  cudaEventDisableTiming);
        cudaEventCreateWithFlags(&evKV,   cudaEventDisableTiming);
        cudaEventCreateWithFlags(&evZero, cudaEventDisableTiming);
        cudaEventCreateWithFlags(&evAttn, cudaEventDisableTiming);
        cudaEventCreateWithFlags(&evTrrO, cudaEventDisableTiming);
        cudaEventCreateWithFlags(&evTrrQ, cudaEventDisableTiming);
        cudaEventCreateWithFlags(&evDoneA, cudaEventDisableTiming);
        cudaEventCreateWithFlags(&evDoneC, cudaEventDisableTiming);
        init = true;
    }

    __half *ghid, *gqwT, *gkwT, *gvwT, *gowT, *gq, *gk, *gv, *gctx;
    float *gcp;
    cudaGetSymbolAddress((void**)&ghid, g_hid);
    cudaGetSymbolAddress((void**)&gqwT, g_qwT);
    cudaGetSymbolAddress((void**)&gkwT, g_kwT);
    cudaGetSymbolAddress((void**)&gvwT, g_vwT);
    cudaGetSymbolAddress((void**)&gowT, g_owT);
    cudaGetSymbolAddress((void**)&gq,   g_q);
    cudaGetSymbolAddress((void**)&gk,   g_k);
    cudaGetSymbolAddress((void**)&gv,   g_v);
    cudaGetSymbolAddress((void**)&gctx, g_ctx);
    cudaGetSymbolAddress((void**)&gcp,  g_colpart);

    cudaEventRecord(evRoot, 0);
    cudaStreamWaitEvent(sA, evRoot, 0);
    cudaStreamWaitEvent(sB, evRoot, 0);
    cudaStreamWaitEvent(sC, evRoot, 0);

    dim3 tb(32, 8);
    f2h_kernel<<<(S_LEN * DMODEL / 8 + 255) / 256, 256, 0, sA>>>(
        ghid, hidden, S_LEN * DMODEL / 8);
    cudaEventRecord(evHid, sA);
    trrh_kernel<<<dim3(DMODEL / 32, DMODEL / 32), tb, 0, sC>>>(gqwT, q_w, DMODEL, DMODEL);
    cudaEventRecord(evTrrQ, sC);
    trrh_kernel<<<dim3(KV_DM / 32, DMODEL / 32), tb, 0, sB>>>(gkwT, k_w, DMODEL, KV_DM);
    trrh_kernel<<<dim3(KV_DM / 32, DMODEL / 32), tb, 0, sB>>>(gvwT, v_w, DMODEL, KV_DM);
    trrh_kernel<<<dim3(DMODEL / 32, DMODEL / 32), tb, 0, sC>>>(gowT, o_w, DMODEL, DMODEL);
    cudaEventRecord(evTrrO, sC);

    cudaStreamWaitEvent(sA, evTrrQ, 0);
    gemm_h<true, false, true><<<dim3(DMODEL / 128, S_LEN / 128, 1), 256, GEMM_H_SMEM, sA>>>(
        ghid, gqwT, nullptr, q_b, nullptr, gq, nullptr, DMODEL);

    cudaStreamWaitEvent(sB, evHid, 0);
    gemm_h<true, true, true><<<dim3(KV_DM / 128, S_LEN / 128, 2), 256, GEMM_H_SMEM, sB>>>(
        ghid, gkwT, gvwT, k_b, v_b, gk, gv, KV_DM);
    cudaEventRecord(evKV, sB);

    const int ncp = NH * NQT16 * S_LEN;
    zero_kernel<<<(ncp + 255) / 256, 256, 0, sC>>>(gcp, ncp);
    cudaEventRecord(evZero, sC);

    cudaStreamWaitEvent(sA, evKV, 0);
    scores_h<<<dim3(16, 16, NH), 256, SCORES_SMEM, sA>>>();

    cudaStreamWaitEvent(sA, evZero, 0);
    attn_pv<<<dim3(16, NH), 512, ATTN_SMEM, sA>>>();
    cudaEventRecord(evAttn, sA);

    cudaStreamWaitEvent(sC, evAttn, 0);
    topk_kernel<<<NH, 1024, 0, sC>>>(out + (size_t)S_LEN * DMODEL);
    cudaEventRecord(evDoneC, sC);

    cudaStreamWaitEvent(sA, evTrrO, 0);
    gemm_h<false, false, false><<<dim3(DMODEL / 128, S_LEN / 128, 1), 256, GEMM_H_SMEM, sA>>>(
        gctx, gowT, nullptr, nullptr, nullptr, out, nullptr, DMODEL);
    cudaEventRecord(evDoneA, sA);

    cudaStreamWaitEvent(0, evDoneA, 0);
    cudaStreamWaitEvent(0, evDoneC, 0);
}

// round 15
// speedup vs baseline: 1.9676x; 1.0524x over previous
#include <cuda_runtime.h>
#include <cuda_fp16.h>
#include <cstdint>

#define S_LEN   2048
#define DMODEL  2048
#define NH      16
#define HDIM    128
#define KV_DM   512
#define NQT16   16
#define HEAVY   204
#define RECENT  204
#define SEL     (S_LEN - RECENT)    // 1844
#define MASKW   (S_LEN + 1)         // 2049

__device__ __half g_hid[S_LEN * DMODEL];
__device__ __half g_qwT[DMODEL * DMODEL];   // [n][k]
__device__ __half g_kwT[KV_DM * DMODEL];
__device__ __half g_vwT[KV_DM * DMODEL];
__device__ __half g_owT[DMODEL * DMODEL];
__device__ __half g_q[S_LEN * DMODEL];
__device__ __half g_k[S_LEN * KV_DM];
__device__ __half g_v[S_LEN * KV_DM];
__device__ __half g_ctx[S_LEN * DMODEL];
__device__ float  g_colpart[NH * NQT16 * S_LEN];
__device__ float  g_lpart[NH * S_LEN * 16];
__device__ __half g_E[(size_t)NH * S_LEN * S_LEN];   // exp'd scores, fp16

// ---------------------------------------------------------------------------
__device__ __forceinline__ float ex2f(float x) {
    float y;
    asm("ex2.approx.ftz.f32 %0, %1;" : "=f"(y) : "f"(x));
    return y;
}
__device__ __forceinline__ void mma_f16(float* c, const uint32_t* a, const uint32_t* b) {
    asm volatile(
        "mma.sync.aligned.m16n8k16.row.col.f32.f16.f16.f32 "
        "{%0,%1,%2,%3}, {%4,%5,%6,%7}, {%8,%9}, {%0,%1,%2,%3};"
        : "+f"(c[0]), "+f"(c[1]), "+f"(c[2]), "+f"(c[3])
        : "r"(a[0]), "r"(a[1]), "r"(a[2]), "r"(a[3]), "r"(b[0]), "r"(b[1]));
}
__device__ __forceinline__ void ldsm4(uint32_t& r0, uint32_t& r1, uint32_t& r2, uint32_t& r3,
                                      uint32_t addr) {
    asm volatile("ldmatrix.sync.aligned.m8n8.x4.shared.b16 {%0,%1,%2,%3}, [%4];"
                 : "=r"(r0), "=r"(r1), "=r"(r2), "=r"(r3) : "r"(addr));
}
__device__ __forceinline__ void ldsm4t(uint32_t& r0, uint32_t& r1, uint32_t& r2, uint32_t& r3,
                                       uint32_t addr) {
    asm volatile("ldmatrix.sync.aligned.m8n8.x4.trans.shared.b16 {%0,%1,%2,%3}, [%4];"
                 : "=r"(r0), "=r"(r1), "=r"(r2), "=r"(r3) : "r"(addr));
}
__device__ __forceinline__ void cpa16(uint32_t s, const void* g) {
    asm volatile("cp.async.cg.shared.global [%0], [%1], 16;" :: "r"(s), "l"(g));
}
__device__ __forceinline__ void cp_commit() { asm volatile("cp.async.commit_group;"); }
template<int N> __device__ __forceinline__ void cp_wait() {
    asm volatile("cp.async.wait_group %0;" :: "n"(N));
}
__device__ __forceinline__ unsigned encf(float x) {
    unsigned b = __float_as_uint(x);
    return (b & 0x80000000u) ? ~b : (b | 0x80000000u);
}

__global__ void zero_kernel(float* p, int n) {
    int i = blockIdx.x * 256 + threadIdx.x;
    if (i < n) p[i] = 0.0f;
}
__global__ void f2h_kernel(__half* dst, const float* src, int n8) {
    int i = blockIdx.x * 256 + threadIdx.x;
    if (i < n8) {
        const float4 v0 = *(const float4*)&src[i * 8];
        const float4 v1 = *(const float4*)&src[i * 8 + 4];
        __half2 h[4];
        h[0] = __floats2half2_rn(v0.x, v0.y);
        h[1] = __floats2half2_rn(v0.z, v0.w);
        h[2] = __floats2half2_rn(v1.x, v1.y);
        h[3] = __floats2half2_rn(v1.z, v1.w);
        *(uint4*)&dst[i * 8] = *(uint4*)h;
    }
}
__global__ __launch_bounds__(256) void trrh_kernel(__half* dst, const float* src, int Kd, int Nd) {
    __shared__ float t[32][33];
    const int bx = blockIdx.x * 32;
    const int by = blockIdx.y * 32;
    const int tx = threadIdx.x, ty = threadIdx.y;
#pragma unroll
    for (int i = 0; i < 32; i += 8)
        t[ty + i][tx] = src[(size_t)(by + ty + i) * Nd + bx + tx];
    __syncthreads();
#pragma unroll
    for (int i = 0; i < 32; i += 8)
        dst[(size_t)(bx + ty + i) * Kd + by + tx] = __float2half_rn(t[tx][ty + i]);
}

// ---------------------------------------------------------------------------
// fp16 GEMM: 128x128 tile, BK=32, ldmatrix b16 + 3-stage cp.async,
// 1 barrier/iter, 2 CTAs/SM. (unchanged, R13)
// ---------------------------------------------------------------------------
#define GEMM_H_SMEM (2 * (3 * 128 * 40) * 2)

template<bool OUT0_HALF, bool OUT1_HALF, bool HASBIAS>
__global__ __launch_bounds__(256, 2) void gemm_h(
    const __half* __restrict__ A,
    const __half* __restrict__ Bt0, const __half* __restrict__ Bt1,
    const float* __restrict__ bias0, const float* __restrict__ bias1,
    void* __restrict__ C0, void* __restrict__ C1, int N)
{
    constexpr int KD = 2048, BK = 32, ASS = 40;
    constexpr int NIT = KD / BK;

    extern __shared__ __half smem_h[];
    __half* AsH = smem_h;
    __half* BsH = smem_h + 3 * 128 * ASS;

    const int tid = threadIdx.x;
    const int lane = tid & 31, w = tid >> 5;
    const int wm0 = (w & 1) * 64;
    const int wn0 = (w >> 1) * 32;
    const int bm = blockIdx.y * 128;
    const int bn = blockIdx.x * 128;

    const __half* Bt = (blockIdx.z == 0) ? Bt0 : Bt1;
    const float* bia = (blockIdx.z == 0) ? bias0 : bias1;

    const int cr = tid & 127;
    const int co = (tid >> 7) * 16;
    const uint32_t sA = (uint32_t)__cvta_generic_to_shared(AsH);
    const uint32_t sB = (uint32_t)__cvta_generic_to_shared(BsH);

    const int a_row = lane & 15;
    const int a_k8  = (lane >> 4) * 8;
    const int b_row = (lane & 7) + ((lane >> 3) & 1) * 8;
    const int b_k8  = (lane >> 4) * 8;

    float acc[4][4][4];
#pragma unroll
    for (int mi = 0; mi < 4; mi++)
#pragma unroll
        for (int nj = 0; nj < 4; nj++)
#pragma unroll
            for (int c = 0; c < 4; c++) acc[mi][nj][c] = 0.0f;

    auto issue = [&](int st, int k0) {
        const __half* ga = &A[(size_t)(bm + cr) * KD + k0 + co];
        uint32_t sa = sA + (uint32_t)((st * 128 + cr) * ASS + co) * 2u;
        cpa16(sa, ga); cpa16(sa + 16, ga + 8);
        const __half* gb = &Bt[(size_t)(bn + cr) * KD + k0 + co];
        uint32_t sb = sB + (uint32_t)((st * 128 + cr) * ASS + co) * 2u;
        cpa16(sb, gb); cpa16(sb + 16, gb + 8);
    };

    issue(0, 0);       cp_commit();
    issue(1, BK);      cp_commit();

    int st = 0;
    for (int it = 0; it < NIT; it++) {
        if (it + 1 < NIT) cp_wait<1>(); else cp_wait<0>();
        __syncthreads();
        const uint32_t aB = sA + (uint32_t)(st * 128 * ASS) * 2u;
        const uint32_t bB = sB + (uint32_t)(st * 128 * ASS) * 2u;

#pragma unroll
        for (int ks = 0; ks < 2; ks++) {
            const int kk = ks * 16;
            uint32_t af[4][4], bf[4][2];
#pragma unroll
            for (int mi = 0; mi < 4; mi++) {
                uint32_t ad = aB + (uint32_t)(((wm0 + 16 * mi + a_row) * ASS) + kk + a_k8) * 2u;
                ldsm4(af[mi][0], af[mi][1], af[mi][2], af[mi][3], ad);
            }
#pragma unroll
            for (int p = 0; p < 2; p++) {
                uint32_t bd = bB + (uint32_t)(((wn0 + 16 * p + b_row) * ASS) + kk + b_k8) * 2u;
                uint32_t r0, r1, r2, r3;
                ldsm4(r0, r1, r2, r3, bd);
                bf[2 * p][0] = r0; bf[2 * p][1] = r2;
                bf[2 * p + 1][0] = r1; bf[2 * p + 1][1] = r3;
            }
#pragma unroll
            for (int mi = 0; mi < 4; mi++)
#pragma unroll
                for (int nj = 0; nj < 4; nj++)
                    mma_f16(acc[mi][nj], af[mi], bf[nj]);
        }

        if (it + 2 < NIT) {
            issue((st + 2) % 3, (it + 2) * BK);
            cp_commit();
        }
        st = (st + 1) % 3;
    }

    const bool outHalf = (blockIdx.z == 0) ? OUT0_HALF : OUT1_HALF;
    void* C = (blockIdx.z == 0) ? C0 : C1;
#pragma unroll
    for (int mi = 0; mi < 4; mi++) {
#pragma unroll
        for (int nj = 0; nj < 4; nj++) {
            int row = bm + wm0 + 16 * mi + (lane >> 2);
            int col = bn + wn0 + 8 * nj + 2 * (lane & 3);
            float bx = 0.0f, by = 0.0f;
            if (HASBIAS) { bx = bia[col]; by = bia[col + 1]; }
            float v0x = acc[mi][nj][0] + bx, v0y = acc[mi][nj][1] + by;
            float v1x = acc[mi][nj][2] + bx, v1y = acc[mi][nj][3] + by;
            if (outHalf) {
                __half* Ch = (__half*)C;
                *(__half2*)&Ch[(size_t)row * N + col] = __floats2half2_rn(v0x, v0y);
                *(__half2*)&Ch[(size_t)(row + 8) * N + col] = __floats2half2_rn(v1x, v1y);
            } else {
                float* Cf = (float*)C;
                *(float2*)&Cf[(size_t)row * N + col] = make_float2(v0x, v0y);
                *(float2*)&Cf[(size_t)(row + 8) * N + col] = make_float2(v1x, v1y);
            }
        }
    }
}

// ---------------------------------------------------------------------------
// Scores (fp16): E = 2^(QK^T * scale * log2e) causal-masked, stored fp16;
// l-partials from ROUNDED values. (unchanged, R13)
// ---------------------------------------------------------------------------
#define SCORES_SMEM (2 * (3 * 128 * 40) * 2 + 128 * 4 * 4)

__global__ __launch_bounds__(256, 2) void scores_h() {
    constexpr int ASS = 40, BK = 32;
    const int nb = blockIdx.x, mb = blockIdx.y, h = blockIdx.z;
    if (nb > mb) return;
    const int kvh = h >> 2;

    extern __shared__ __half smem_h[];
    __half* AsH = smem_h;
    __half* BsH = smem_h + 3 * 128 * ASS;
    float* red = (float*)(smem_h + 2 * 3 * 128 * ASS);

    const int tid = threadIdx.x;
    const int lane = tid & 31, w = tid >> 5;
    const int wm0 = (w & 1) * 64;
    const int wn0 = (w >> 1) * 32;

    const int cr = tid & 127;
    const int co = (tid >> 7) * 16;
    const uint32_t sA = (uint32_t)__cvta_generic_to_shared(AsH);
    const uint32_t sB = (uint32_t)__cvta_generic_to_shared(BsH);

    const int a_row = lane & 15;
    const int a_k8  = (lane >> 4) * 8;
    const int b_row = (lane & 7) + ((lane >> 3) & 1) * 8;
    const int b_k8  = (lane >> 4) * 8;

    const __half* Qg = g_q + (size_t)(mb * 128) * DMODEL + h * HDIM;
    const __half* Kg = g_k + (size_t)(nb * 128) * KV_DM + kvh * HDIM;

    float acc[4][4][4];
#pragma unroll
    for (int mi = 0; mi < 4; mi++)
#pragma unroll
        for (int nj = 0; nj < 4; nj++)
#pragma unroll
            for (int c = 0; c < 4; c++) acc[mi][nj][c] = 0.0f;

    auto issue = [&](int st, int k0) {
        const __half* ga = &Qg[(size_t)cr * DMODEL + k0 + co];
        uint32_t sa = sA + (uint32_t)((st * 128 + cr) * ASS + co) * 2u;
        cpa16(sa, ga); cpa16(sa + 16, ga + 8);
        const __half* gb = &Kg[(size_t)cr * KV_DM + k0 + co];
        uint32_t sb = sB + (uint32_t)((st * 128 + cr) * ASS + co) * 2u;
        cpa16(sb, gb); cpa16(sb + 16, gb + 8);
    };

    issue(0, 0);      cp_commit();
    issue(1, BK);     cp_commit();

    constexpr int NIT = HDIM / BK;   // 4
    int st = 0;
    for (int it = 0; it < NIT; it++) {
        if (it + 1 < NIT) cp_wait<1>(); else cp_wait<0>();
        __syncthreads();
        const uint32_t aB = sA + (uint32_t)(st * 128 * ASS) * 2u;
        const uint32_t bB = sB + (uint32_t)(st * 128 * ASS) * 2u;
#pragma unroll
        for (int ks = 0; ks < 2; ks++) {
            const int kk = ks * 16;
            uint32_t af[4][4], bf[4][2];
#pragma unroll
            for (int mi = 0; mi < 4; mi++) {
                uint32_t ad = aB + (uint32_t)(((wm0 + 16 * mi + a_row) * ASS) + kk + a_k8) * 2u;
                ldsm4(af[mi][0], af[mi][1], af[mi][2], af[mi][3], ad);
            }
#pragma unroll
            for (int p = 0; p < 2; p++) {
                uint32_t bd = bB + (uint32_t)(((wn0 + 16 * p + b_row) * ASS) + kk + b_k8) * 2u;
                uint32_t r0, r1, r2, r3;
                ldsm4(r0, r1, r2, r3, bd);
                bf[2 * p][0] = r0; bf[2 * p][1] = r2;
                bf[2 * p + 1][0] = r1; bf[2 * p + 1][1] = r3;
            }
#pragma unroll
            for (int mi = 0; mi < 4; mi++)
#pragma unroll
                for (int nj = 0; nj < 4; nj++)
                    mma_f16(acc[mi][nj], af[mi], bf[nj]);
        }
        if (it + 2 < NIT) {
            issue((st + 2) % 3, (it + 2) * BK);
            cp_commit();
        }
        st = (st + 1) % 3;
    }

    const float SCL2 = 0.08838834764831845f * 1.4426950408889634f;
    __half* Eh = g_E + (size_t)h * S_LEN * S_LEN;
    float rs[4][2];
#pragma unroll
    for (int mi = 0; mi < 4; mi++) { rs[mi][0] = 0.f; rs[mi][1] = 0.f; }

#pragma unroll
    for (int mi = 0; mi < 4; mi++) {
#pragma unroll
        for (int nj = 0; nj < 4; nj++) {
            int row = mb * 128 + wm0 + 16 * mi + (lane >> 2);
            int col = nb * 128 + wn0 + 8 * nj + 2 * (lane & 3);
            float e0 = (col     <= row)     ? ex2f(acc[mi][nj][0] * SCL2) : 0.f;
            float e1 = (col + 1 <= row)     ? ex2f(acc[mi][nj][1] * SCL2) : 0.f;
            float e2 = (col     <= row + 8) ? ex2f(acc[mi][nj][2] * SCL2) : 0.f;
            float e3 = (col + 1 <= row + 8) ? ex2f(acc[mi][nj][3] * SCL2) : 0.f;
            __half2 h01 = __floats2half2_rn(e0, e1);
            __half2 h23 = __floats2half2_rn(e2, e3);
            *(__half2*)&Eh[(size_t)row * S_LEN + col] = h01;
            *(__half2*)&Eh[(size_t)(row + 8) * S_LEN + col] = h23;
            float2 f01 = __half22float2(h01);
            float2 f23 = __half22float2(h23);
            rs[mi][0] += f01.x + f01.y;
            rs[mi][1] += f23.x + f23.y;
        }
    }
#pragma unroll
    for (int mi = 0; mi < 4; mi++)
#pragma unroll
        for (int hh = 0; hh < 2; hh++) {
            rs[mi][hh] += __shfl_xor_sync(0xFFFFFFFFu, rs[mi][hh], 1);
            rs[mi][hh] += __shfl_xor_sync(0xFFFFFFFFu, rs[mi][hh], 2);
        }
    if ((lane & 3) == 0) {
        int wg = w >> 1;
#pragma unroll
        for (int mi = 0; mi < 4; mi++) {
            red[(wm0 + 16 * mi + (lane >> 2)) * 4 + wg]     = rs[mi][0];
            red[(wm0 + 16 * mi + 8 + (lane >> 2)) * 4 + wg] = rs[mi][1];
        }
    }
    __syncthreads();
    if (tid < 128)
        g_lpart[((size_t)h * S_LEN + mb * 128 + tid) * 16 + nb] =
            red[tid * 4] + red[tid * 4 + 1] + red[tid * 4 + 2] + red[tid * 4 + 3];
}

// ---------------------------------------------------------------------------
// Attention over E (fp16): R13 inner loop, now with triangle pairing —
// one CTA handles qt = 15-pair then qt = pair (34 tiles, balanced, 1 wave).
// ---------------------------------------------------------------------------
#define ESS 72
#define VSS 136
#define ATTN_SMEM (3 * 128 * ESS * 2 + 3 * 64 * VSS * 2 + 2 * 256 * 4 + 128 * 4)

__global__ __launch_bounds__(512, 1) void attn_pv() {
    extern __shared__ __half smh[];
    __half* Es = smh;                               // [3][128][72]
    __half* Vs = smh + 3 * 128 * ESS;               // [3][64][136]
    float* red = (float*)(smh + 3 * 128 * ESS + 3 * 64 * VSS);  // [2][256]
    float* il  = red + 2 * 256;                     // [128]

    const int pair = blockIdx.x;
    const int h  = blockIdx.y;
    const int kvh = h >> 2;
    const int tid = threadIdx.x;
    const int lane = tid & 31, w = tid >> 5;
    const int wm  = (w & 3) * 32;
    const int wn2 = (w >> 2) * 32;

    const int a_row = lane & 15;
    const int a_k8  = (lane >> 4) * 8;
    const uint32_t sET = (uint32_t)__cvta_generic_to_shared(Es);
    const uint32_t sVT = (uint32_t)__cvta_generic_to_shared(Vs);

    const __half* Eg = g_E + (size_t)h * S_LEN * S_LEN;
    const int prow = tid >> 2, pcb = (tid & 3) * 16;
    const int vr = tid >> 3, vcb = (tid & 7) * 16;

#pragma unroll 1
    for (int s = 0; s < 2; s++) {
        const int qt = (s == 0) ? 15 - pair : pair;
        const int qbase = qt * 128;
        const int nkt = 2 * qt + 2;

        auto issue = [&](int st, int kt) {
            const __half* ep = &Eg[(size_t)(qbase + prow) * S_LEN + kt * 64 + pcb];
            uint32_t se = sET + (uint32_t)((st * 128 + prow) * ESS + pcb) * 2u;
            cpa16(se, ep); cpa16(se + 16, ep + 8);
            const __half* vp = &g_v[(size_t)(kt * 64 + vr) * KV_DM + kvh * HDIM + vcb];
            uint32_t sv = sVT + (uint32_t)((st * 64 + vr) * VSS + vcb) * 2u;
            cpa16(sv, vp); cpa16(sv + 16, vp + 8);
        };

        issue(0, 0);  cp_commit();
        issue(1, 1);  cp_commit();   // nkt >= 2 always

        if (tid < 128) {
            const float* lp = &g_lpart[((size_t)h * S_LEN + qbase + tid) * 16];
            float l = 0.0f;
            for (int nb = 0; nb <= qt; nb++) l += lp[nb];
            il[tid] = 1.0f / l;
        }
        __syncthreads();

        float il0[2], il1[2];
#pragma unroll
        for (int mi = 0; mi < 2; mi++) {
            il0[mi] = il[wm + 16 * mi + (lane >> 2)];
            il1[mi] = il[wm + 16 * mi + 8 + (lane >> 2)];
        }

        float o[2][4][4];
#pragma unroll
        for (int mi = 0; mi < 2; mi++)
#pragma unroll
            for (int nj = 0; nj < 4; nj++)
#pragma unroll
                for (int c = 0; c < 4; c++) o[mi][nj][c] = 0.0f;

        float* cpart = &g_colpart[((size_t)h * NQT16 + qt) * S_LEN];

        int st = 0;
        for (int kt = 0; kt < nkt; kt++) {
            if (kt + 1 < nkt) cp_wait<1>(); else cp_wait<0>();
            __syncthreads();

            if (kt > 0 && tid < 64) {
                const float* rp = &red[((kt - 1) & 1) * 256 + tid * 4];
                cpart[(kt - 1) * 64 + tid] = rp[0] + rp[1] + rp[2] + rp[3];
            }

            if (kt + 2 < nkt) {
                issue((st + 2) % 3, kt + 2);
                cp_commit();
            }

            if (tid < 256) {
                int c = tid & 63, seg = tid >> 6;
                const __half* eb = &Es[(st * 128 + seg * 32) * ESS + c];
                float cs = 0.0f;
#pragma unroll 8
                for (int q = 0; q < 32; q++)
                    cs += __half2float(eb[q * ESS]) * il[seg * 32 + q];
                red[(kt & 1) * 256 + c * 4 + seg] = cs;
            }

            const uint32_t eB = sET + (uint32_t)(st * 128 * ESS) * 2u;
            const uint32_t vB = sVT + (uint32_t)(st * 64 * VSS) * 2u;
#pragma unroll
            for (int ks = 0; ks < 4; ks++) {
                const int kk = ks * 16;
                uint32_t af[2][4], bf[4][2];
#pragma unroll
                for (int mi = 0; mi < 2; mi++) {
                    uint32_t ad = eB + (uint32_t)(((wm + 16 * mi + a_row) * ESS) + kk + a_k8) * 2u;
                    ldsm4(af[mi][0], af[mi][1], af[mi][2], af[mi][3], ad);
#pragma unroll
                    for (int r = 0; r < 4; r++) {
                        float sc = (r & 1) ? il1[mi] : il0[mi];
                        __half2 hv = *(__half2*)&af[mi][r];
                        float2 f = __half22float2(hv);
                        __half2 ho = __floats2half2_rn(f.x * sc, f.y * sc);
                        af[mi][r] = *(uint32_t*)&ho;
                    }
                }
#pragma unroll
                for (int p = 0; p < 2; p++) {
                    uint32_t bd = vB + (uint32_t)(((kk + (lane & 15)) * VSS) + wn2 + p * 16 + (lane >> 4) * 8) * 2u;
                    uint32_t r0, r1, r2, r3;
                    ldsm4t(r0, r1, r2, r3, bd);
                    bf[2 * p][0] = r0; bf[2 * p][1] = r1;
                    bf[2 * p + 1][0] = r2; bf[2 * p + 1][1] = r3;
                }
#pragma unroll
                for (int mi = 0; mi < 2; mi++)
#pragma unroll
                    for (int nj = 0; nj < 4; nj++)
                        mma_f16(o[mi][nj], af[mi], bf[nj]);
            }
            st = (st + 1) % 3;
        }

        __syncthreads();
        if (tid < 64) {
            const float* rp = &red[((nkt - 1) & 1) * 256 + tid * 4];
            cpart[(nkt - 1) * 64 + tid] = rp[0] + rp[1] + rp[2] + rp[3];
        }

#pragma unroll
        for (int mi = 0; mi < 2; mi++)
#pragma unroll
            for (int nj = 0; nj < 4; nj++) {
                int row = qbase + wm + 16 * mi + (lane >> 2);
                int col = h * HDIM + wn2 + 8 * nj + 2 * (lane & 3);
                *(__half2*)&g_ctx[(size_t)row * DMODEL + col] =
                    __floats2half2_rn(o[mi][nj][0], o[mi][nj][1]);
                *(__half2*)&g_ctx[(size_t)(row + 8) * DMODEL + col] =
                    __floats2half2_rn(o[mi][nj][2], o[mi][nj][3]);
            }
        __syncthreads();   // all red/il reads done before next strip overwrites
    }
}

// ---------------------------------------------------------------------------
// Heavy-hitter mask via bitonic sort (exact jax.lax.top_k tie semantics).
// ---------------------------------------------------------------------------
__global__ __launch_bounds__(1024) void topk_kernel(float* __restrict__ mask_out) {
    const int h = blockIdx.x;
    const int tid = threadIdx.x;
    __shared__ unsigned long long keys[2048];

    for (int i = tid; i < 2048; i += 1024) {
        unsigned ev = 0u;
        if (i < SEL) {
            float s = 0.0f;
#pragma unroll
            for (int qt = 0; qt < NQT16; qt++)
                s += g_colpart[((size_t)h * NQT16 + qt) * S_LEN + i];
            ev = encf(s);
        }
        keys[i] = ((unsigned long long)ev << 32) | (unsigned)(2047 - i);
    }
    float* mrow = mask_out + (size_t)h * MASKW;
    for (int i = tid; i < MASKW; i += 1024)
        mrow[i] = (i >= (MASKW - RECENT)) ? 1.0f : 0.0f;
    __syncthreads();

    for (int k = 2; k <= 2048; k <<= 1) {
        for (int j = k >> 1; j > 0; j >>= 1) {
            for (int idx = tid; idx < 2048; idx += 1024) {
                int ixj = idx ^ j;
                if (ixj > idx) {
                    unsigned long long a = keys[idx], b = keys[ixj];
                    bool up = (idx & k) == 0;
                    if (up ? (a > b) : (a < b)) { keys[idx] = b; keys[ixj] = a; }
                }
            }
            __syncthreads();
        }
    }
    for (int i = 2048 - HEAVY + tid; i < 2048; i += 1024) {
        int idx = 2047 - (int)(keys[i] & 0xFFFFFFFFu);
        mrow[idx] = 1.0f;
    }
}

// ---------------------------------------------------------------------------
extern "C" void kernel_launch(void* const* d_in, const int* in_sizes, int n_in,
                              void* d_out, int out_size) {
    (void)in_sizes; (void)n_in; (void)out_size;
    const float* hidden = (const float*)d_in[0];
    const float* q_w = (const float*)d_in[1];
    const float* q_b = (const float*)d_in[2];
    const float* k_w = (const float*)d_in[3];
    const float* k_b = (const float*)d_in[4];
    const float* v_w = (const float*)d_in[5];
    const float* v_b = (const float*)d_in[6];
    const float* o_w = (const float*)d_in[7];
    float* out = (float*)d_out;

    static bool init = false;
    static cudaStream_t sA, sB, sC;
    static cudaEvent_t evRoot, evHid, evKV, evZero, evAttn, evTrrO, evTrrQ, evDoneA, evDoneC;
    if (!init) {
        cudaFuncSetAttribute(attn_pv, cudaFuncAttributeMaxDynamicSharedMemorySize, ATTN_SMEM);
        cudaFuncSetAttribute(gemm_h<true, false, true>,
                             cudaFuncAttributeMaxDynamicSharedMemorySize, GEMM_H_SMEM);
        cudaFuncSetAttribute(gemm_h<true, true, true>,
                             cudaFuncAttributeMaxDynamicSharedMemorySize, GEMM_H_SMEM);
        cudaFuncSetAttribute(gemm_h<false, false, false>,
                             cudaFuncAttributeMaxDynamicSharedMemorySize, GEMM_H_SMEM);
        cudaFuncSetAttribute(scores_h,
                             cudaFuncAttributeMaxDynamicSharedMemorySize, SCORES_SMEM);
        cudaStreamCreateWithFlags(&sA, cudaStreamNonBlocking);
        cudaStreamCreateWithFlags(&sB, cudaStreamNonBlocking);
        cudaStreamCreateWithFlags(&sC, cudaStreamNonBlocking);
        cudaEventCreateWithFlags(&evRoot, cudaEventDisableTiming);
        cudaEventCreateWithFlags(&evHid,  cudaEventDisableTiming);
        cudaEventCreateWithFlags(&evKV,   cudaEventDisableTiming);
        cudaEventCreateWithFlags(&evZero, cudaEventDisableTiming);
        cudaEventCreateWithFlags(&evAttn, cudaEventDisableTiming);
        cudaEventCreateWithFlags(&evTrrO, cudaEventDisableTiming);
        cudaEventCreateWithFlags(&evTrrQ, cudaEventDisableTiming);
        cudaEventCreateWithFlags(&evDoneA, cudaEventDisableTiming);
        cudaEventCreateWithFlags(&evDoneC, cudaEventDisableTiming);
        init = true;
    }

    __half *ghid, *gqwT, *gkwT, *gvwT, *gowT, *gq, *gk, *gv, *gctx;
    float *gcp;
    cudaGetSymbolAddress((void**)&ghid, g_hid);
    cudaGetSymbolAddress((void**)&gqwT, g_qwT);
    cudaGetSymbolAddress((void**)&gkwT, g_kwT);
    cudaGetSymbolAddress((void**)&gvwT, g_vwT);
    cudaGetSymbolAddress((void**)&gowT, g_owT);
    cudaGetSymbolAddress((void**)&gq,   g_q);
    cudaGetSymbolAddress((void**)&gk,   g_k);
    cudaGetSymbolAddress((void**)&gv,   g_v);
    cudaGetSymbolAddress((void**)&gctx, g_ctx);
    cudaGetSymbolAddress((void**)&gcp,  g_colpart);

    cudaEventRecord(evRoot, 0);
    cudaStreamWaitEvent(sA, evRoot, 0);
    cudaStreamWaitEvent(sB, evRoot, 0);
    cudaStreamWaitEvent(sC, evRoot, 0);

    dim3 tb(32, 8);
    f2h_kernel<<<(S_LEN * DMODEL / 8 + 255) / 256, 256, 0, sA>>>(
        ghid, hidden, S_LEN * DMODEL / 8);
    cudaEventRecord(evHid, sA);
    trrh_kernel<<<dim3(DMODEL / 32, DMODEL / 32), tb, 0, sC>>>(gqwT, q_w, DMODEL, DMODEL);
    cudaEventRecord(evTrrQ, sC);
    trrh_kernel<<<dim3(KV_DM / 32, DMODEL / 32), tb, 0, sB>>>(gkwT, k_w, DMODEL, KV_DM);
    trrh_kernel<<<dim3(KV_DM / 32, DMODEL / 32), tb, 0, sB>>>(gvwT, v_w, DMODEL, KV_DM);
    trrh_kernel<<<dim3(DMODEL / 32, DMODEL / 32), tb, 0, sC>>>(gowT, o_w, DMODEL, DMODEL);
    cudaEventRecord(evTrrO, sC);

    cudaStreamWaitEvent(sA, evTrrQ, 0);
    gemm_h<true, false, true><<<dim3(DMODEL / 128, S_LEN / 128, 1), 256, GEMM_H_SMEM, sA>>>(
        ghid, gqwT, nullptr, q_b, nullptr, gq, nullptr, DMODEL);

    cudaStreamWaitEvent(sB, evHid, 0);
    gemm_h<true, true, true><<<dim3(KV_DM / 128, S_LEN / 128, 2), 256, GEMM_H_SMEM, sB>>>(
        ghid, gkwT, gvwT, k_b, v_b, gk, gv, KV_DM);
    cudaEventRecord(evKV, sB);

    const int ncp = NH * NQT16 * S_LEN;
    zero_kernel<<<(ncp + 255) / 256, 256, 0, sC>>>(gcp, ncp);
    cudaEventRecord(evZero, sC);

    cudaStreamWaitEvent(sA, evKV, 0);
    scores_h<<<dim3(16, 16, NH), 256, SCORES_SMEM, sA>>>();

    cudaStreamWaitEvent(sA, evZero, 0);
    attn_pv<<<dim3(8, NH), 512, ATTN_SMEM, sA>>>();
    cudaEventRecord(evAttn, sA);

    cudaStreamWaitEvent(sC, evAttn, 0);
    topk_kernel<<<NH, 1024, 0, sC>>>(out + (size_t)S_LEN * DMODEL);
    cudaEventRecord(evDoneC, sC);

    cudaStreamWaitEvent(sA, evTrrO, 0);
    gemm_h<false, false, false><<<dim3(DMODEL / 128, S_LEN / 128, 1), 256, GEMM_H_SMEM, sA>>>(
        gctx, gowT, nullptr, nullptr, nullptr, out, nullptr, DMODEL);
    cudaEventRecord(evDoneA, sA);

    cudaStreamWaitEvent(0, evDoneA, 0);
    cudaStreamWaitEvent(0, evDoneC, 0);
}

// round 16
// speedup vs baseline: 1.9725x; 1.0025x over previous
#include <cuda_runtime.h>
#include <cuda_fp16.h>
#include <cstdint>
#include <cmath>

#define S_LEN   2048
#define DMODEL  2048
#define NH      16
#define HDIM    128
#define KV_DM   512
#define NQT16   16
#define HEAVY   204
#define RECENT  204
#define SEL     (S_LEN - RECENT)    // 1844
#define MASKW   (S_LEN + 1)         // 2049

__device__ __half g_hid[S_LEN * DMODEL];
__device__ __half g_qwT[DMODEL * DMODEL];   // [n][k]
__device__ __half g_kwT[KV_DM * DMODEL];
__device__ __half g_vwT[KV_DM * DMODEL];
__device__ __half g_owT[DMODEL * DMODEL];
__device__ __half g_q[S_LEN * DMODEL];
__device__ __half g_k[S_LEN * KV_DM];
__device__ __half g_v[S_LEN * KV_DM];
__device__ __half g_ctx[S_LEN * DMODEL];
__device__ float  g_colpart[NH * NQT16 * S_LEN];
__device__ float  g_lpart[NH * S_LEN * 16];
__device__ __half g_E[(size_t)NH * S_LEN * S_LEN];   // exp'd scores, fp16

// ---------------------------------------------------------------------------
__device__ __forceinline__ float ex2f(float x) {
    float y;
    asm("ex2.approx.ftz.f32 %0, %1;" : "=f"(y) : "f"(x));
    return y;
}
__device__ __forceinline__ void mma_f16(float* c, const uint32_t* a, const uint32_t* b) {
    asm volatile(
        "mma.sync.aligned.m16n8k16.row.col.f32.f16.f16.f32 "
        "{%0,%1,%2,%3}, {%4,%5,%6,%7}, {%8,%9}, {%0,%1,%2,%3};"
        : "+f"(c[0]), "+f"(c[1]), "+f"(c[2]), "+f"(c[3])
        : "r"(a[0]), "r"(a[1]), "r"(a[2]), "r"(a[3]), "r"(b[0]), "r"(b[1]));
}
__device__ __forceinline__ void ldsm4(uint32_t& r0, uint32_t& r1, uint32_t& r2, uint32_t& r3,
                                      uint32_t addr) {
    asm volatile("ldmatrix.sync.aligned.m8n8.x4.shared.b16 {%0,%1,%2,%3}, [%4];"
                 : "=r"(r0), "=r"(r1), "=r"(r2), "=r"(r3) : "r"(addr));
}
__device__ __forceinline__ void ldsm4t(uint32_t& r0, uint32_t& r1, uint32_t& r2, uint32_t& r3,
                                       uint32_t addr) {
    asm volatile("ldmatrix.sync.aligned.m8n8.x4.trans.shared.b16 {%0,%1,%2,%3}, [%4];"
                 : "=r"(r0), "=r"(r1), "=r"(r2), "=r"(r3) : "r"(addr));
}
__device__ __forceinline__ void cpa16(uint32_t s, const void* g) {
    asm volatile("cp.async.cg.shared.global [%0], [%1], 16;" :: "r"(s), "l"(g));
}
__device__ __forceinline__ void cp_commit() { asm volatile("cp.async.commit_group;"); }
template<int N> __device__ __forceinline__ void cp_wait() {
    asm volatile("cp.async.wait_group %0;" :: "n"(N));
}
__device__ __forceinline__ unsigned encf(float x) {
    unsigned b = __float_as_uint(x);
    return (b & 0x80000000u) ? ~b : (b | 0x80000000u);
}

__global__ void zero_kernel(float* p, int n) {
    int i = blockIdx.x * 256 + threadIdx.x;
    if (i < n) p[i] = 0.0f;
}
__global__ void f2h_kernel(__half* dst, const float* src, int n8) {
    int i = blockIdx.x * 256 + threadIdx.x;
    if (i < n8) {
        const float4 v0 = *(const float4*)&src[i * 8];
        const float4 v1 = *(const float4*)&src[i * 8 + 4];
        __half2 h[4];
        h[0] = __floats2half2_rn(v0.x, v0.y);
        h[1] = __floats2half2_rn(v0.z, v0.w);
        h[2] = __floats2half2_rn(v1.x, v1.y);
        h[3] = __floats2half2_rn(v1.z, v1.w);
        *(uint4*)&dst[i * 8] = *(uint4*)h;
    }
}
__global__ __launch_bounds__(256) void trrh_kernel(__half* dst, const float* src, int Kd, int Nd) {
    __shared__ float t[32][33];
    const int bx = blockIdx.x * 32;
    const int by = blockIdx.y * 32;
    const int tx = threadIdx.x, ty = threadIdx.y;
#pragma unroll
    for (int i = 0; i < 32; i += 8)
        t[ty + i][tx] = src[(size_t)(by + ty + i) * Nd + bx + tx];
    __syncthreads();
#pragma unroll
    for (int i = 0; i < 32; i += 8)
        dst[(size_t)(bx + ty + i) * Kd + by + tx] = __float2half_rn(t[tx][ty + i]);
}

// ---------------------------------------------------------------------------
// fp16 GEMM: 128x128 tile, BK=32, ldmatrix b16 + 3-stage cp.async,
// 1 barrier/iter, 2 CTAs/SM. (unchanged)
// ---------------------------------------------------------------------------
#define GEMM_H_SMEM (2 * (3 * 128 * 40) * 2)

template<bool OUT0_HALF, bool OUT1_HALF, bool HASBIAS>
__global__ __launch_bounds__(256, 2) void gemm_h(
    const __half* __restrict__ A,
    const __half* __restrict__ Bt0, const __half* __restrict__ Bt1,
    const float* __restrict__ bias0, const float* __restrict__ bias1,
    void* __restrict__ C0, void* __restrict__ C1, int N)
{
    constexpr int KD = 2048, BK = 32, ASS = 40;
    constexpr int NIT = KD / BK;

    extern __shared__ __half smem_h[];
    __half* AsH = smem_h;
    __half* BsH = smem_h + 3 * 128 * ASS;

    const int tid = threadIdx.x;
    const int lane = tid & 31, w = tid >> 5;
    const int wm0 = (w & 1) * 64;
    const int wn0 = (w >> 1) * 32;
    const int bm = blockIdx.y * 128;
    const int bn = blockIdx.x * 128;

    const __half* Bt = (blockIdx.z == 0) ? Bt0 : Bt1;
    const float* bia = (blockIdx.z == 0) ? bias0 : bias1;

    const int cr = tid & 127;
    const int co = (tid >> 7) * 16;
    const uint32_t sA = (uint32_t)__cvta_generic_to_shared(AsH);
    const uint32_t sB = (uint32_t)__cvta_generic_to_shared(BsH);

    const int a_row = lane & 15;
    const int a_k8  = (lane >> 4) * 8;
    const int b_row = (lane & 7) + ((lane >> 3) & 1) * 8;
    const int b_k8  = (lane >> 4) * 8;

    float acc[4][4][4];
#pragma unroll
    for (int mi = 0; mi < 4; mi++)
#pragma unroll
        for (int nj = 0; nj < 4; nj++)
#pragma unroll
            for (int c = 0; c < 4; c++) acc[mi][nj][c] = 0.0f;

    auto issue = [&](int st, int k0) {
        const __half* ga = &A[(size_t)(bm + cr) * KD + k0 + co];
        uint32_t sa = sA + (uint32_t)((st * 128 + cr) * ASS + co) * 2u;
        cpa16(sa, ga); cpa16(sa + 16, ga + 8);
        const __half* gb = &Bt[(size_t)(bn + cr) * KD + k0 + co];
        uint32_t sb = sB + (uint32_t)((st * 128 + cr) * ASS + co) * 2u;
        cpa16(sb, gb); cpa16(sb + 16, gb + 8);
    };

    issue(0, 0);       cp_commit();
    issue(1, BK);      cp_commit();

    int st = 0;
    for (int it = 0; it < NIT; it++) {
        if (it + 1 < NIT) cp_wait<1>(); else cp_wait<0>();
        __syncthreads();
        const uint32_t aB = sA + (uint32_t)(st * 128 * ASS) * 2u;
        const uint32_t bB = sB + (uint32_t)(st * 128 * ASS) * 2u;

#pragma unroll
        for (int ks = 0; ks < 2; ks++) {
            const int kk = ks * 16;
            uint32_t af[4][4], bf[4][2];
#pragma unroll
            for (int mi = 0; mi < 4; mi++) {
                uint32_t ad = aB + (uint32_t)(((wm0 + 16 * mi + a_row) * ASS) + kk + a_k8) * 2u;
                ldsm4(af[mi][0], af[mi][1], af[mi][2], af[mi][3], ad);
            }
#pragma unroll
            for (int p = 0; p < 2; p++) {
                uint32_t bd = bB + (uint32_t)(((wn0 + 16 * p + b_row) * ASS) + kk + b_k8) * 2u;
                uint32_t r0, r1, r2, r3;
                ldsm4(r0, r1, r2, r3, bd);
                bf[2 * p][0] = r0; bf[2 * p][1] = r2;
                bf[2 * p + 1][0] = r1; bf[2 * p + 1][1] = r3;
            }
#pragma unroll
            for (int mi = 0; mi < 4; mi++)
#pragma unroll
                for (int nj = 0; nj < 4; nj++)
                    mma_f16(acc[mi][nj], af[mi], bf[nj]);
        }

        if (it + 2 < NIT) {
            issue((st + 2) % 3, (it + 2) * BK);
            cp_commit();
        }
        st = (st + 1) % 3;
    }

    const bool outHalf = (blockIdx.z == 0) ? OUT0_HALF : OUT1_HALF;
    void* C = (blockIdx.z == 0) ? C0 : C1;
#pragma unroll
    for (int mi = 0; mi < 4; mi++) {
#pragma unroll
        for (int nj = 0; nj < 4; nj++) {
            int row = bm + wm0 + 16 * mi + (lane >> 2);
            int col = bn + wn0 + 8 * nj + 2 * (lane & 3);
            float bx = 0.0f, by = 0.0f;
            if (HASBIAS) { bx = bia[col]; by = bia[col + 1]; }
            float v0x = acc[mi][nj][0] + bx, v0y = acc[mi][nj][1] + by;
            float v1x = acc[mi][nj][2] + bx, v1y = acc[mi][nj][3] + by;
            if (outHalf) {
                __half* Ch = (__half*)C;
                *(__half2*)&Ch[(size_t)row * N + col] = __floats2half2_rn(v0x, v0y);
                *(__half2*)&Ch[(size_t)(row + 8) * N + col] = __floats2half2_rn(v1x, v1y);
            } else {
                float* Cf = (float*)C;
                *(float2*)&Cf[(size_t)row * N + col] = make_float2(v0x, v0y);
                *(float2*)&Cf[(size_t)(row + 8) * N + col] = make_float2(v1x, v1y);
            }
        }
    }
}

// ---------------------------------------------------------------------------
// Scores (fp16): lower-triangle enumeration — grid.x = 136 live (mb,nb) tiles,
// no dead CTAs. Body identical to R15.
// ---------------------------------------------------------------------------
#define SCORES_SMEM (2 * (3 * 128 * 40) * 2 + 128 * 4 * 4)

__global__ __launch_bounds__(256, 2) void scores_h() {
    constexpr int ASS = 40, BK = 32;
    // un-triangularize: t -> (mb, nb) with nb <= mb
    const int t = blockIdx.x;
    int mb = (int)((sqrtf(8.0f * (float)t + 1.0f) - 1.0f) * 0.5f);
    while ((mb + 1) * (mb + 2) / 2 <= t) mb++;
    while (mb * (mb + 1) / 2 > t) mb--;
    const int nb = t - mb * (mb + 1) / 2;
    const int h = blockIdx.z;
    const int kvh = h >> 2;

    extern __shared__ __half smem_h[];
    __half* AsH = smem_h;
    __half* BsH = smem_h + 3 * 128 * ASS;
    float* red = (float*)(smem_h + 2 * 3 * 128 * ASS);

    const int tid = threadIdx.x;
    const int lane = tid & 31, w = tid >> 5;
    const int wm0 = (w & 1) * 64;
    const int wn0 = (w >> 1) * 32;

    const int cr = tid & 127;
    const int co = (tid >> 7) * 16;
    const uint32_t sA = (uint32_t)__cvta_generic_to_shared(AsH);
    const uint32_t sB = (uint32_t)__cvta_generic_to_shared(BsH);

    const int a_row = lane & 15;
    const int a_k8  = (lane >> 4) * 8;
    const int b_row = (lane & 7) + ((lane >> 3) & 1) * 8;
    const int b_k8  = (lane >> 4) * 8;

    const __half* Qg = g_q + (size_t)(mb * 128) * DMODEL + h * HDIM;
    const __half* Kg = g_k + (size_t)(nb * 128) * KV_DM + kvh * HDIM;

    float acc[4][4][4];
#pragma unroll
    for (int mi = 0; mi < 4; mi++)
#pragma unroll
        for (int nj = 0; nj < 4; nj++)
#pragma unroll
            for (int c = 0; c < 4; c++) acc[mi][nj][c] = 0.0f;

    auto issue = [&](int st, int k0) {
        const __half* ga = &Qg[(size_t)cr * DMODEL + k0 + co];
        uint32_t sa = sA + (uint32_t)((st * 128 + cr) * ASS + co) * 2u;
        cpa16(sa, ga); cpa16(sa + 16, ga + 8);
        const __half* gb = &Kg[(size_t)cr * KV_DM + k0 + co];
        uint32_t sb = sB + (uint32_t)((st * 128 + cr) * ASS + co) * 2u;
        cpa16(sb, gb); cpa16(sb + 16, gb + 8);
    };

    issue(0, 0);      cp_commit();
    issue(1, BK);     cp_commit();

    constexpr int NIT = HDIM / BK;   // 4
    int st = 0;
    for (int it = 0; it < NIT; it++) {
        if (it + 1 < NIT) cp_wait<1>(); else cp_wait<0>();
        __syncthreads();
        const uint32_t aB = sA + (uint32_t)(st * 128 * ASS) * 2u;
        const uint32_t bB = sB + (uint32_t)(st * 128 * ASS) * 2u;
#pragma unroll
        for (int ks = 0; ks < 2; ks++) {
            const int kk = ks * 16;
            uint32_t af[4][4], bf[4][2];
#pragma unroll
            for (int mi = 0; mi < 4; mi++) {
                uint32_t ad = aB + (uint32_t)(((wm0 + 16 * mi + a_row) * ASS) + kk + a_k8) * 2u;
                ldsm4(af[mi][0], af[mi][1], af[mi][2], af[mi][3], ad);
            }
#pragma unroll
            for (int p = 0; p < 2; p++) {
                uint32_t bd = bB + (uint32_t)(((wn0 + 16 * p + b_row) * ASS) + kk + b_k8) * 2u;
                uint32_t r0, r1, r2, r3;
                ldsm4(r0, r1, r2, r3, bd);
                bf[2 * p][0] = r0; bf[2 * p][1] = r2;
                bf[2 * p + 1][0] = r1; bf[2 * p + 1][1] = r3;
            }
#pragma unroll
            for (int mi = 0; mi < 4; mi++)
#pragma unroll
                for (int nj = 0; nj < 4; nj++)
                    mma_f16(acc[mi][nj], af[mi], bf[nj]);
        }
        if (it + 2 < NIT) {
            issue((st + 2) % 3, (it + 2) * BK);
            cp_commit();
        }
        st = (st + 1) % 3;
    }

    const float SCL2 = 0.08838834764831845f * 1.4426950408889634f;
    __half* Eh = g_E + (size_t)h * S_LEN * S_LEN;
    float rs[4][2];
#pragma unroll
    for (int mi = 0; mi < 4; mi++) { rs[mi][0] = 0.f; rs[mi][1] = 0.f; }

#pragma unroll
    for (int mi = 0; mi < 4; mi++) {
#pragma unroll
        for (int nj = 0; nj < 4; nj++) {
            int row = mb * 128 + wm0 + 16 * mi + (lane >> 2);
            int col = nb * 128 + wn0 + 8 * nj + 2 * (lane & 3);
            float e0 = (col     <= row)     ? ex2f(acc[mi][nj][0] * SCL2) : 0.f;
            float e1 = (col + 1 <= row)     ? ex2f(acc[mi][nj][1] * SCL2) : 0.f;
            float e2 = (col     <= row + 8) ? ex2f(acc[mi][nj][2] * SCL2) : 0.f;
            float e3 = (col + 1 <= row + 8) ? ex2f(acc[mi][nj][3] * SCL2) : 0.f;
            __half2 h01 = __floats2half2_rn(e0, e1);
            __half2 h23 = __floats2half2_rn(e2, e3);
            *(__half2*)&Eh[(size_t)row * S_LEN + col] = h01;
            *(__half2*)&Eh[(size_t)(row + 8) * S_LEN + col] = h23;
            float2 f01 = __half22float2(h01);
            float2 f23 = __half22float2(h23);
            rs[mi][0] += f01.x + f01.y;
            rs[mi][1] += f23.x + f23.y;
        }
    }
#pragma unroll
    for (int mi = 0; mi < 4; mi++)
#pragma unroll
        for (int hh = 0; hh < 2; hh++) {
            rs[mi][hh] += __shfl_xor_sync(0xFFFFFFFFu, rs[mi][hh], 1);
            rs[mi][hh] += __shfl_xor_sync(0xFFFFFFFFu, rs[mi][hh], 2);
        }
    if ((lane & 3) == 0) {
        int wg = w >> 1;
#pragma unroll
        for (int mi = 0; mi < 4; mi++) {
            red[(wm0 + 16 * mi + (lane >> 2)) * 4 + wg]     = rs[mi][0];
            red[(wm0 + 16 * mi + 8 + (lane >> 2)) * 4 + wg] = rs[mi][1];
        }
    }
    __syncthreads();
    if (tid < 128)
        g_lpart[((size_t)h * S_LEN + mb * 128 + tid) * 16 + nb] =
            red[tid * 4] + red[tid * 4 + 1] + red[tid * 4 + 2] + red[tid * 4 + 3];
}

// ---------------------------------------------------------------------------
// Attention over E (fp16): triangle-paired strips. (unchanged, R15)
// ---------------------------------------------------------------------------
#define ESS 72
#define VSS 136
#define ATTN_SMEM (3 * 128 * ESS * 2 + 3 * 64 * VSS * 2 + 2 * 256 * 4 + 128 * 4)

__global__ __launch_bounds__(512, 1) void attn_pv() {
    extern __shared__ __half smh[];
    __half* Es = smh;                               // [3][128][72]
    __half* Vs = smh + 3 * 128 * ESS;               // [3][64][136]
    float* red = (float*)(smh + 3 * 128 * ESS + 3 * 64 * VSS);  // [2][256]
    float* il  = red + 2 * 256;                     // [128]

    const int pair = blockIdx.x;
    const int h  = blockIdx.y;
    const int kvh = h >> 2;
    const int tid = threadIdx.x;
    const int lane = tid & 31, w = tid >> 5;
    const int wm  = (w & 3) * 32;
    const int wn2 = (w >> 2) * 32;

    const int a_row = lane & 15;
    const int a_k8  = (lane >> 4) * 8;
    const uint32_t sET = (uint32_t)__cvta_generic_to_shared(Es);
    const uint32_t sVT = (uint32_t)__cvta_generic_to_shared(Vs);

    const __half* Eg = g_E + (size_t)h * S_LEN * S_LEN;
    const int prow = tid >> 2, pcb = (tid & 3) * 16;
    const int vr = tid >> 3, vcb = (tid & 7) * 16;

#pragma unroll 1
    for (int s = 0; s < 2; s++) {
        const int qt = (s == 0) ? 15 - pair : pair;
        const int qbase = qt * 128;
        const int nkt = 2 * qt + 2;

        auto issue = [&](int st, int kt) {
            const __half* ep = &Eg[(size_t)(qbase + prow) * S_LEN + kt * 64 + pcb];
            uint32_t se = sET + (uint32_t)((st * 128 + prow) * ESS + pcb) * 2u;
            cpa16(se, ep); cpa16(se + 16, ep + 8);
            const __half* vp = &g_v[(size_t)(kt * 64 + vr) * KV_DM + kvh * HDIM + vcb];
            uint32_t sv = sVT + (uint32_t)((st * 64 + vr) * VSS + vcb) * 2u;
            cpa16(sv, vp); cpa16(sv + 16, vp + 8);
        };

        issue(0, 0);  cp_commit();
        issue(1, 1);  cp_commit();   // nkt >= 2 always

        if (tid < 128) {
            const float* lp = &g_lpart[((size_t)h * S_LEN + qbase + tid) * 16];
            float l = 0.0f;
            for (int nb = 0; nb <= qt; nb++) l += lp[nb];
            il[tid] = 1.0f / l;
        }
        __syncthreads();

        float il0[2], il1[2];
#pragma unroll
        for (int mi = 0; mi < 2; mi++) {
            il0[mi] = il[wm + 16 * mi + (lane >> 2)];
            il1[mi] = il[wm + 16 * mi + 8 + (lane >> 2)];
        }

        float o[2][4][4];
#pragma unroll
        for (int mi = 0; mi < 2; mi++)
#pragma unroll
            for (int nj = 0; nj < 4; nj++)
#pragma unroll
                for (int c = 0; c < 4; c++) o[mi][nj][c] = 0.0f;

        float* cpart = &g_colpart[((size_t)h * NQT16 + qt) * S_LEN];

        int st = 0;
        for (int kt = 0; kt < nkt; kt++) {
            if (kt + 1 < nkt) cp_wait<1>(); else cp_wait<0>();
            __syncthreads();

            if (kt > 0 && tid < 64) {
                const float* rp = &red[((kt - 1) & 1) * 256 + tid * 4];
                cpart[(kt - 1) * 64 + tid] = rp[0] + rp[1] + rp[2] + rp[3];
            }

            if (kt + 2 < nkt) {
                issue((st + 2) % 3, kt + 2);
                cp_commit();
            }

            if (tid < 256) {
                int c = tid & 63, seg = tid >> 6;
                const __half* eb = &Es[(st * 128 + seg * 32) * ESS + c];
                float cs = 0.0f;
#pragma unroll 8
                for (int q = 0; q < 32; q++)
                    cs += __half2float(eb[q * ESS]) * il[seg * 32 + q];
                red[(kt & 1) * 256 + c * 4 + seg] = cs;
            }

            const uint32_t eB = sET + (uint32_t)(st * 128 * ESS) * 2u;
            const uint32_t vB = sVT + (uint32_t)(st * 64 * VSS) * 2u;
#pragma unroll
            for (int ks = 0; ks < 4; ks++) {
                const int kk = ks * 16;
                uint32_t af[2][4], bf[4][2];
#pragma unroll
                for (int mi = 0; mi < 2; mi++) {
                    uint32_t ad = eB + (uint32_t)(((wm + 16 * mi + a_row) * ESS) + kk + a_k8) * 2u;
                    ldsm4(af[mi][0], af[mi][1], af[mi][2], af[mi][3], ad);
#pragma unroll
                    for (int r = 0; r < 4; r++) {
                        float sc = (r & 1) ? il1[mi] : il0[mi];
                        __half2 hv = *(__half2*)&af[mi][r];
                        float2 f = __half22float2(hv);
                        __half2 ho = __floats2half2_rn(f.x * sc, f.y * sc);
                        af[mi][r] = *(uint32_t*)&ho;
                    }
                }
#pragma unroll
                for (int p = 0; p < 2; p++) {
                    uint32_t bd = vB + (uint32_t)(((kk + (lane & 15)) * VSS) + wn2 + p * 16 + (lane >> 4) * 8) * 2u;
                    uint32_t r0, r1, r2, r3;
                    ldsm4t(r0, r1, r2, r3, bd);
                    bf[2 * p][0] = r0; bf[2 * p][1] = r1;
                    bf[2 * p + 1][0] = r2; bf[2 * p + 1][1] = r3;
                }
#pragma unroll
                for (int mi = 0; mi < 2; mi++)
#pragma unroll
                    for (int nj = 0; nj < 4; nj++)
                        mma_f16(o[mi][nj], af[mi], bf[nj]);
            }
            st = (st + 1) % 3;
        }

        __syncthreads();
        if (tid < 64) {
            const float* rp = &red[((nkt - 1) & 1) * 256 + tid * 4];
            cpart[(nkt - 1) * 64 + tid] = rp[0] + rp[1] + rp[2] + rp[3];
        }

#pragma unroll
        for (int mi = 0; mi < 2; mi++)
#pragma unroll
            for (int nj = 0; nj < 4; nj++) {
                int row = qbase + wm + 16 * mi + (lane >> 2);
                int col = h * HDIM + wn2 + 8 * nj + 2 * (lane & 3);
                *(__half2*)&g_ctx[(size_t)row * DMODEL + col] =
                    __floats2half2_rn(o[mi][nj][0], o[mi][nj][1]);
                *(__half2*)&g_ctx[(size_t)(row + 8) * DMODEL + col] =
                    __floats2half2_rn(o[mi][nj][2], o[mi][nj][3]);
            }
        __syncthreads();   // all red/il reads done before next strip overwrites
    }
}

// ---------------------------------------------------------------------------
// Heavy-hitter mask via bitonic sort (exact jax.lax.top_k tie semantics).
// ---------------------------------------------------------------------------
__global__ __launch_bounds__(1024) void topk_kernel(float* __restrict__ mask_out) {
    const int h = blockIdx.x;
    const int tid = threadIdx.x;
    __shared__ unsigned long long keys[2048];

    for (int i = tid; i < 2048; i += 1024) {
        unsigned ev = 0u;
        if (i < SEL) {
            float s = 0.0f;
#pragma unroll
            for (int qt = 0; qt < NQT16; qt++)
                s += g_colpart[((size_t)h * NQT16 + qt) * S_LEN + i];
            ev = encf(s);
        }
        keys[i] = ((unsigned long long)ev << 32) | (unsigned)(2047 - i);
    }
    float* mrow = mask_out + (size_t)h * MASKW;
    for (int i = tid; i < MASKW; i += 1024)
        mrow[i] = (i >= (MASKW - RECENT)) ? 1.0f : 0.0f;
    __syncthreads();

    for (int k = 2; k <= 2048; k <<= 1) {
        for (int j = k >> 1; j > 0; j >>= 1) {
            for (int idx = tid; idx < 2048; idx += 1024) {
                int ixj = idx ^ j;
                if (ixj > idx) {
                    unsigned long long a = keys[idx], b = keys[ixj];
                    bool up = (idx & k) == 0;
                    if (up ? (a > b) : (a < b)) { keys[idx] = b; keys[ixj] = a; }
                }
            }
            __syncthreads();
        }
    }
    for (int i = 2048 - HEAVY + tid; i < 2048; i += 1024) {
        int idx = 2047 - (int)(keys[i] & 0xFFFFFFFFu);
        mrow[idx] = 1.0f;
    }
}

// ---------------------------------------------------------------------------
extern "C" void kernel_launch(void* const* d_in, const int* in_sizes, int n_in,
                              void* d_out, int out_size) {
    (void)in_sizes; (void)n_in; (void)out_size;
    const float* hidden = (const float*)d_in[0];
    const float* q_w = (const float*)d_in[1];
    const float* q_b = (const float*)d_in[2];
    const float* k_w = (const float*)d_in[3];
    const float* k_b = (const float*)d_in[4];
    const float* v_w = (const float*)d_in[5];
    const float* v_b = (const float*)d_in[6];
    const float* o_w = (const float*)d_in[7];
    float* out = (float*)d_out;

    static bool init = false;
    static cudaStream_t sA, sB, sC;
    static cudaEvent_t evRoot, evHid, evKV, evZero, evAttn, evTrrO, evTrrQ, evDoneA, evDoneC;
    if (!init) {
        cudaFuncSetAttribute(attn_pv, cudaFuncAttributeMaxDynamicSharedMemorySize, ATTN_SMEM);
        cudaFuncSetAttribute(gemm_h<true, false, true>,
                             cudaFuncAttributeMaxDynamicSharedMemorySize, GEMM_H_SMEM);
        cudaFuncSetAttribute(gemm_h<true, true, true>,
                             cudaFuncAttributeMaxDynamicSharedMemorySize, GEMM_H_SMEM);
        cudaFuncSetAttribute(gemm_h<false, false, false>,
                             cudaFuncAttributeMaxDynamicSharedMemorySize, GEMM_H_SMEM);
        cudaFuncSetAttribute(scores_h,
                             cudaFuncAttributeMaxDynamicSharedMemorySize, SCORES_SMEM);
        cudaStreamCreateWithFlags(&sA, cudaStreamNonBlocking);
        cudaStreamCreateWithFlags(&sB, cudaStreamNonBlocking);
        cudaStreamCreateWithFlags(&sC, cudaStreamNonBlocking);
        cudaEventCreateWithFlags(&evRoot, cudaEventDisableTiming);
        cudaEventCreateWithFlags(&evHid,  cudaEventDisableTiming);
        cudaEventCreateWithFlags(&evKV,   cudaEventDisableTiming);
        cudaEventCreateWithFlags(&evZero, cudaEventDisableTiming);
        cudaEventCreateWithFlags(&evAttn, cudaEventDisableTiming);
        cudaEventCreateWithFlags(&evTrrO, cudaEventDisableTiming);
        cudaEventCreateWithFlags(&evTrrQ, cudaEventDisableTiming);
        cudaEventCreateWithFlags(&evDoneA, cudaEventDisableTiming);
        cudaEventCreateWithFlags(&evDoneC, cudaEventDisableTiming);
        init = true;
    }

    __half *ghid, *gqwT, *gkwT, *gvwT, *gowT, *gq, *gk, *gv, *gctx;
    float *gcp;
    cudaGetSymbolAddress((void**)&ghid, g_hid);
    cudaGetSymbolAddress((void**)&gqwT, g_qwT);
    cudaGetSymbolAddress((void**)&gkwT, g_kwT);
    cudaGetSymbolAddress((void**)&gvwT, g_vwT);
    cudaGetSymbolAddress((void**)&gowT, g_owT);
    cudaGetSymbolAddress((void**)&gq,   g_q);
    cudaGetSymbolAddress((void**)&gk,   g_k);
    cudaGetSymbolAddress((void**)&gv,   g_v);
    cudaGetSymbolAddress((void**)&gctx, g_ctx);
    cudaGetSymbolAddress((void**)&gcp,  g_colpart);

    cudaEventRecord(evRoot, 0);
    cudaStreamWaitEvent(sA, evRoot, 0);
    cudaStreamWaitEvent(sB, evRoot, 0);
    cudaStreamWaitEvent(sC, evRoot, 0);

    dim3 tb(32, 8);
    f2h_kernel<<<(S_LEN * DMODEL / 8 + 255) / 256, 256, 0, sA>>>(
        ghid, hidden, S_LEN * DMODEL / 8);
    cudaEventRecord(evHid, sA);
    trrh_kernel<<<dim3(DMODEL / 32, DMODEL / 32), tb, 0, sC>>>(gqwT, q_w, DMODEL, DMODEL);
    cudaEventRecord(evTrrQ, sC);
    trrh_kernel<<<dim3(KV_DM / 32, DMODEL / 32), tb, 0, sB>>>(gkwT, k_w, DMODEL, KV_DM);
    trrh_kernel<<<dim3(KV_DM / 32, DMODEL / 32), tb, 0, sB>>>(gvwT, v_w, DMODEL, KV_DM);
    trrh_kernel<<<dim3(DMODEL / 32, DMODEL / 32), tb, 0, sC>>>(gowT, o_w, DMODEL, DMODEL);
    cudaEventRecord(evTrrO, sC);

    cudaStreamWaitEvent(sA, evTrrQ, 0);
    gemm_h<true, false, true><<<dim3(DMODEL / 128, S_LEN / 128, 1), 256, GEMM_H_SMEM, sA>>>(
        ghid, gqwT, nullptr, q_b, nullptr, gq, nullptr, DMODEL);

    cudaStreamWaitEvent(sB, evHid, 0);
    gemm_h<true, true, true><<<dim3(KV_DM / 128, S_LEN / 128, 2), 256, GEMM_H_SMEM, sB>>>(
        ghid, gkwT, gvwT, k_b, v_b, gk, gv, KV_DM);
    cudaEventRecord(evKV, sB);

    const int ncp = NH * NQT16 * S_LEN;
    zero_kernel<<<(ncp + 255) / 256, 256, 0, sC>>>(gcp, ncp);
    cudaEventRecord(evZero, sC);

    cudaStreamWaitEvent(sA, evKV, 0);
    scores_h<<<dim3(136, 1, NH), 256, SCORES_SMEM, sA>>>();

    cudaStreamWaitEvent(sA, evZero, 0);
    attn_pv<<<dim3(8, NH), 512, ATTN_SMEM, sA>>>();
    cudaEventRecord(evAttn, sA);

    cudaStreamWaitEvent(sC, evAttn, 0);
    topk_kernel<<<NH, 1024, 0, sC>>>(out + (size_t)S_LEN * DMODEL);
    cudaEventRecord(evDoneC, sC);

    cudaStreamWaitEvent(sA, evTrrO, 0);
    gemm_h<false, false, false><<<dim3(DMODEL / 128, S_LEN / 128, 1), 256, GEMM_H_SMEM, sA>>>(
        gctx, gowT, nullptr, nullptr, nullptr, out, nullptr, DMODEL);
    cudaEventRecord(evDoneA, sA);

    cudaStreamWaitEvent(0, evDoneA, 0);
    cudaStreamWaitEvent(0, evDoneC, 0);
}

// round 17
// speedup vs baseline: 2.0000x; 1.0139x over previous
#include <cuda_runtime.h>
#include <cuda_fp16.h>
#include <cstdint>
#include <cmath>

#define S_LEN   2048
#define DMODEL  2048
#define NH      16
#define HDIM    128
#define KV_DM   512
#define NQT16   16
#define HEAVY   204
#define RECENT  204
#define SEL     (S_LEN - RECENT)    // 1844
#define MASKW   (S_LEN + 1)         // 2049

__device__ __half g_hid[S_LEN * DMODEL];
__device__ __half g_qwT[DMODEL * DMODEL];   // [n][k]
__device__ __half g_kwT[KV_DM * DMODEL];
__device__ __half g_vwT[KV_DM * DMODEL];
__device__ __half g_owT[DMODEL * DMODEL];
__device__ __half g_q[S_LEN * DMODEL];
__device__ __half g_k[S_LEN * KV_DM];
__device__ __half g_v[S_LEN * KV_DM];
__device__ __half g_ctx[S_LEN * DMODEL];
__device__ float  g_colpart[NH * NQT16 * S_LEN];
__device__ float  g_lpart[NH * S_LEN * 16];
__device__ __half g_E[(size_t)NH * S_LEN * S_LEN];   // exp'd scores, fp16

// ---------------------------------------------------------------------------
__device__ __forceinline__ float ex2f(float x) {
    float y;
    asm("ex2.approx.ftz.f32 %0, %1;" : "=f"(y) : "f"(x));
    return y;
}
__device__ __forceinline__ void mma_f16(float* c, const uint32_t* a, const uint32_t* b) {
    asm volatile(
        "mma.sync.aligned.m16n8k16.row.col.f32.f16.f16.f32 "
        "{%0,%1,%2,%3}, {%4,%5,%6,%7}, {%8,%9}, {%0,%1,%2,%3};"
        : "+f"(c[0]), "+f"(c[1]), "+f"(c[2]), "+f"(c[3])
        : "r"(a[0]), "r"(a[1]), "r"(a[2]), "r"(a[3]), "r"(b[0]), "r"(b[1]));
}
__device__ __forceinline__ void ldsm4(uint32_t& r0, uint32_t& r1, uint32_t& r2, uint32_t& r3,
                                      uint32_t addr) {
    asm volatile("ldmatrix.sync.aligned.m8n8.x4.shared.b16 {%0,%1,%2,%3}, [%4];"
                 : "=r"(r0), "=r"(r1), "=r"(r2), "=r"(r3) : "r"(addr));
}
__device__ __forceinline__ void ldsm4t(uint32_t& r0, uint32_t& r1, uint32_t& r2, uint32_t& r3,
                                       uint32_t addr) {
    asm volatile("ldmatrix.sync.aligned.m8n8.x4.trans.shared.b16 {%0,%1,%2,%3}, [%4];"
                 : "=r"(r0), "=r"(r1), "=r"(r2), "=r"(r3) : "r"(addr));
}
__device__ __forceinline__ void cpa16(uint32_t s, const void* g) {
    asm volatile("cp.async.cg.shared.global [%0], [%1], 16;" :: "r"(s), "l"(g));
}
__device__ __forceinline__ void cp_commit() { asm volatile("cp.async.commit_group;"); }
template<int N> __device__ __forceinline__ void cp_wait() {
    asm volatile("cp.async.wait_group %0;" :: "n"(N));
}
__device__ __forceinline__ unsigned encf(float x) {
    unsigned b = __float_as_uint(x);
    return (b & 0x80000000u) ? ~b : (b | 0x80000000u);
}

__global__ void zero_kernel(float* p, int n) {
    int i = blockIdx.x * 256 + threadIdx.x;
    if (i < n) p[i] = 0.0f;
}
__global__ void f2h_kernel(__half* dst, const float* src, int n8) {
    int i = blockIdx.x * 256 + threadIdx.x;
    if (i < n8) {
        const float4 v0 = *(const float4*)&src[i * 8];
        const float4 v1 = *(const float4*)&src[i * 8 + 4];
        __half2 h[4];
        h[0] = __floats2half2_rn(v0.x, v0.y);
        h[1] = __floats2half2_rn(v0.z, v0.w);
        h[2] = __floats2half2_rn(v1.x, v1.y);
        h[3] = __floats2half2_rn(v1.z, v1.w);
        *(uint4*)&dst[i * 8] = *(uint4*)h;
    }
}
__global__ __launch_bounds__(256) void trrh_kernel(__half* dst, const float* src, int Kd, int Nd) {
    __shared__ float t[32][33];
    const int bx = blockIdx.x * 32;
    const int by = blockIdx.y * 32;
    const int tx = threadIdx.x, ty = threadIdx.y;
#pragma unroll
    for (int i = 0; i < 32; i += 8)
        t[ty + i][tx] = src[(size_t)(by + ty + i) * Nd + bx + tx];
    __syncthreads();
#pragma unroll
    for (int i = 0; i < 32; i += 8)
        dst[(size_t)(bx + ty + i) * Kd + by + tx] = __float2half_rn(t[tx][ty + i]);
}

// ---------------------------------------------------------------------------
// fp16 GEMM: 128x128 tile, BK=32, ldmatrix b16 + 3-stage cp.async,
// 1 barrier/iter, 2 CTAs/SM. (unchanged)
// ---------------------------------------------------------------------------
#define GEMM_H_SMEM (2 * (3 * 128 * 40) * 2)

template<bool OUT0_HALF, bool OUT1_HALF, bool HASBIAS>
__global__ __launch_bounds__(256, 2) void gemm_h(
    const __half* __restrict__ A,
    const __half* __restrict__ Bt0, const __half* __restrict__ Bt1,
    const float* __restrict__ bias0, const float* __restrict__ bias1,
    void* __restrict__ C0, void* __restrict__ C1, int N)
{
    constexpr int KD = 2048, BK = 32, ASS = 40;
    constexpr int NIT = KD / BK;

    extern __shared__ __half smem_h[];
    __half* AsH = smem_h;
    __half* BsH = smem_h + 3 * 128 * ASS;

    const int tid = threadIdx.x;
    const int lane = tid & 31, w = tid >> 5;
    const int wm0 = (w & 1) * 64;
    const int wn0 = (w >> 1) * 32;
    const int bm = blockIdx.y * 128;
    const int bn = blockIdx.x * 128;

    const __half* Bt = (blockIdx.z == 0) ? Bt0 : Bt1;
    const float* bia = (blockIdx.z == 0) ? bias0 : bias1;

    const int cr = tid & 127;
    const int co = (tid >> 7) * 16;
    const uint32_t sA = (uint32_t)__cvta_generic_to_shared(AsH);
    const uint32_t sB = (uint32_t)__cvta_generic_to_shared(BsH);

    const int a_row = lane & 15;
    const int a_k8  = (lane >> 4) * 8;
    const int b_row = (lane & 7) + ((lane >> 3) & 1) * 8;
    const int b_k8  = (lane >> 4) * 8;

    float acc[4][4][4];
#pragma unroll
    for (int mi = 0; mi < 4; mi++)
#pragma unroll
        for (int nj = 0; nj < 4; nj++)
#pragma unroll
            for (int c = 0; c < 4; c++) acc[mi][nj][c] = 0.0f;

    auto issue = [&](int st, int k0) {
        const __half* ga = &A[(size_t)(bm + cr) * KD + k0 + co];
        uint32_t sa = sA + (uint32_t)((st * 128 + cr) * ASS + co) * 2u;
        cpa16(sa, ga); cpa16(sa + 16, ga + 8);
        const __half* gb = &Bt[(size_t)(bn + cr) * KD + k0 + co];
        uint32_t sb = sB + (uint32_t)((st * 128 + cr) * ASS + co) * 2u;
        cpa16(sb, gb); cpa16(sb + 16, gb + 8);
    };

    issue(0, 0);       cp_commit();
    issue(1, BK);      cp_commit();

    int st = 0;
    for (int it = 0; it < NIT; it++) {
        if (it + 1 < NIT) cp_wait<1>(); else cp_wait<0>();
        __syncthreads();
        const uint32_t aB = sA + (uint32_t)(st * 128 * ASS) * 2u;
        const uint32_t bB = sB + (uint32_t)(st * 128 * ASS) * 2u;

#pragma unroll
        for (int ks = 0; ks < 2; ks++) {
            const int kk = ks * 16;
            uint32_t af[4][4], bf[4][2];
#pragma unroll
            for (int mi = 0; mi < 4; mi++) {
                uint32_t ad = aB + (uint32_t)(((wm0 + 16 * mi + a_row) * ASS) + kk + a_k8) * 2u;
                ldsm4(af[mi][0], af[mi][1], af[mi][2], af[mi][3], ad);
            }
#pragma unroll
            for (int p = 0; p < 2; p++) {
                uint32_t bd = bB + (uint32_t)(((wn0 + 16 * p + b_row) * ASS) + kk + b_k8) * 2u;
                uint32_t r0, r1, r2, r3;
                ldsm4(r0, r1, r2, r3, bd);
                bf[2 * p][0] = r0; bf[2 * p][1] = r2;
                bf[2 * p + 1][0] = r1; bf[2 * p + 1][1] = r3;
            }
#pragma unroll
            for (int mi = 0; mi < 4; mi++)
#pragma unroll
                for (int nj = 0; nj < 4; nj++)
                    mma_f16(acc[mi][nj], af[mi], bf[nj]);
        }

        if (it + 2 < NIT) {
            issue((st + 2) % 3, (it + 2) * BK);
            cp_commit();
        }
        st = (st + 1) % 3;
    }

    const bool outHalf = (blockIdx.z == 0) ? OUT0_HALF : OUT1_HALF;
    void* C = (blockIdx.z == 0) ? C0 : C1;
#pragma unroll
    for (int mi = 0; mi < 4; mi++) {
#pragma unroll
        for (int nj = 0; nj < 4; nj++) {
            int row = bm + wm0 + 16 * mi + (lane >> 2);
            int col = bn + wn0 + 8 * nj + 2 * (lane & 3);
            float bx = 0.0f, by = 0.0f;
            if (HASBIAS) { bx = bia[col]; by = bia[col + 1]; }
            float v0x = acc[mi][nj][0] + bx, v0y = acc[mi][nj][1] + by;
            float v1x = acc[mi][nj][2] + bx, v1y = acc[mi][nj][3] + by;
            if (outHalf) {
                __half* Ch = (__half*)C;
                *(__half2*)&Ch[(size_t)row * N + col] = __floats2half2_rn(v0x, v0y);
                *(__half2*)&Ch[(size_t)(row + 8) * N + col] = __floats2half2_rn(v1x, v1y);
            } else {
                float* Cf = (float*)C;
                *(float2*)&Cf[(size_t)row * N + col] = make_float2(v0x, v0y);
                *(float2*)&Cf[(size_t)(row + 8) * N + col] = make_float2(v1x, v1y);
            }
        }
    }
}

// ---------------------------------------------------------------------------
// Scores (fp16): lower-triangle enumeration, no dead CTAs. (unchanged, R16)
// ---------------------------------------------------------------------------
#define SCORES_SMEM (2 * (3 * 128 * 40) * 2 + 128 * 4 * 4)

__global__ __launch_bounds__(256, 2) void scores_h() {
    constexpr int ASS = 40, BK = 32;
    const int t = blockIdx.x;
    int mb = (int)((sqrtf(8.0f * (float)t + 1.0f) - 1.0f) * 0.5f);
    while ((mb + 1) * (mb + 2) / 2 <= t) mb++;
    while (mb * (mb + 1) / 2 > t) mb--;
    const int nb = t - mb * (mb + 1) / 2;
    const int h = blockIdx.z;
    const int kvh = h >> 2;

    extern __shared__ __half smem_h[];
    __half* AsH = smem_h;
    __half* BsH = smem_h + 3 * 128 * ASS;
    float* red = (float*)(smem_h + 2 * 3 * 128 * ASS);

    const int tid = threadIdx.x;
    const int lane = tid & 31, w = tid >> 5;
    const int wm0 = (w & 1) * 64;
    const int wn0 = (w >> 1) * 32;

    const int cr = tid & 127;
    const int co = (tid >> 7) * 16;
    const uint32_t sA = (uint32_t)__cvta_generic_to_shared(AsH);
    const uint32_t sB = (uint32_t)__cvta_generic_to_shared(BsH);

    const int a_row = lane & 15;
    const int a_k8  = (lane >> 4) * 8;
    const int b_row = (lane & 7) + ((lane >> 3) & 1) * 8;
    const int b_k8  = (lane >> 4) * 8;

    const __half* Qg = g_q + (size_t)(mb * 128) * DMODEL + h * HDIM;
    const __half* Kg = g_k + (size_t)(nb * 128) * KV_DM + kvh * HDIM;

    float acc[4][4][4];
#pragma unroll
    for (int mi = 0; mi < 4; mi++)
#pragma unroll
        for (int nj = 0; nj < 4; nj++)
#pragma unroll
            for (int c = 0; c < 4; c++) acc[mi][nj][c] = 0.0f;

    auto issue = [&](int st, int k0) {
        const __half* ga = &Qg[(size_t)cr * DMODEL + k0 + co];
        uint32_t sa = sA + (uint32_t)((st * 128 + cr) * ASS + co) * 2u;
        cpa16(sa, ga); cpa16(sa + 16, ga + 8);
        const __half* gb = &Kg[(size_t)cr * KV_DM + k0 + co];
        uint32_t sb = sB + (uint32_t)((st * 128 + cr) * ASS + co) * 2u;
        cpa16(sb, gb); cpa16(sb + 16, gb + 8);
    };

    issue(0, 0);      cp_commit();
    issue(1, BK);     cp_commit();

    constexpr int NIT = HDIM / BK;   // 4
    int st = 0;
    for (int it = 0; it < NIT; it++) {
        if (it + 1 < NIT) cp_wait<1>(); else cp_wait<0>();
        __syncthreads();
        const uint32_t aB = sA + (uint32_t)(st * 128 * ASS) * 2u;
        const uint32_t bB = sB + (uint32_t)(st * 128 * ASS) * 2u;
#pragma unroll
        for (int ks = 0; ks < 2; ks++) {
            const int kk = ks * 16;
            uint32_t af[4][4], bf[4][2];
#pragma unroll
            for (int mi = 0; mi < 4; mi++) {
                uint32_t ad = aB + (uint32_t)(((wm0 + 16 * mi + a_row) * ASS) + kk + a_k8) * 2u;
                ldsm4(af[mi][0], af[mi][1], af[mi][2], af[mi][3], ad);
            }
#pragma unroll
            for (int p = 0; p < 2; p++) {
                uint32_t bd = bB + (uint32_t)(((wn0 + 16 * p + b_row) * ASS) + kk + b_k8) * 2u;
                uint32_t r0, r1, r2, r3;
                ldsm4(r0, r1, r2, r3, bd);
                bf[2 * p][0] = r0; bf[2 * p][1] = r2;
                bf[2 * p + 1][0] = r1; bf[2 * p + 1][1] = r3;
            }
#pragma unroll
            for (int mi = 0; mi < 4; mi++)
#pragma unroll
                for (int nj = 0; nj < 4; nj++)
                    mma_f16(acc[mi][nj], af[mi], bf[nj]);
        }
        if (it + 2 < NIT) {
            issue((st + 2) % 3, (it + 2) * BK);
            cp_commit();
        }
        st = (st + 1) % 3;
    }

    const float SCL2 = 0.08838834764831845f * 1.4426950408889634f;
    __half* Eh = g_E + (size_t)h * S_LEN * S_LEN;
    float rs[4][2];
#pragma unroll
    for (int mi = 0; mi < 4; mi++) { rs[mi][0] = 0.f; rs[mi][1] = 0.f; }

#pragma unroll
    for (int mi = 0; mi < 4; mi++) {
#pragma unroll
        for (int nj = 0; nj < 4; nj++) {
            int row = mb * 128 + wm0 + 16 * mi + (lane >> 2);
            int col = nb * 128 + wn0 + 8 * nj + 2 * (lane & 3);
            float e0 = (col     <= row)     ? ex2f(acc[mi][nj][0] * SCL2) : 0.f;
            float e1 = (col + 1 <= row)     ? ex2f(acc[mi][nj][1] * SCL2) : 0.f;
            float e2 = (col     <= row + 8) ? ex2f(acc[mi][nj][2] * SCL2) : 0.f;
            float e3 = (col + 1 <= row + 8) ? ex2f(acc[mi][nj][3] * SCL2) : 0.f;
            __half2 h01 = __floats2half2_rn(e0, e1);
            __half2 h23 = __floats2half2_rn(e2, e3);
            *(__half2*)&Eh[(size_t)row * S_LEN + col] = h01;
            *(__half2*)&Eh[(size_t)(row + 8) * S_LEN + col] = h23;
            float2 f01 = __half22float2(h01);
            float2 f23 = __half22float2(h23);
            rs[mi][0] += f01.x + f01.y;
            rs[mi][1] += f23.x + f23.y;
        }
    }
#pragma unroll
    for (int mi = 0; mi < 4; mi++)
#pragma unroll
        for (int hh = 0; hh < 2; hh++) {
            rs[mi][hh] += __shfl_xor_sync(0xFFFFFFFFu, rs[mi][hh], 1);
            rs[mi][hh] += __shfl_xor_sync(0xFFFFFFFFu, rs[mi][hh], 2);
        }
    if ((lane & 3) == 0) {
        int wg = w >> 1;
#pragma unroll
        for (int mi = 0; mi < 4; mi++) {
            red[(wm0 + 16 * mi + (lane >> 2)) * 4 + wg]     = rs[mi][0];
            red[(wm0 + 16 * mi + 8 + (lane >> 2)) * 4 + wg] = rs[mi][1];
        }
    }
    __syncthreads();
    if (tid < 128)
        g_lpart[((size_t)h * S_LEN + mb * 128 + tid) * 16 + nb] =
            red[tid * 4] + red[tid * 4 + 1] + red[tid * 4 + 2] + red[tid * 4 + 3];
}

// ---------------------------------------------------------------------------
// Attention over E (fp16): triangle-paired strips; raw-E MMA with il applied
// to the fp32 accumulators in the EPILOGUE (O = il * (E @ V)) — no per-tile
// fragment scaling. Colsums unchanged (need per-row il inside the sum).
// ---------------------------------------------------------------------------
#define ESS 72
#define VSS 136
#define ATTN_SMEM (3 * 128 * ESS * 2 + 3 * 64 * VSS * 2 + 2 * 256 * 4 + 128 * 4)

__global__ __launch_bounds__(512, 1) void attn_pv() {
    extern __shared__ __half smh[];
    __half* Es = smh;                               // [3][128][72]
    __half* Vs = smh + 3 * 128 * ESS;               // [3][64][136]
    float* red = (float*)(smh + 3 * 128 * ESS + 3 * 64 * VSS);  // [2][256]
    float* il  = red + 2 * 256;                     // [128]

    const int pair = blockIdx.x;
    const int h  = blockIdx.y;
    const int kvh = h >> 2;
    const int tid = threadIdx.x;
    const int lane = tid & 31, w = tid >> 5;
    const int wm  = (w & 3) * 32;
    const int wn2 = (w >> 2) * 32;

    const int a_row = lane & 15;
    const int a_k8  = (lane >> 4) * 8;
    const uint32_t sET = (uint32_t)__cvta_generic_to_shared(Es);
    const uint32_t sVT = (uint32_t)__cvta_generic_to_shared(Vs);

    const __half* Eg = g_E + (size_t)h * S_LEN * S_LEN;
    const int prow = tid >> 2, pcb = (tid & 3) * 16;
    const int vr = tid >> 3, vcb = (tid & 7) * 16;

#pragma unroll 1
    for (int s = 0; s < 2; s++) {
        const int qt = (s == 0) ? 15 - pair : pair;
        const int qbase = qt * 128;
        const int nkt = 2 * qt + 2;

        auto issue = [&](int st, int kt) {
            const __half* ep = &Eg[(size_t)(qbase + prow) * S_LEN + kt * 64 + pcb];
            uint32_t se = sET + (uint32_t)((st * 128 + prow) * ESS + pcb) * 2u;
            cpa16(se, ep); cpa16(se + 16, ep + 8);
            const __half* vp = &g_v[(size_t)(kt * 64 + vr) * KV_DM + kvh * HDIM + vcb];
            uint32_t sv = sVT + (uint32_t)((st * 64 + vr) * VSS + vcb) * 2u;
            cpa16(sv, vp); cpa16(sv + 16, vp + 8);
        };

        issue(0, 0);  cp_commit();
        issue(1, 1);  cp_commit();   // nkt >= 2 always

        if (tid < 128) {
            const float* lp = &g_lpart[((size_t)h * S_LEN + qbase + tid) * 16];
            float l = 0.0f;
            for (int nb = 0; nb <= qt; nb++) l += lp[nb];
            il[tid] = 1.0f / l;
        }
        __syncthreads();

        float il0[2], il1[2];
#pragma unroll
        for (int mi = 0; mi < 2; mi++) {
            il0[mi] = il[wm + 16 * mi + (lane >> 2)];
            il1[mi] = il[wm + 16 * mi + 8 + (lane >> 2)];
        }

        float o[2][4][4];
#pragma unroll
        for (int mi = 0; mi < 2; mi++)
#pragma unroll
            for (int nj = 0; nj < 4; nj++)
#pragma unroll
                for (int c = 0; c < 4; c++) o[mi][nj][c] = 0.0f;

        float* cpart = &g_colpart[((size_t)h * NQT16 + qt) * S_LEN];

        int st = 0;
        for (int kt = 0; kt < nkt; kt++) {
            if (kt + 1 < nkt) cp_wait<1>(); else cp_wait<0>();
            __syncthreads();

            if (kt > 0 && tid < 64) {
                const float* rp = &red[((kt - 1) & 1) * 256 + tid * 4];
                cpart[(kt - 1) * 64 + tid] = rp[0] + rp[1] + rp[2] + rp[3];
            }

            if (kt + 2 < nkt) {
                issue((st + 2) % 3, kt + 2);
                cp_commit();
            }

            if (tid < 256) {
                int c = tid & 63, seg = tid >> 6;
                const __half* eb = &Es[(st * 128 + seg * 32) * ESS + c];
                float cs = 0.0f;
#pragma unroll 8
                for (int q = 0; q < 32; q++)
                    cs += __half2float(eb[q * ESS]) * il[seg * 32 + q];
                red[(kt & 1) * 256 + c * 4 + seg] = cs;
            }

            const uint32_t eB = sET + (uint32_t)(st * 128 * ESS) * 2u;
            const uint32_t vB = sVT + (uint32_t)(st * 64 * VSS) * 2u;
#pragma unroll
            for (int ks = 0; ks < 4; ks++) {
                const int kk = ks * 16;
                uint32_t af[2][4], bf[4][2];
#pragma unroll
                for (int mi = 0; mi < 2; mi++) {
                    uint32_t ad = eB + (uint32_t)(((wm + 16 * mi + a_row) * ESS) + kk + a_k8) * 2u;
                    ldsm4(af[mi][0], af[mi][1], af[mi][2], af[mi][3], ad);
                }
#pragma unroll
                for (int p = 0; p < 2; p++) {
                    uint32_t bd = vB + (uint32_t)(((kk + (lane & 15)) * VSS) + wn2 + p * 16 + (lane >> 4) * 8) * 2u;
                    uint32_t r0, r1, r2, r3;
                    ldsm4t(r0, r1, r2, r3, bd);
                    bf[2 * p][0] = r0; bf[2 * p][1] = r1;
                    bf[2 * p + 1][0] = r2; bf[2 * p + 1][1] = r3;
                }
#pragma unroll
                for (int mi = 0; mi < 2; mi++)
#pragma unroll
                    for (int nj = 0; nj < 4; nj++)
                        mma_f16(o[mi][nj], af[mi], bf[nj]);
            }
            st = (st + 1) % 3;
        }

        __syncthreads();
        if (tid < 64) {
            const float* rp = &red[((nkt - 1) & 1) * 256 + tid * 4];
            cpart[(nkt - 1) * 64 + tid] = rp[0] + rp[1] + rp[2] + rp[3];
        }

        // epilogue: O = il * (E @ V)
#pragma unroll
        for (int mi = 0; mi < 2; mi++)
#pragma unroll
            for (int nj = 0; nj < 4; nj++) {
                int row = qbase + wm + 16 * mi + (lane >> 2);
                int col = h * HDIM + wn2 + 8 * nj + 2 * (lane & 3);
                *(__half2*)&g_ctx[(size_t)row * DMODEL + col] =
                    __floats2half2_rn(o[mi][nj][0] * il0[mi], o[mi][nj][1] * il0[mi]);
                *(__half2*)&g_ctx[(size_t)(row + 8) * DMODEL + col] =
                    __floats2half2_rn(o[mi][nj][2] * il1[mi], o[mi][nj][3] * il1[mi]);
            }
        __syncthreads();   // all red/il reads done before next strip overwrites
    }
}

// ---------------------------------------------------------------------------
// Heavy-hitter mask via bitonic sort (exact jax.lax.top_k tie semantics).
// ---------------------------------------------------------------------------
__global__ __launch_bounds__(1024) void topk_kernel(float* __restrict__ mask_out) {
    const int h = blockIdx.x;
    const int tid = threadIdx.x;
    __shared__ unsigned long long keys[2048];

    for (int i = tid; i < 2048; i += 1024) {
        unsigned ev = 0u;
        if (i < SEL) {
            float s = 0.0f;
#pragma unroll
            for (int qt = 0; qt < NQT16; qt++)
                s += g_colpart[((size_t)h * NQT16 + qt) * S_LEN + i];
            ev = encf(s);
        }
        keys[i] = ((unsigned long long)ev << 32) | (unsigned)(2047 - i);
    }
    float* mrow = mask_out + (size_t)h * MASKW;
    for (int i = tid; i < MASKW; i += 1024)
        mrow[i] = (i >= (MASKW - RECENT)) ? 1.0f : 0.0f;
    __syncthreads();

    for (int k = 2; k <= 2048; k <<= 1) {
        for (int j = k >> 1; j > 0; j >>= 1) {
            for (int idx = tid; idx < 2048; idx += 1024) {
                int ixj = idx ^ j;
                if (ixj > idx) {
                    unsigned long long a = keys[idx], b = keys[ixj];
                    bool up = (idx & k) == 0;
                    if (up ? (a > b) : (a < b)) { keys[idx] = b; keys[ixj] = a; }
                }
            }
            __syncthreads();
        }
    }
    for (int i = 2048 - HEAVY + tid; i < 2048; i += 1024) {
        int idx = 2047 - (int)(keys[i] & 0xFFFFFFFFu);
        mrow[idx] = 1.0f;
    }
}

// ---------------------------------------------------------------------------
extern "C" void kernel_launch(void* const* d_in, const int* in_sizes, int n_in,
                              void* d_out, int out_size) {
    (void)in_sizes; (void)n_in; (void)out_size;
    const float* hidden = (const float*)d_in[0];
    const float* q_w = (const float*)d_in[1];
    const float* q_b = (const float*)d_in[2];
    const float* k_w = (const float*)d_in[3];
    const float* k_b = (const float*)d_in[4];
    const float* v_w = (const float*)d_in[5];
    const float* v_b = (const float*)d_in[6];
    const float* o_w = (const float*)d_in[7];
    float* out = (float*)d_out;

    static bool init = false;
    static cudaStream_t sA, sB, sC;
    static cudaEvent_t evRoot, evHid, evKV, evZero, evAttn, evTrrO, evTrrQ, evDoneA, evDoneC;
    if (!init) {
        cudaFuncSetAttribute(attn_pv, cudaFuncAttributeMaxDynamicSharedMemorySize, ATTN_SMEM);
        cudaFuncSetAttribute(gemm_h<true, false, true>,
                             cudaFuncAttributeMaxDynamicSharedMemorySize, GEMM_H_SMEM);
        cudaFuncSetAttribute(gemm_h<true, true, true>,
                             cudaFuncAttributeMaxDynamicSharedMemorySize, GEMM_H_SMEM);
        cudaFuncSetAttribute(gemm_h<false, false, false>,
                             cudaFuncAttributeMaxDynamicSharedMemorySize, GEMM_H_SMEM);
        cudaFuncSetAttribute(scores_h,
                             cudaFuncAttributeMaxDynamicSharedMemorySize, SCORES_SMEM);
        cudaStreamCreateWithFlags(&sA, cudaStreamNonBlocking);
        cudaStreamCreateWithFlags(&sB, cudaStreamNonBlocking);
        cudaStreamCreateWithFlags(&sC, cudaStreamNonBlocking);
        cudaEventCreateWithFlags(&evRoot, cudaEventDisableTiming);
        cudaEventCreateWithFlags(&evHid,  cudaEventDisableTiming);
        cudaEventCreateWithFlags(&evKV,   cudaEventDisableTiming);
        cudaEventCreateWithFlags(&evZero, cudaEventDisableTiming);
        cudaEventCreateWithFlags(&evAttn, cudaEventDisableTiming);
        cudaEventCreateWithFlags(&evTrrO, cudaEventDisableTiming);
        cudaEventCreateWithFlags(&evTrrQ, cudaEventDisableTiming);
        cudaEventCreateWithFlags(&evDoneA, cudaEventDisableTiming);
        cudaEventCreateWithFlags(&evDoneC, cudaEventDisableTiming);
        init = true;
    }

    __half *ghid, *gqwT, *gkwT, *gvwT, *gowT, *gq, *gk, *gv, *gctx;
    float *gcp;
    cudaGetSymbolAddress((void**)&ghid, g_hid);
    cudaGetSymbolAddress((void**)&gqwT, g_qwT);
    cudaGetSymbolAddress((void**)&gkwT, g_kwT);
    cudaGetSymbolAddress((void**)&gvwT, g_vwT);
    cudaGetSymbolAddress((void**)&gowT, g_owT);
    cudaGetSymbolAddress((void**)&gq,   g_q);
    cudaGetSymbolAddress((void**)&gk,   g_k);
    cudaGetSymbolAddress((void**)&gv,   g_v);
    cudaGetSymbolAddress((void**)&gctx, g_ctx);
    cudaGetSymbolAddress((void**)&gcp,  g_colpart);

    cudaEventRecord(evRoot, 0);
    cudaStreamWaitEvent(sA, evRoot, 0);
    cudaStreamWaitEvent(sB, evRoot, 0);
    cudaStreamWaitEvent(sC, evRoot, 0);

    dim3 tb(32, 8);
    f2h_kernel<<<(S_LEN * DMODEL / 8 + 255) / 256, 256, 0, sA>>>(
        ghid, hidden, S_LEN * DMODEL / 8);
    cudaEventRecord(evHid, sA);
    trrh_kernel<<<dim3(DMODEL / 32, DMODEL / 32), tb, 0, sC>>>(gqwT, q_w, DMODEL, DMODEL);
    cudaEventRecord(evTrrQ, sC);
    trrh_kernel<<<dim3(KV_DM / 32, DMODEL / 32), tb, 0, sB>>>(gkwT, k_w, DMODEL, KV_DM);
    trrh_kernel<<<dim3(KV_DM / 32, DMODEL / 32), tb, 0, sB>>>(gvwT, v_w, DMODEL, KV_DM);
    trrh_kernel<<<dim3(DMODEL / 32, DMODEL / 32), tb, 0, sC>>>(gowT, o_w, DMODEL, DMODEL);
    cudaEventRecord(evTrrO, sC);

    cudaStreamWaitEvent(sA, evTrrQ, 0);
    gemm_h<true, false, true><<<dim3(DMODEL / 128, S_LEN / 128, 1), 256, GEMM_H_SMEM, sA>>>(
        ghid, gqwT, nullptr, q_b, nullptr, gq, nullptr, DMODEL);

    cudaStreamWaitEvent(sB, evHid, 0);
    gemm_h<true, true, true><<<dim3(KV_DM / 128, S_LEN / 128, 2), 256, GEMM_H_SMEM, sB>>>(
        ghid, gkwT, gvwT, k_b, v_b, gk, gv, KV_DM);
    cudaEventRecord(evKV, sB);

    const int ncp = NH * NQT16 * S_LEN;
    zero_kernel<<<(ncp + 255) / 256, 256, 0, sC>>>(gcp, ncp);
    cudaEventRecord(evZero, sC);

    cudaStreamWaitEvent(sA, evKV, 0);
    scores_h<<<dim3(136, 1, NH), 256, SCORES_SMEM, sA>>>();

    cudaStreamWaitEvent(sA, evZero, 0);
    attn_pv<<<dim3(8, NH), 512, ATTN_SMEM, sA>>>();
    cudaEventRecord(evAttn, sA);

    cudaStreamWaitEvent(sC, evAttn, 0);
    topk_kernel<<<NH, 1024, 0, sC>>>(out + (size_t)S_LEN * DMODEL);
    cudaEventRecord(evDoneC, sC);

    cudaStreamWaitEvent(sA, evTrrO, 0);
    gemm_h<false, false, false><<<dim3(DMODEL / 128, S_LEN / 128, 1), 256, GEMM_H_SMEM, sA>>>(
        gctx, gowT, nullptr, nullptr, nullptr, out, nullptr, DMODEL);
    cudaEventRecord(evDoneA, sA);

    cudaStreamWaitEvent(0, evDoneA, 0);
    cudaStreamWaitEvent(0, evDoneC, 0);
}